// round 7
// baseline (speedup 1.0000x reference)
#include <cuda_runtime.h>
#include <math.h>

#define NE 640000
#define NN 20000
#define NB 8
#define LAT 64
#define TBL 8192
#define ST 69          // float4 stride for x and w tiles (bank spread)
#define SEF 66         // float stride for staged result

__device__ __align__(16) float g_ef[(size_t)NE * LAT];
__device__ float g_score[NE];
__device__ __align__(16) float g_pooled[(size_t)NN * LAT];
__device__ __align__(16) float g_gate[(TBL + 1) * LAT];
__device__ unsigned g_umax;
__device__ float g_sumexp;

__device__ __forceinline__ float wsum(float v) {
#pragma unroll
    for (int o = 16; o; o >>= 1) v += __shfl_xor_sync(0xffffffffu, v, o);
    return v;
}
__device__ __forceinline__ unsigned enc_key(float f) {
    int b = __float_as_int(f);
    return (b >= 0) ? ((unsigned)b | 0x80000000u) : ~(unsigned)b;
}
__device__ __forceinline__ float dec_key(unsigned u) {
    int b = (u & 0x80000000u) ? (int)(u ^ 0x80000000u) : ~(int)u;
    return __int_as_float(b);
}
__device__ __forceinline__ unsigned s2u(const void* p) {
    return (unsigned)__cvta_generic_to_shared(p);
}
#define FMA2(d, a, b) asm("fma.rn.f32x2 %0, %1, %2, %0;" : "+l"(d) : "l"(a), "l"(b))
#define LDSV2(lo, hi, addr) \
    asm volatile("ld.shared.v2.b64 {%0,%1},[%2];" : "=l"(lo), "=l"(hi) : "r"(addr))
#define PACK2(d, lo, hi) \
    asm("mov.b64 %0, {%1, %2};" : "=l"(d) : "r"(__float_as_int(lo)), "r"(__float_as_int(hi)))
#define UNPACK2(lo, hi, s) \
    do { unsigned _a, _b; asm("mov.b64 {%0,%1}, %2;" : "=r"(_a), "=r"(_b) : "l"(s)); \
         lo = __int_as_float(_a); hi = __int_as_float(_b); } while (0)

__device__ __forceinline__ float cutoff3(float r) {
    float t = r * (1.0f / 6.0f), t2 = t * t, t6 = t2 * t2 * t2;
    float ct = tanhf(1.0f - t6);
    return ct * ct * ct;
}

__global__ void k_init() {
    int i = blockIdx.x * blockDim.x + threadIdx.x;
    for (; i < NN * LAT; i += gridDim.x * blockDim.x) g_pooled[i] = 0.f;
    if (blockIdx.x == 0 && threadIdx.x == 0) { g_umax = 0u; g_sumexp = 0.f; }
}

__global__ void __launch_bounds__(256) k_gate(const float* __restrict__ fW1,
                                              const float* __restrict__ fW2) {
    __shared__ float st[8][128];
    const int w = threadIdx.x >> 5, lane = threadIdx.x & 31;
    const int p = blockIdx.x * 8 + w;
    if (p > TBL) return;
    const float r = 0.5f + (5.5f / (float)TBL) * (float)p;
    const float cut = cutoff3(r);
    float rb[NB];
#pragma unroll
    for (int n = 0; n < NB; n++)
        rb[n] = 0.57735026918962576f * sinf((float)(n + 1) * 0.5235987755982988f * r) / r * cut;
#pragma unroll
    for (int j = 0; j < 4; j++) {
        const int k = lane + 32 * j;
        float a = 0.f, g = 0.f;
#pragma unroll
        for (int n = 0; n < NB; n++) {
            a = fmaf(rb[n], fW1[n * 256 + k], a);
            g = fmaf(rb[n], fW1[n * 256 + 128 + k], g);
        }
        st[w][k] = a / (1.0f + expf(-a)) * g;
    }
    __syncwarp();
    float q0 = 0.f, q1 = 0.f;
#pragma unroll 8
    for (int k = 0; k < 128; k++) {
        const float2 f2 = ((const float2*)fW2)[k * 32 + lane];
        q0 = fmaf(st[w][k], f2.x, q0);
        q1 = fmaf(st[w][k], f2.y, q1);
    }
    ((float2*)g_gate)[p * 32 + lane] =
        make_float2(1.0f / (1.0f + expf(-q0)), 1.0f / (1.0f + expf(-q1)));
}

// ---------------- K1: ef = LN1(edge_in) @ W1 + b1 ; score ----------------
// dyn smem: sW 32*ST*16=35328 | sx 64*ST*16=70656 (sef 64*66*4 aliased) | params 2880
#define K1_SMEM 108864
__global__ void __launch_bounds__(256, 2) k_edge1(
    const int* __restrict__ eidx, const float* __restrict__ elen,
    const float* __restrict__ nattr,
    const float* __restrict__ ln1g, const float* __restrict__ ln1b,
    const float* __restrict__ W1, const float* __restrict__ b1,
    const float* __restrict__ ln2g, const float* __restrict__ ln2b,
    const float* __restrict__ W2, const float* __restrict__ b2)
{
    extern __shared__ __align__(16) char dsm[];
    float4* sW = (float4*)dsm;
    float4* sx = (float4*)(dsm + 35328);
    float*  sef = (float*)(dsm + 35328);
    float* sg1 = (float*)(dsm + 35328 + 70656);
    float* sb1 = sg1 + 136;
    float* sg2 = sb1 + 136;
    float* sb2 = sg2 + 128;
    float* sW2 = sb2 + 128;
    float* b1e = sW2 + 128;
    __shared__ float smax_s[8];

    const int tid = threadIdx.x;
    // weight tile: sW[j*ST+kk] = {W1[2kk][2j],W1[2kk][2j+1],W1[2kk+1][2j],W1[2kk+1][2j+1]}
    for (int i = tid; i < 68 * 32; i += 256) {
        const int kk = i >> 5, j = i & 31;
        sW[j * ST + kk] = make_float4(
            W1[(2 * kk) * 64 + 2 * j], W1[(2 * kk) * 64 + 2 * j + 1],
            W1[(2 * kk + 1) * 64 + 2 * j], W1[(2 * kk + 1) * 64 + 2 * j + 1]);
    }
    for (int i = tid; i < 136; i += 256) { sg1[i] = ln1g[i]; sb1[i] = ln1b[i]; }
    for (int i = tid; i < 128; i += 256) { sg2[i] = ln2g[i]; sb2[i] = ln2b[i]; sW2[i] = W2[i]; }
    if (tid < 64) b1e[tid] = b1[tid];
    __syncthreads();

    const int w = tid >> 5, lane = tid & 31;
    const int p = w >> 1, q = w & 1;
    const int egrp = lane >> 3, cpg = lane & 7;
    const float b2v = b2[0];
    const float2* nat2 = (const float2*)nattr;
    float runmax = -3.4e38f;

    const unsigned sx_u = s2u(sx);
    const unsigned xu = sx_u + (unsigned)((p * 16 + egrp) * ST) * 16u;
    const unsigned wu = s2u(sW) + (unsigned)((q * 16 + cpg) * ST) * 16u;
    const int j0 = q * 16 + cpg, j1 = j0 + 8;
    unsigned long long bias0, bias1;
    PACK2(bias0, b1e[2 * j0], b1e[2 * j0 + 1]);
    PACK2(bias1, b1e[2 * j1], b1e[2 * j1 + 1]);

    for (int g0 = blockIdx.x * 64; g0 < NE; g0 += gridDim.x * 64) {
        // ---- LN phase: warp w owns edges w*8..w*8+7 ----
        int cI[8];
        float2 acv[8];
        {
            int nI[8];
            float rr_[8];
#pragma unroll
            for (int e = 0; e < 8; e++) {
                const int ge = g0 + w * 8 + e;
                cI[e] = eidx[ge]; nI[e] = eidx[NE + ge]; rr_[e] = elen[ge];
            }
            float2 anv[8];
#pragma unroll
            for (int e = 0; e < 8; e++) {
                acv[e] = nat2[(size_t)cI[e] * 32 + lane];
                anv[e] = nat2[(size_t)nI[e] * 32 + lane];
            }
#pragma unroll
            for (int e = 0; e < 8; e++) {
                const float2 ac = acv[e], an = anv[e];
                const float r = rr_[e];
                const float rb = 0.57735026918962576f *
                    sinf((float)(lane + 1) * 0.5235987755982988f * r) / r * cutoff3(r);
                float ls = ac.x + ac.y + an.x + an.y;
                float lss = ac.x * ac.x + ac.y * ac.y + an.x * an.x + an.y * an.y;
                if (lane < 8) { ls += rb; lss += rb * rb; }
                const float S = wsum(ls), SS = wsum(lss);
                const float mean = S * (1.0f / 136.0f);
                const float ri = rsqrtf(SS * (1.0f / 136.0f) - mean * mean + 1e-5f);
                const int eb = (w * 8 + e) * ST;
                const float x0 = (ac.x - mean) * ri * sg1[2 * lane] + sb1[2 * lane];
                const float x1 = (ac.y - mean) * ri * sg1[2 * lane + 1] + sb1[2 * lane + 1];
                sx[eb + lane] = make_float4(x0, x0, x1, x1);
                const float y0 = (an.x - mean) * ri * sg1[64 + 2 * lane] + sb1[64 + 2 * lane];
                const float y1 = (an.y - mean) * ri * sg1[64 + 2 * lane + 1] + sb1[64 + 2 * lane + 1];
                sx[eb + 32 + lane] = make_float4(y0, y0, y1, y1);
                if (lane < 8) {
                    const float z = (rb - mean) * ri * sg1[128 + lane] + sb1[128 + lane];
                    ((float2*)(sx + eb + 64))[lane] = make_float2(z, z);
                }
            }
        }
        __syncthreads();

        // ---- cooperative GEMV: warp pair p, col half q ----
        unsigned long long acc[4][2];
#pragma unroll
        for (int s = 0; s < 4; s++) { acc[s][0] = bias0; acc[s][1] = bias1; }
#pragma unroll 4
        for (int kk = 0; kk < 68; kk++) {
            unsigned long long w0l, w0h, w1l, w1h;
            LDSV2(w0l, w0h, wu + kk * 16);
            LDSV2(w1l, w1h, wu + 8 * ST * 16 + kk * 16);
#pragma unroll
            for (int s = 0; s < 4; s++) {
                unsigned long long xl, xh;
                LDSV2(xl, xh, xu + (unsigned)(s * 4 * ST) * 16u + kk * 16);
                FMA2(acc[s][0], xl, w0l); FMA2(acc[s][0], xh, w0h);
                FMA2(acc[s][1], xl, w1l); FMA2(acc[s][1], xh, w1h);
            }
        }
        __syncthreads();

        // ---- stage result (aliases x region) ----
#pragma unroll
        for (int s = 0; s < 4; s++) {
            const int le = p * 16 + egrp + 4 * s;
            float e0, e1;
            UNPACK2(e0, e1, acc[s][0]);
            *(float2*)&sef[le * SEF + 2 * j0] = make_float2(e0, e1);
            UNPACK2(e0, e1, acc[s][1]);
            *(float2*)&sef[le * SEF + 2 * j1] = make_float2(e0, e1);
        }
        __syncthreads();

        // ---- epilogue: owning warp w, its 8 edges ----
#pragma unroll
        for (int e = 0; e < 8; e++) {
            const int le = w * 8 + e;
            const float2 efv = *(const float2*)&sef[le * SEF + 2 * lane];
            const float2 a = acv[e];
            float s2 = efv.x + efv.y + a.x + a.y;
            float ss2 = efv.x * efv.x + efv.y * efv.y + a.x * a.x + a.y * a.y;
            const float T = wsum(s2), TT = wsum(ss2);
            const float m2 = T * (1.0f / 128.0f);
            const float ri2 = rsqrtf(TT * (1.0f / 128.0f) - m2 * m2 + 1e-5f);
            float sc = ((efv.x - m2) * ri2 * sg2[2 * lane] + sb2[2 * lane]) * sW2[2 * lane]
                     + ((efv.y - m2) * ri2 * sg2[2 * lane + 1] + sb2[2 * lane + 1]) * sW2[2 * lane + 1]
                     + ((a.x - m2) * ri2 * sg2[64 + 2 * lane] + sb2[64 + 2 * lane]) * sW2[64 + 2 * lane]
                     + ((a.y - m2) * ri2 * sg2[64 + 2 * lane + 1] + sb2[64 + 2 * lane + 1]) * sW2[64 + 2 * lane + 1];
            sc = wsum(sc) + b2v;
            if (lane == 0) g_score[g0 + le] = sc;
            runmax = fmaxf(runmax, sc);
            ((float2*)g_ef)[(size_t)(g0 + le) * 32 + lane] = efv;
        }
        __syncthreads();
    }
    if (lane == 0) smax_s[w] = runmax;
    __syncthreads();
    if (tid == 0) {
        float m = smax_s[0];
        for (int i = 1; i < 8; i++) m = fmaxf(m, smax_s[i]);
        atomicMax(&g_umax, enc_key(m));
    }
}

__global__ void __launch_bounds__(256) k_sumexp() {
    __shared__ float sred[256];
    const float mx = dec_key(g_umax);
    float v = 0.f;
    for (int i = blockIdx.x * 256 + threadIdx.x; i < NE; i += gridDim.x * 256)
        v += expf(g_score[i] - mx);
    sred[threadIdx.x] = v;
    __syncthreads();
    for (int o = 128; o; o >>= 1) {
        if (threadIdx.x < o) sred[threadIdx.x] += sred[threadIdx.x + o];
        __syncthreads();
    }
    if (threadIdx.x == 0) atomicAdd(&g_sumexp, sred[0]);
}

__global__ void __launch_bounds__(256) k_scatter(const int* __restrict__ eidx) {
    const int e = blockIdx.x * 8 + (threadIdx.x >> 5);
    if (e >= NE) return;
    const int lane = threadIdx.x & 31;
    const float wgt = expf(g_score[e] - dec_key(g_umax)) / g_sumexp;
    const int c = eidx[e];
    if (lane < 16) {
        const float4 v = ((const float4*)g_ef)[(size_t)e * 16 + lane];
        float* dst = &g_pooled[(size_t)c * 64 + 4 * lane];
        asm volatile("red.global.add.v4.f32 [%0], {%1,%2,%3,%4};"
                     :: "l"(dst), "f"(wgt * v.x), "f"(wgt * v.y),
                        "f"(wgt * v.z), "f"(wgt * v.w) : "memory");
    }
}

// ---------------- K4: upd = LN3([ef,pooled[ec]])@W3+b3 ; gate ; out ----------------
// dyn smem: sW 35328 | sx 70656 (sef aliased) | params 1280
#define K4_SMEM 107264
__global__ void __launch_bounds__(256, 2) k_edge2(
    const int* __restrict__ eidx, const float* __restrict__ elen,
    const float* __restrict__ ln3g, const float* __restrict__ ln3b,
    const float* __restrict__ W3, const float* __restrict__ b3,
    const float* __restrict__ resp, float* __restrict__ out)
{
    extern __shared__ __align__(16) char dsm[];
    float4* sW = (float4*)dsm;
    float4* sx = (float4*)(dsm + 35328);
    float*  sef = (float*)(dsm + 35328);
    float* sg3 = (float*)(dsm + 35328 + 70656);
    float* sb3 = sg3 + 128;
    float* b3e = sb3 + 128;

    const int tid = threadIdx.x;
    for (int i = tid; i < 64 * 32; i += 256) {
        const int kk = i >> 5, j = i & 31;
        sW[j * ST + kk] = make_float4(
            W3[(2 * kk) * 64 + 2 * j], W3[(2 * kk) * 64 + 2 * j + 1],
            W3[(2 * kk + 1) * 64 + 2 * j], W3[(2 * kk + 1) * 64 + 2 * j + 1]);
    }
    for (int i = tid; i < 128; i += 256) { sg3[i] = ln3g[i]; sb3[i] = ln3b[i]; }
    if (tid < 64) b3e[tid] = b3[tid];
    __syncthreads();

    const float pr = resp[0];
    const float uc = 1.0f / (1.0f + expf(-pr));
    const float cc = rsqrtf(uc * uc + 1.0f);
    const float ssc = uc * cc * (1.0f + cc + cc * cc);   // 3 recycles collapsed

    const int w = tid >> 5, lane = tid & 31;
    const int p = w >> 1, q = w & 1;
    const int egrp = lane >> 3, cpg = lane & 7;
    const unsigned sx_u = s2u(sx);
    const unsigned xu = sx_u + (unsigned)((p * 16 + egrp) * ST) * 16u;
    const unsigned wu = s2u(sW) + (unsigned)((q * 16 + cpg) * ST) * 16u;
    const int j0 = q * 16 + cpg, j1 = j0 + 8;
    unsigned long long bias0, bias1;
    PACK2(bias0, b3e[2 * j0], b3e[2 * j0 + 1]);
    PACK2(bias1, b3e[2 * j1], b3e[2 * j1 + 1]);

    for (int g0 = blockIdx.x * 64; g0 < NE; g0 += gridDim.x * 64) {
        float rr_[8];
        {
            int cI[8];
#pragma unroll
            for (int e = 0; e < 8; e++) {
                const int ge = g0 + w * 8 + e;
                cI[e] = eidx[ge]; rr_[e] = elen[ge];
            }
            float2 efv[8], pcv[8];
#pragma unroll
            for (int e = 0; e < 8; e++) {
                efv[e] = ((const float2*)g_ef)[(size_t)(g0 + w * 8 + e) * 32 + lane];
                pcv[e] = ((const float2*)g_pooled)[(size_t)cI[e] * 32 + lane];
            }
#pragma unroll
            for (int e = 0; e < 8; e++) {
                const float2 ef = efv[e], pc = pcv[e];
                float ls = ef.x + ef.y + pc.x + pc.y;
                float lss = ef.x * ef.x + ef.y * ef.y + pc.x * pc.x + pc.y * pc.y;
                const float S = wsum(ls), SS = wsum(lss);
                const float mean = S * (1.0f / 128.0f);
                const float ri = rsqrtf(SS * (1.0f / 128.0f) - mean * mean + 1e-5f);
                const int eb = (w * 8 + e) * ST;
                const float x0 = (ef.x - mean) * ri * sg3[2 * lane] + sb3[2 * lane];
                const float x1 = (ef.y - mean) * ri * sg3[2 * lane + 1] + sb3[2 * lane + 1];
                sx[eb + lane] = make_float4(x0, x0, x1, x1);
                const float y0 = (pc.x - mean) * ri * sg3[64 + 2 * lane] + sb3[64 + 2 * lane];
                const float y1 = (pc.y - mean) * ri * sg3[64 + 2 * lane + 1] + sb3[64 + 2 * lane + 1];
                sx[eb + 32 + lane] = make_float4(y0, y0, y1, y1);
            }
        }
        __syncthreads();

        unsigned long long acc[4][2];
#pragma unroll
        for (int s = 0; s < 4; s++) { acc[s][0] = bias0; acc[s][1] = bias1; }
#pragma unroll 4
        for (int kk = 0; kk < 64; kk++) {
            unsigned long long w0l, w0h, w1l, w1h;
            LDSV2(w0l, w0h, wu + kk * 16);
            LDSV2(w1l, w1h, wu + 8 * ST * 16 + kk * 16);
#pragma unroll
            for (int s = 0; s < 4; s++) {
                unsigned long long xl, xh;
                LDSV2(xl, xh, xu + (unsigned)(s * 4 * ST) * 16u + kk * 16);
                FMA2(acc[s][0], xl, w0l); FMA2(acc[s][0], xh, w0h);
                FMA2(acc[s][1], xl, w1l); FMA2(acc[s][1], xh, w1h);
            }
        }
        __syncthreads();

#pragma unroll
        for (int s = 0; s < 4; s++) {
            const int le = p * 16 + egrp + 4 * s;
            float e0, e1;
            UNPACK2(e0, e1, acc[s][0]);
            *(float2*)&sef[le * SEF + 2 * j0] = make_float2(e0, e1);
            UNPACK2(e0, e1, acc[s][1]);
            *(float2*)&sef[le * SEF + 2 * j1] = make_float2(e0, e1);
        }
        __syncthreads();

        // epilogue: owning warp, gate lerp + scale + store
#pragma unroll
        for (int e = 0; e < 8; e++) {
            const int le = w * 8 + e;
            const float2 uv = *(const float2*)&sef[le * SEF + 2 * lane];
            float u = (rr_[e] - 0.5f) * ((float)TBL / 5.5f);
            u = fminf(fmaxf(u, 0.f), (float)TBL - 0.001f);
            const int gi = (int)u;
            const float fr = u - (float)gi;
            const float2 lo = ((const float2*)g_gate)[(size_t)gi * 32 + lane];
            const float2 hi = ((const float2*)g_gate)[(size_t)(gi + 1) * 32 + lane];
            const float ga = fmaf(fr, hi.x - lo.x, lo.x);
            const float gb = fmaf(fr, hi.y - lo.y, lo.y);
            ((float2*)out)[(size_t)(g0 + le) * 32 + lane] =
                make_float2(uv.x * ga * ssc, uv.y * gb * ssc);
        }
        __syncthreads();
    }
}

extern "C" void kernel_launch(void* const* d_in, const int* in_sizes, int n_in,
                              void* d_out, int out_size) {
    const int*   eidx  = (const int*)d_in[0];
    const float* elen  = (const float*)d_in[1];
    const float* nattr = (const float*)d_in[2];
    const float* ln1g  = (const float*)d_in[3];
    const float* ln1b  = (const float*)d_in[4];
    const float* W1    = (const float*)d_in[5];
    const float* b1    = (const float*)d_in[6];
    const float* ln2g  = (const float*)d_in[7];
    const float* ln2b  = (const float*)d_in[8];
    const float* W2    = (const float*)d_in[9];
    const float* b2    = (const float*)d_in[10];
    const float* ln3g  = (const float*)d_in[11];
    const float* ln3b  = (const float*)d_in[12];
    const float* W3    = (const float*)d_in[13];
    const float* b3    = (const float*)d_in[14];
    const float* fW1   = (const float*)d_in[15];
    const float* fW2   = (const float*)d_in[16];
    const float* resp  = (const float*)d_in[17];
    float* out = (float*)d_out;

    static int once = 0;
    if (!once) {
        cudaFuncSetAttribute(k_edge1, cudaFuncAttributeMaxDynamicSharedMemorySize, K1_SMEM);
        cudaFuncSetAttribute(k_edge2, cudaFuncAttributeMaxDynamicSharedMemorySize, K4_SMEM);
        once = 1;
    }
    k_init<<<2048, 256>>>();
    k_gate<<<(TBL + 8) / 8, 256>>>(fW1, fW2);
    k_edge1<<<296, 256, K1_SMEM>>>(eidx, elen, nattr, ln1g, ln1b, W1, b1, ln2g, ln2b, W2, b2);
    k_sumexp<<<592, 256>>>();
    k_scatter<<<(NE + 7) / 8, 256>>>(eidx);
    k_edge2<<<296, 256, K4_SMEM>>>(eidx, elen, ln3g, ln3b, W3, b3, resp, out);
}

// round 8
// speedup vs baseline: 2.5081x; 2.5081x over previous
#include <cuda_runtime.h>
#include <math.h>
#include <stdint.h>

#define NE 640000
#define NN 20000
#define TBL 8192

// ---- device scratch (no allocations) ----
__device__ float g_M13[4096], g_M23[4096];
__device__ float g_s1[64], g_c1[64], g_u1[64], g_w1[64], g_s3[64], g_c3[64], g_gw2a[64];
__device__ float g_S2, g_C2;
__device__ float g_Pc[NN * 64], g_Pn[NN * 64], g_Yc[NN * 64], g_Yn[NN * 64], g_PP[NN * 64];
__device__ float4 g_nodeA[NN];   // sumA, sumsqA, w2a, 0
__device__ float2 g_nodeB[NN];   // sumPool, sumsqPool
__device__ float g_T[(TBL + 1) * 64], g_T3[(TBL + 1) * 64], g_gate[(TBL + 1) * 64];
__device__ float2 g_tsc[TBL + 1];
__device__ float g_score[NE];
__device__ float2 g_efsc[NE];    // sum_ef, sumsq_ef
__device__ float g_pooled[NN * 64];
__device__ unsigned g_umax;
__device__ float g_sumexp;

__device__ __forceinline__ float wsum(float v) {
#pragma unroll
    for (int o = 16; o; o >>= 1) v += __shfl_xor_sync(0xffffffffu, v, o);
    return v;
}
__device__ __forceinline__ unsigned enc_key(float f) {
    int b = __float_as_int(f);
    return (b >= 0) ? ((unsigned)b | 0x80000000u) : ~(unsigned)b;
}
__device__ __forceinline__ float dec_key(unsigned u) {
    int b = (u & 0x80000000u) ? (int)(u ^ 0x80000000u) : ~(int)u;
    return __int_as_float(b);
}
__device__ __forceinline__ void bessel8(float r, float* rb) {
    float t = r * (1.0f / 6.0f), t2 = t * t, t6 = t2 * t2 * t2;
    float ct = tanhf(1.0f - t6);
    const float pre = 0.57735026918962576f / r * (ct * ct * ct);
    const float th = r * 0.5235987755982988f;
    const float tc = 2.f * cosf(th);
    float sm1 = 0.f, sc = sinf(th);
#pragma unroll
    for (int n = 0; n < 8; n++) {
        rb[n] = pre * sc;
        const float nx = tc * sc - sm1;
        sm1 = sc; sc = nx;
    }
}

__global__ void k_init() {
    int i = blockIdx.x * blockDim.x + threadIdx.x;
    for (; i < NN * 64; i += gridDim.x * blockDim.x) g_pooled[i] = 0.f;
    if (blockIdx.x == 0 && threadIdx.x == 0) { g_umax = 0u; g_sumexp = 0.f; }
}

// ---------------- matrix precomputes (single block) ----------------
#define MATS_SMEM 86592
__global__ void __launch_bounds__(256) k_mats(
    const float* __restrict__ W1, const float* __restrict__ b1,
    const float* __restrict__ ln1g, const float* __restrict__ ln1b,
    const float* __restrict__ ln2g, const float* __restrict__ ln2b,
    const float* __restrict__ W2, const float* __restrict__ b2,
    const float* __restrict__ ln3g, const float* __restrict__ ln3b,
    const float* __restrict__ W3, const float* __restrict__ b3)
{
    extern __shared__ float sm[];
    float* W1s = sm;             // 8704
    float* W3s = W1s + 8704;     // 8192
    float* G3a = W3s + 8192;     // 4096
    float* ss1 = G3a + 4096;     // 64
    float* sc1 = ss1 + 64;       // 64
    float* g1s = sc1 + 64;       // 136
    float* b1s = g1s + 136;      // 136
    float* g3s = b1s + 136;      // 128
    float* b3s = g3s + 128;      // 128
    const int tid = threadIdx.x;
    for (int i = tid; i < 8704; i += 256) W1s[i] = W1[i];
    for (int i = tid; i < 8192; i += 256) W3s[i] = W3[i];
    for (int i = tid; i < 136; i += 256) { g1s[i] = ln1g[i]; b1s[i] = ln1b[i]; }
    for (int i = tid; i < 128; i += 256) { g3s[i] = ln3g[i]; b3s[i] = ln3b[i]; }
    __syncthreads();
    for (int i = tid; i < 4096; i += 256) G3a[i] = g3s[i >> 6] * W3s[i];
    if (tid < 64) {
        float s = 0.f, c = 0.f;
        for (int k = 0; k < 136; k++) {
            s = fmaf(g1s[k], W1s[k * 64 + tid], s);
            c = fmaf(b1s[k], W1s[k * 64 + tid], c);
        }
        ss1[tid] = s; sc1[tid] = c + b1[tid];
        g_s1[tid] = s; g_c1[tid] = sc1[tid];
    } else if (tid < 128) {
        const int j = tid - 64;
        float s = 0.f, c = 0.f;
        for (int k = 0; k < 128; k++) {
            s = fmaf(g3s[k], W3s[k * 64 + j], s);
            c = fmaf(b3s[k], W3s[k * 64 + j], c);
        }
        g_s3[j] = s; g_c3[j] = c + b3[j];
    } else if (tid < 192) {
        const int j = tid - 128;
        g_gw2a[j] = ln2g[j] * W2[j];
    } else if (tid == 192) {
        float s = 0.f, c = 0.f;
        for (int k = 0; k < 128; k++) { s = fmaf(ln2g[k], W2[k], s); c = fmaf(ln2b[k], W2[k], c); }
        g_S2 = s; g_C2 = c + b2[0];
    }
    __syncthreads();
    if (tid < 64) {
        float a = 0.f, b_ = 0.f;
        for (int k = 0; k < 64; k++) {
            a = fmaf(ss1[k], G3a[k * 64 + tid], a);
            b_ = fmaf(sc1[k], G3a[k * 64 + tid], b_);
        }
        g_u1[tid] = a; g_w1[tid] = b_;
    }
    for (int idx = tid; idx < 4096; idx += 256) {
        const int i = idx >> 6, j = idx & 63;
        float a = 0.f, b_ = 0.f;
        for (int k = 0; k < 64; k++) {
            a = fmaf(W1s[i * 64 + k], G3a[k * 64 + j], a);
            b_ = fmaf(W1s[(64 + i) * 64 + k], G3a[k * 64 + j], b_);
        }
        g_M13[idx] = g1s[i] * a;
        g_M23[idx] = g1s[64 + i] * b_;
    }
}

// ---------------- r-tables: T, T3, gate, scalars ----------------
#define TBLK_SMEM 65536
__global__ void __launch_bounds__(256) k_table(
    const float* __restrict__ W1, const float* __restrict__ ln1g,
    const float* __restrict__ W3, const float* __restrict__ ln3g,
    const float* __restrict__ fW1, const float* __restrict__ fW2)
{
    extern __shared__ float sm[];
    float* G3a = sm;             // 4096
    float* G1b = G3a + 4096;     // 512
    float* f1s = G1b + 512;      // 2048
    float* f2s = f1s + 2048;     // 8192
    float* sT  = f2s + 8192;     // 512
    float* st  = sT + 512;       // 1024
    const int tid = threadIdx.x, w = tid >> 5, lane = tid & 31;
    for (int i = tid; i < 4096; i += 256) G3a[i] = ln3g[i >> 6] * W3[i];
    for (int i = tid; i < 512; i += 256)
        G1b[i] = ln1g[128 + (i >> 6)] * W1[(128 + (i >> 6)) * 64 + (i & 63)];
    for (int i = tid; i < 2048; i += 256) f1s[i] = fW1[i];
    for (int i = tid; i < 8192; i += 256) f2s[i] = fW2[i];
    __syncthreads();
    const int p = blockIdx.x * 8 + w;
    if (p > TBL) return;
    const float r = 0.5f + (5.5f / (float)TBL) * (float)p;
    float rb[8];
    bessel8(r, rb);
    const int j0 = 2 * lane;
    float T0 = 0.f, T1 = 0.f;
#pragma unroll
    for (int i = 0; i < 8; i++) {
        T0 = fmaf(rb[i], G1b[i * 64 + j0], T0);
        T1 = fmaf(rb[i], G1b[i * 64 + j0 + 1], T1);
    }
    sT[w * 64 + j0] = T0; sT[w * 64 + j0 + 1] = T1;
    g_T[p * 64 + j0] = T0; g_T[p * 64 + j0 + 1] = T1;
    __syncwarp();
    float a3 = 0.f, b3_ = 0.f;
#pragma unroll 8
    for (int k = 0; k < 64; k++) {
        const float tv = sT[w * 64 + k];
        a3 = fmaf(tv, G3a[k * 64 + j0], a3);
        b3_ = fmaf(tv, G3a[k * 64 + j0 + 1], b3_);
    }
    g_T3[p * 64 + j0] = a3; g_T3[p * 64 + j0 + 1] = b3_;
#pragma unroll
    for (int j = 0; j < 4; j++) {
        const int k = lane + 32 * j;
        float a = 0.f, g = 0.f;
#pragma unroll
        for (int n = 0; n < 8; n++) {
            a = fmaf(rb[n], f1s[n * 256 + k], a);
            g = fmaf(rb[n], f1s[n * 256 + 128 + k], g);
        }
        st[w * 128 + k] = a / (1.f + expf(-a)) * g;
    }
    __syncwarp();
    float q0 = 0.f, q1 = 0.f;
#pragma unroll 8
    for (int k = 0; k < 128; k++) {
        const float tv = st[w * 128 + k];
        q0 = fmaf(tv, f2s[k * 64 + j0], q0);
        q1 = fmaf(tv, f2s[k * 64 + j0 + 1], q1);
    }
    g_gate[p * 64 + j0] = 1.f / (1.f + expf(-q0));
    g_gate[p * 64 + j0 + 1] = 1.f / (1.f + expf(-q1));
    if (lane == 0) {
        float s = 0.f, q = 0.f;
#pragma unroll
        for (int i = 0; i < 8; i++) { s += rb[i]; q = fmaf(rb[i], rb[i], q); }
        g_tsc[p] = make_float2(s, q);
    }
}

// ---------------- node precomputes: Pc,Pn,Yc,Yn + scalars ----------------
#define NODES_SMEM 67840
__global__ void __launch_bounds__(256) k_nodes(
    const float* __restrict__ nattr, const float* __restrict__ W1,
    const float* __restrict__ ln1g, const float* __restrict__ ln2g,
    const float* __restrict__ W2)
{
    extern __shared__ float sm[];
    float* sw = sm;              // 16384
    float* sa = sw + 16384;      // 512
    float* gwb = sa + 512;       // 64
    const int tid = threadIdx.x;
    for (int idx = tid; idx < 16384; idx += 256) {
        const int m = idx >> 12, rest = idx & 4095, i = rest >> 6, c = rest & 63;
        float v;
        if (m == 0) v = ln1g[i] * W1[i * 64 + c];
        else if (m == 1) v = ln1g[64 + i] * W1[(64 + i) * 64 + c];
        else if (m == 2) v = g_M13[rest];
        else v = g_M23[rest];
        sw[idx] = v;
    }
    if (tid < 64) gwb[tid] = ln2g[64 + tid] * W2[64 + tid];
    __syncthreads();
    const int m = tid >> 6, c = tid & 63;
    for (int nb = blockIdx.x; nb < NN / 8; nb += gridDim.x) {
        for (int idx = tid; idx < 512; idx += 256)
            sa[idx] = nattr[(size_t)(nb * 8) * 64 + idx];
        __syncthreads();
        float acc[8];
#pragma unroll
        for (int nd = 0; nd < 8; nd++) acc[nd] = 0.f;
#pragma unroll 4
        for (int k = 0; k < 64; k++) {
            const float wv = sw[m * 4096 + k * 64 + c];
#pragma unroll
            for (int nd = 0; nd < 8; nd++) acc[nd] = fmaf(sa[nd * 64 + k], wv, acc[nd]);
        }
        float* dst = (m == 0) ? g_Pc : (m == 1) ? g_Pn : (m == 2) ? g_Yc : g_Yn;
#pragma unroll
        for (int nd = 0; nd < 8; nd++) dst[(size_t)(nb * 8 + nd) * 64 + c] = acc[nd];
        if (tid < 8) {
            float s = 0.f, q = 0.f, w2 = 0.f;
            for (int k = 0; k < 64; k++) {
                const float a = sa[tid * 64 + k];
                s += a; q = fmaf(a, a, q); w2 = fmaf(a, gwb[k], w2);
            }
            g_nodeA[nb * 8 + tid] = make_float4(s, q, w2, 0.f);
        }
        __syncthreads();
    }
}

// ---------------- K1: score + ef scalars (ef never stored) ----------------
#define LERP(lo, hi, f) fmaf(f, (hi) - (lo), lo)
__global__ void __launch_bounds__(256) k_score(const int* __restrict__ eidx,
                                               const float* __restrict__ elen) {
    __shared__ float smax_s[8];
    const int tid = threadIdx.x, w = tid >> 5, lane = tid & 31;
    const float2 s1v = ((const float2*)g_s1)[lane];
    const float2 c1v = ((const float2*)g_c1)[lane];
    const float2 gwv = ((const float2*)g_gw2a)[lane];
    const float S2 = g_S2, C2 = g_C2;
    float runmax = -3.4e38f;
    for (int g0 = blockIdx.x * 32 + w * 4; g0 < NE; g0 += gridDim.x * 32) {
#pragma unroll
        for (int e = 0; e < 4; e++) {
            const int ge = g0 + e;
            const int ec = eidx[ge], en = eidx[NE + ge];
            const float r = elen[ge];
            const float4 nc = g_nodeA[ec], nn = g_nodeA[en];
            const float2 pc = ((const float2*)g_Pc)[ec * 32 + lane];
            const float2 pn = ((const float2*)g_Pn)[en * 32 + lane];
            float u = (r - 0.5f) * ((float)TBL / 5.5f);
            u = fminf(fmaxf(u, 0.f), (float)TBL - 0.001f);
            const int gi = (int)u;
            const float fr = u - (float)gi;
            const float2 tlo = ((const float2*)g_T)[gi * 32 + lane];
            const float2 thi = ((const float2*)g_T)[(gi + 1) * 32 + lane];
            const float2 slo = g_tsc[gi], shi = g_tsc[gi + 1];
            const float m1 = (nc.x + nn.x + LERP(slo.x, shi.x, fr)) * (1.f / 136.f);
            const float ri1 = rsqrtf((nc.y + nn.y + LERP(slo.y, shi.y, fr)) * (1.f / 136.f)
                                     - m1 * m1 + 1e-5f);
            const float ef0 = ri1 * (pc.x + pn.x + LERP(tlo.x, thi.x, fr) - m1 * s1v.x) + c1v.x;
            const float ef1 = ri1 * (pc.y + pn.y + LERP(tlo.y, thi.y, fr) - m1 * s1v.y) + c1v.y;
            const float S_s = wsum(ef0 + ef1);
            const float S_q = wsum(fmaf(ef0, ef0, ef1 * ef1));
            const float S_d = wsum(fmaf(ef0, gwv.x, ef1 * gwv.y));
            const float m2 = (S_s + nc.x) * (1.f / 128.f);
            const float ri2 = rsqrtf((S_q + nc.y) * (1.f / 128.f) - m2 * m2 + 1e-5f);
            const float sc = ri2 * (S_d + nc.z - m2 * S2) + C2;
            if (lane == 0) { g_score[ge] = sc; g_efsc[ge] = make_float2(S_s, S_q); }
            runmax = fmaxf(runmax, sc);
        }
    }
    if (lane == 0) smax_s[w] = runmax;
    __syncthreads();
    if (tid == 0) {
        float m = smax_s[0];
        for (int i = 1; i < 8; i++) m = fmaxf(m, smax_s[i]);
        atomicMax(&g_umax, enc_key(m));
    }
}

__global__ void __launch_bounds__(256) k_sumexp() {
    __shared__ float sred[256];
    const float mx = dec_key(g_umax);
    float v = 0.f;
    for (int i = blockIdx.x * 256 + threadIdx.x; i < NE; i += gridDim.x * 256)
        v += expf(g_score[i] - mx);
    sred[threadIdx.x] = v;
    __syncthreads();
    for (int o = 128; o; o >>= 1) {
        if (threadIdx.x < o) sred[threadIdx.x] += sred[threadIdx.x + o];
        __syncthreads();
    }
    if (threadIdx.x == 0) atomicAdd(&g_sumexp, sred[0]);
}

// ---------------- K3: recompute ef, scatter attn*ef ----------------
__global__ void __launch_bounds__(256) k_scatter(const int* __restrict__ eidx,
                                                 const float* __restrict__ elen) {
    const int tid = threadIdx.x, w = tid >> 5, lane = tid & 31;
    const float2 s1v = ((const float2*)g_s1)[lane];
    const float2 c1v = ((const float2*)g_c1)[lane];
    const float mx = dec_key(g_umax);
    const float inv = 1.f / g_sumexp;
    for (int g0 = blockIdx.x * 32 + w * 4; g0 < NE; g0 += gridDim.x * 32) {
#pragma unroll
        for (int e = 0; e < 4; e++) {
            const int ge = g0 + e;
            const int ec = eidx[ge], en = eidx[NE + ge];
            const float r = elen[ge];
            const float4 nc = g_nodeA[ec], nn = g_nodeA[en];
            const float2 pc = ((const float2*)g_Pc)[ec * 32 + lane];
            const float2 pn = ((const float2*)g_Pn)[en * 32 + lane];
            float u = (r - 0.5f) * ((float)TBL / 5.5f);
            u = fminf(fmaxf(u, 0.f), (float)TBL - 0.001f);
            const int gi = (int)u;
            const float fr = u - (float)gi;
            const float2 tlo = ((const float2*)g_T)[gi * 32 + lane];
            const float2 thi = ((const float2*)g_T)[(gi + 1) * 32 + lane];
            const float2 slo = g_tsc[gi], shi = g_tsc[gi + 1];
            const float m1 = (nc.x + nn.x + LERP(slo.x, shi.x, fr)) * (1.f / 136.f);
            const float ri1 = rsqrtf((nc.y + nn.y + LERP(slo.y, shi.y, fr)) * (1.f / 136.f)
                                     - m1 * m1 + 1e-5f);
            const float ef0 = ri1 * (pc.x + pn.x + LERP(tlo.x, thi.x, fr) - m1 * s1v.x) + c1v.x;
            const float ef1 = ri1 * (pc.y + pn.y + LERP(tlo.y, thi.y, fr) - m1 * s1v.y) + c1v.y;
            const float wgt = expf(g_score[ge] - mx) * inv;
            float* dst = &g_pooled[(size_t)ec * 64 + 2 * lane];
            asm volatile("red.global.add.v2.f32 [%0], {%1,%2};"
                         :: "l"(dst), "f"(wgt * ef0), "f"(wgt * ef1) : "memory");
        }
    }
}

// ---------------- pool projections ----------------
#define POOL_SMEM 18432
__global__ void __launch_bounds__(256) k_poolproj(const float* __restrict__ W3,
                                                  const float* __restrict__ ln3g) {
    extern __shared__ float sm[];
    float* sw1 = sm;            // 4096
    float* sp = sw1 + 4096;     // 512
    const int tid = threadIdx.x;
    for (int idx = tid; idx < 4096; idx += 256)
        sw1[idx] = ln3g[64 + (idx >> 6)] * W3[(64 + (idx >> 6)) * 64 + (idx & 63)];
    __syncthreads();
    const int s = tid >> 6, c = tid & 63;
    for (int nb = blockIdx.x; nb < NN / 8; nb += gridDim.x) {
        for (int idx = tid; idx < 512; idx += 256)
            sp[idx] = g_pooled[(size_t)(nb * 8) * 64 + idx];
        __syncthreads();
        float a0 = 0.f, a1 = 0.f;
#pragma unroll 4
        for (int k = 0; k < 64; k++) {
            const float wv = sw1[k * 64 + c];
            a0 = fmaf(sp[s * 64 + k], wv, a0);
            a1 = fmaf(sp[(s + 4) * 64 + k], wv, a1);
        }
        g_PP[(size_t)(nb * 8 + s) * 64 + c] = a0;
        g_PP[(size_t)(nb * 8 + s + 4) * 64 + c] = a1;
        if (tid < 8) {
            float su = 0.f, q = 0.f;
            for (int k = 0; k < 64; k++) {
                const float a = sp[tid * 64 + k];
                su += a; q = fmaf(a, a, q);
            }
            g_nodeB[nb * 8 + tid] = make_float2(su, q);
        }
        __syncthreads();
    }
}

// ---------------- K4: out = upd * gate * ssc (no GEMV, no reductions) ----------------
__global__ void __launch_bounds__(256) k_out(const int* __restrict__ eidx,
                                             const float* __restrict__ elen,
                                             const float* __restrict__ resp,
                                             float* __restrict__ out) {
    const int tid = threadIdx.x, w = tid >> 5, lane = tid & 31;
    const float2 u1v = ((const float2*)g_u1)[lane];
    const float2 w1v = ((const float2*)g_w1)[lane];
    const float2 s3v = ((const float2*)g_s3)[lane];
    const float2 c3v = ((const float2*)g_c3)[lane];
    const float p = resp[0];
    const float uc = 1.f / (1.f + expf(-p));
    const float cc = rsqrtf(uc * uc + 1.f);
    const float ssc = uc * cc * (1.f + cc + cc * cc);   // 3 recycles collapsed
    for (int g0 = blockIdx.x * 32 + w * 4; g0 < NE; g0 += gridDim.x * 32) {
#pragma unroll
        for (int e = 0; e < 4; e++) {
            const int ge = g0 + e;
            const int ec = eidx[ge], en = eidx[NE + ge];
            const float r = elen[ge];
            const float4 nc = g_nodeA[ec], nn = g_nodeA[en];
            const float2 nb = g_nodeB[ec];
            const float2 es = g_efsc[ge];
            const float2 yc = ((const float2*)g_Yc)[ec * 32 + lane];
            const float2 yn = ((const float2*)g_Yn)[en * 32 + lane];
            const float2 pp = ((const float2*)g_PP)[ec * 32 + lane];
            float u = (r - 0.5f) * ((float)TBL / 5.5f);
            u = fminf(fmaxf(u, 0.f), (float)TBL - 0.001f);
            const int gi = (int)u;
            const float fr = u - (float)gi;
            const float2 t3l = ((const float2*)g_T3)[gi * 32 + lane];
            const float2 t3h = ((const float2*)g_T3)[(gi + 1) * 32 + lane];
            const float2 glo = ((const float2*)g_gate)[gi * 32 + lane];
            const float2 ghi = ((const float2*)g_gate)[(gi + 1) * 32 + lane];
            const float2 slo = g_tsc[gi], shi = g_tsc[gi + 1];
            const float m1 = (nc.x + nn.x + LERP(slo.x, shi.x, fr)) * (1.f / 136.f);
            const float ri1 = rsqrtf((nc.y + nn.y + LERP(slo.y, shi.y, fr)) * (1.f / 136.f)
                                     - m1 * m1 + 1e-5f);
            const float efg0 = ri1 * (yc.x + yn.x + LERP(t3l.x, t3h.x, fr) - m1 * u1v.x) + w1v.x;
            const float efg1 = ri1 * (yc.y + yn.y + LERP(t3l.y, t3h.y, fr) - m1 * u1v.y) + w1v.y;
            const float m3 = (es.x + nb.x) * (1.f / 128.f);
            const float ri3 = rsqrtf((es.y + nb.y) * (1.f / 128.f) - m3 * m3 + 1e-5f);
            const float o0 = (ri3 * (efg0 + pp.x - m3 * s3v.x) + c3v.x) * LERP(glo.x, ghi.x, fr) * ssc;
            const float o1 = (ri3 * (efg1 + pp.y - m3 * s3v.y) + c3v.y) * LERP(glo.y, ghi.y, fr) * ssc;
            ((float2*)out)[(size_t)ge * 32 + lane] = make_float2(o0, o1);
        }
    }
}

extern "C" void kernel_launch(void* const* d_in, const int* in_sizes, int n_in,
                              void* d_out, int out_size) {
    const int*   eidx  = (const int*)d_in[0];
    const float* elen  = (const float*)d_in[1];
    const float* nattr = (const float*)d_in[2];
    const float* ln1g  = (const float*)d_in[3];
    const float* ln1b  = (const float*)d_in[4];
    const float* W1    = (const float*)d_in[5];
    const float* b1    = (const float*)d_in[6];
    const float* ln2g  = (const float*)d_in[7];
    const float* ln2b  = (const float*)d_in[8];
    const float* W2    = (const float*)d_in[9];
    const float* b2    = (const float*)d_in[10];
    const float* ln3g  = (const float*)d_in[11];
    const float* ln3b  = (const float*)d_in[12];
    const float* W3    = (const float*)d_in[13];
    const float* b3    = (const float*)d_in[14];
    const float* fW1   = (const float*)d_in[15];
    const float* fW2   = (const float*)d_in[16];
    const float* resp  = (const float*)d_in[17];
    float* out = (float*)d_out;

    static int once = 0;
    if (!once) {
        cudaFuncSetAttribute(k_mats, cudaFuncAttributeMaxDynamicSharedMemorySize, MATS_SMEM);
        cudaFuncSetAttribute(k_table, cudaFuncAttributeMaxDynamicSharedMemorySize, TBLK_SMEM);
        cudaFuncSetAttribute(k_nodes, cudaFuncAttributeMaxDynamicSharedMemorySize, NODES_SMEM);
        once = 1;
    }
    k_init<<<512, 256>>>();
    k_mats<<<1, 256, MATS_SMEM>>>(W1, b1, ln1g, ln1b, ln2g, ln2b, W2, b2, ln3g, ln3b, W3, b3);
    k_table<<<(TBL + 8) / 8, 256, TBLK_SMEM>>>(W1, ln1g, W3, ln3g, fW1, fW2);
    k_nodes<<<296, 256, NODES_SMEM>>>(nattr, W1, ln1g, ln2g, W2);
    k_score<<<1184, 256>>>(eidx, elen);
    k_sumexp<<<592, 256>>>();
    k_scatter<<<1184, 256>>>(eidx, elen);
    k_poolproj<<<296, 256, POOL_SMEM>>>(W3, ln3g);
    k_out<<<1184, 256>>>(eidx, elen, resp, out);
}

// round 9
// speedup vs baseline: 3.3129x; 1.3209x over previous
#include <cuda_runtime.h>
#include <math.h>
#include <stdint.h>

#define NE 640000
#define NN 20000
#define TBL 8192

__device__ float g_M13[4096], g_M23[4096];
__device__ __align__(16) float g_s1[64], g_c1[64], g_u1[64], g_w1[64], g_s3[64], g_c3[64], g_gw2a[64];
__device__ float g_S2, g_C2;
__device__ __align__(16) float g_Pc[NN * 64], g_Pn[NN * 64], g_Yc[NN * 64], g_Yn[NN * 64], g_PP[NN * 64];
__device__ __align__(16) float4 g_nodeA[NN];   // sumA, sumsqA, w2a, 0
__device__ __align__(16) float2 g_nodeB[NN];   // sumPool, sumsqPool
__device__ __align__(16) float g_T[(TBL + 1) * 64], g_T3[(TBL + 1) * 64], g_gate[(TBL + 1) * 64];
__device__ __align__(16) float2 g_tsc[TBL + 1];
__device__ float g_score[NE];
__device__ __align__(16) float4 g_efsc[NE];    // S_s, S_q, m1, ri1
__device__ __align__(16) float g_pooled[NN * 64];
__device__ unsigned g_umax;
__device__ float g_sumexp;

__device__ __forceinline__ float hsum16(float v) {
#pragma unroll
    for (int o = 8; o; o >>= 1) v += __shfl_xor_sync(0xffffffffu, v, o);
    return v;
}
__device__ __forceinline__ unsigned enc_key(float f) {
    int b = __float_as_int(f);
    return (b >= 0) ? ((unsigned)b | 0x80000000u) : ~(unsigned)b;
}
__device__ __forceinline__ float dec_key(unsigned u) {
    int b = (u & 0x80000000u) ? (int)(u ^ 0x80000000u) : ~(int)u;
    return __int_as_float(b);
}
__device__ __forceinline__ void bessel8(float r, float* rb) {
    float t = r * (1.0f / 6.0f), t2 = t * t, t6 = t2 * t2 * t2;
    float ct = tanhf(1.0f - t6);
    const float pre = 0.57735026918962576f / r * (ct * ct * ct);
    const float th = r * 0.5235987755982988f;
    const float tc = 2.f * cosf(th);
    float sm1 = 0.f, sc = sinf(th);
#pragma unroll
    for (int n = 0; n < 8; n++) {
        rb[n] = pre * sc;
        const float nx = tc * sc - sm1;
        sm1 = sc; sc = nx;
    }
}
#define LERP(lo, hi, f) fmaf(f, (hi) - (lo), lo)
#define LERP4(d, lo, hi, f) do { d.x = LERP(lo.x, hi.x, f); d.y = LERP(lo.y, hi.y, f); \
    d.z = LERP(lo.z, hi.z, f); d.w = LERP(lo.w, hi.w, f); } while (0)

__global__ void k_init() {
    int i = blockIdx.x * blockDim.x + threadIdx.x;
    for (; i < NN * 64; i += gridDim.x * blockDim.x) g_pooled[i] = 0.f;
    if (blockIdx.x == 0 && threadIdx.x == 0) { g_umax = 0u; g_sumexp = 0.f; }
}

// ---------------- matrix precomputes (grid=9: blk0 scalars, blk1-8 M13/M23) ----------------
#define MATS_SMEM 86592
__global__ void __launch_bounds__(256) k_mats(
    const float* __restrict__ W1, const float* __restrict__ b1,
    const float* __restrict__ ln1g, const float* __restrict__ ln1b,
    const float* __restrict__ ln2g, const float* __restrict__ ln2b,
    const float* __restrict__ W2, const float* __restrict__ b2,
    const float* __restrict__ ln3g, const float* __restrict__ ln3b,
    const float* __restrict__ W3, const float* __restrict__ b3)
{
    extern __shared__ float sm[];
    float* W1s = sm;             // 8704
    float* W3s = W1s + 8704;     // 8192
    float* G3a = W3s + 8192;     // 4096
    float* ss1 = G3a + 4096;     // 64
    float* sc1 = ss1 + 64;       // 64
    float* g1s = sc1 + 64;       // 136
    float* b1s = g1s + 136;      // 136
    float* g3s = b1s + 136;      // 128
    float* b3s = g3s + 128;      // 128
    const int tid = threadIdx.x;
    for (int i = tid; i < 8704; i += 256) W1s[i] = W1[i];
    for (int i = tid; i < 8192; i += 256) W3s[i] = W3[i];
    for (int i = tid; i < 136; i += 256) { g1s[i] = ln1g[i]; b1s[i] = ln1b[i]; }
    for (int i = tid; i < 128; i += 256) { g3s[i] = ln3g[i]; b3s[i] = ln3b[i]; }
    __syncthreads();
    for (int i = tid; i < 4096; i += 256) G3a[i] = g3s[i >> 6] * W3s[i];
    if (blockIdx.x == 0) {
        if (tid < 64) {
            float s = 0.f, c = 0.f;
            for (int k = 0; k < 136; k++) {
                s = fmaf(g1s[k], W1s[k * 64 + tid], s);
                c = fmaf(b1s[k], W1s[k * 64 + tid], c);
            }
            ss1[tid] = s; sc1[tid] = c + b1[tid];
            g_s1[tid] = s; g_c1[tid] = sc1[tid];
        } else if (tid < 128) {
            const int j = tid - 64;
            float s = 0.f, c = 0.f;
            for (int k = 0; k < 128; k++) {
                s = fmaf(g3s[k], W3s[k * 64 + j], s);
                c = fmaf(b3s[k], W3s[k * 64 + j], c);
            }
            g_s3[j] = s; g_c3[j] = c + b3[j];
        } else if (tid < 192) {
            const int j = tid - 128;
            g_gw2a[j] = ln2g[j] * W2[j];
        } else if (tid == 192) {
            float s = 0.f, c = 0.f;
            for (int k = 0; k < 128; k++) { s = fmaf(ln2g[k], W2[k], s); c = fmaf(ln2b[k], W2[k], c); }
            g_S2 = s; g_C2 = c + b2[0];
        }
        __syncthreads();
        if (tid < 64) {
            float a = 0.f, b_ = 0.f;
            for (int k = 0; k < 64; k++) {
                a = fmaf(ss1[k], G3a[k * 64 + tid], a);
                b_ = fmaf(sc1[k], G3a[k * 64 + tid], b_);
            }
            g_u1[tid] = a; g_w1[tid] = b_;
        }
    } else {
        const int idx = (blockIdx.x - 1) * 512 + tid;
#pragma unroll
        for (int h = 0; h < 2; h++) {
            const int ix = idx + h * 256, i = ix >> 6, j = ix & 63;
            float a = 0.f, b_ = 0.f;
            for (int k = 0; k < 64; k++) {
                a = fmaf(W1s[i * 64 + k], G3a[k * 64 + j], a);
                b_ = fmaf(W1s[(64 + i) * 64 + k], G3a[k * 64 + j], b_);
            }
            g_M13[ix] = g1s[i] * a;
            g_M23[ix] = g1s[64 + i] * b_;
        }
    }
}

// ---------------- r-tables ----------------
#define TBLK_SMEM 65536
__global__ void __launch_bounds__(256) k_table(
    const float* __restrict__ W1, const float* __restrict__ ln1g,
    const float* __restrict__ W3, const float* __restrict__ ln3g,
    const float* __restrict__ fW1, const float* __restrict__ fW2)
{
    extern __shared__ float sm[];
    float* G3a = sm;             // 4096
    float* G1b = G3a + 4096;     // 512
    float* f1s = G1b + 512;      // 2048
    float* f2s = f1s + 2048;     // 8192
    float* sT  = f2s + 8192;     // 512
    float* st  = sT + 512;       // 1024
    const int tid = threadIdx.x, w = tid >> 5, lane = tid & 31;
    for (int i = tid; i < 4096; i += 256) G3a[i] = ln3g[i >> 6] * W3[i];
    for (int i = tid; i < 512; i += 256)
        G1b[i] = ln1g[128 + (i >> 6)] * W1[(128 + (i >> 6)) * 64 + (i & 63)];
    for (int i = tid; i < 2048; i += 256) f1s[i] = fW1[i];
    for (int i = tid; i < 8192; i += 256) f2s[i] = fW2[i];
    __syncthreads();
    const int p = blockIdx.x * 8 + w;
    if (p > TBL) return;
    const float r = 0.5f + (5.5f / (float)TBL) * (float)p;
    float rb[8];
    bessel8(r, rb);
    const int j0 = 2 * lane;
    float T0 = 0.f, T1 = 0.f;
#pragma unroll
    for (int i = 0; i < 8; i++) {
        T0 = fmaf(rb[i], G1b[i * 64 + j0], T0);
        T1 = fmaf(rb[i], G1b[i * 64 + j0 + 1], T1);
    }
    sT[w * 64 + j0] = T0; sT[w * 64 + j0 + 1] = T1;
    g_T[p * 64 + j0] = T0; g_T[p * 64 + j0 + 1] = T1;
    __syncwarp();
    float a3 = 0.f, b3_ = 0.f;
#pragma unroll 8
    for (int k = 0; k < 64; k++) {
        const float tv = sT[w * 64 + k];
        a3 = fmaf(tv, G3a[k * 64 + j0], a3);
        b3_ = fmaf(tv, G3a[k * 64 + j0 + 1], b3_);
    }
    g_T3[p * 64 + j0] = a3; g_T3[p * 64 + j0 + 1] = b3_;
#pragma unroll
    for (int j = 0; j < 4; j++) {
        const int k = lane + 32 * j;
        float a = 0.f, g = 0.f;
#pragma unroll
        for (int n = 0; n < 8; n++) {
            a = fmaf(rb[n], f1s[n * 256 + k], a);
            g = fmaf(rb[n], f1s[n * 256 + 128 + k], g);
        }
        st[w * 128 + k] = a / (1.f + expf(-a)) * g;
    }
    __syncwarp();
    float q0 = 0.f, q1 = 0.f;
#pragma unroll 8
    for (int k = 0; k < 128; k++) {
        const float tv = st[w * 128 + k];
        q0 = fmaf(tv, f2s[k * 64 + j0], q0);
        q1 = fmaf(tv, f2s[k * 64 + j0 + 1], q1);
    }
    g_gate[p * 64 + j0] = 1.f / (1.f + expf(-q0));
    g_gate[p * 64 + j0 + 1] = 1.f / (1.f + expf(-q1));
    if (lane == 0) {
        float s = 0.f, q = 0.f;
#pragma unroll
        for (int i = 0; i < 8; i++) { s += rb[i]; q = fmaf(rb[i], rb[i], q); }
        g_tsc[p] = make_float2(s, q);
    }
}

// ---------------- node precomputes (transposed weights, float4 k-loop) ----------------
#define NODES_SMEM 71936
__global__ void __launch_bounds__(256) k_nodes(
    const float* __restrict__ nattr, const float* __restrict__ W1,
    const float* __restrict__ ln1g, const float* __restrict__ ln2g,
    const float* __restrict__ W2)
{
    extern __shared__ float sm[];
    float* sw = sm;               // 4*64*68 = 17408 floats
    float* sa = sw + 17408;       // 512
    float* gwb = sa + 512;        // 64
    const int tid = threadIdx.x;
    for (int idx = tid; idx < 4 * 64 * 68; idx += 256) {
        const int m = idx / 4352, rest = idx - m * 4352, c = rest / 68, k = rest - c * 68;
        float v = 0.f;
        if (k < 64) {
            if (m == 0) v = ln1g[k] * W1[k * 64 + c];
            else if (m == 1) v = ln1g[64 + k] * W1[(64 + k) * 64 + c];
            else if (m == 2) v = g_M13[k * 64 + c];
            else v = g_M23[k * 64 + c];
        }
        sw[idx] = v;
    }
    if (tid < 64) gwb[tid] = ln2g[64 + tid] * W2[64 + tid];
    __syncthreads();
    const int m = tid >> 6, c = tid & 63;
    const float4* swq = (const float4*)(sw + m * 4352 + c * 68);
    for (int nb = blockIdx.x; nb < NN / 8; nb += gridDim.x) {
        for (int idx = tid; idx < 512; idx += 256)
            sa[idx] = nattr[(size_t)(nb * 8) * 64 + idx];
        __syncthreads();
        float acc[8];
#pragma unroll
        for (int nd = 0; nd < 8; nd++) acc[nd] = 0.f;
#pragma unroll
        for (int k4 = 0; k4 < 16; k4++) {
            const float4 wv = swq[k4];
#pragma unroll
            for (int nd = 0; nd < 8; nd++) {
                const float4 av = *(const float4*)(sa + nd * 64 + 4 * k4);
                acc[nd] = fmaf(av.x, wv.x, fmaf(av.y, wv.y,
                          fmaf(av.z, wv.z, fmaf(av.w, wv.w, acc[nd]))));
            }
        }
        float* dst = (m == 0) ? g_Pc : (m == 1) ? g_Pn : (m == 2) ? g_Yc : g_Yn;
#pragma unroll
        for (int nd = 0; nd < 8; nd++) dst[(size_t)(nb * 8 + nd) * 64 + c] = acc[nd];
        if (tid < 8) {
            float s = 0.f, q = 0.f, w2 = 0.f;
            for (int k = 0; k < 64; k++) {
                const float a = sa[tid * 64 + k];
                s += a; q = fmaf(a, a, q); w2 = fmaf(a, gwb[k], w2);
            }
            g_nodeA[nb * 8 + tid] = make_float4(s, q, w2, 0.f);
        }
        __syncthreads();
    }
}

// ---------------- K1: score + (S_s,S_q,m1,ri1) per edge ----------------
__global__ void __launch_bounds__(256) k_score(const int* __restrict__ eidx,
                                               const float* __restrict__ elen) {
    __shared__ float smax_s[8];
    const int tid = threadIdx.x, w = tid >> 5, lane = tid & 31;
    const int g = lane >> 4, l = lane & 15;
    const float4 s1q = ((const float4*)g_s1)[l];
    const float4 c1q = ((const float4*)g_c1)[l];
    const float4 gwq = ((const float4*)g_gw2a)[l];
    const float S2 = g_S2, C2 = g_C2;
    float runmax = -3.4e38f;
    for (int base = blockIdx.x * 64 + w * 8 + g * 4; base < NE; base += gridDim.x * 64) {
#pragma unroll
        for (int e = 0; e < 4; e++) {
            const int ge = base + e;
            const int ec = eidx[ge], en = eidx[NE + ge];
            const float r = elen[ge];
            const float4 nc = g_nodeA[ec], nn = g_nodeA[en];
            const float4 pc = ((const float4*)g_Pc)[ec * 16 + l];
            const float4 pn = ((const float4*)g_Pn)[en * 16 + l];
            float u = (r - 0.5f) * ((float)TBL / 5.5f);
            u = fminf(fmaxf(u, 0.f), (float)TBL - 0.001f);
            const int gi = (int)u;
            const float fr = u - (float)gi;
            const float4 tlo = ((const float4*)g_T)[gi * 16 + l];
            const float4 thi = ((const float4*)g_T)[(gi + 1) * 16 + l];
            const float2 slo = g_tsc[gi], shi = g_tsc[gi + 1];
            const float m1 = (nc.x + nn.x + LERP(slo.x, shi.x, fr)) * (1.f / 136.f);
            const float ri1 = rsqrtf((nc.y + nn.y + LERP(slo.y, shi.y, fr)) * (1.f / 136.f)
                                     - m1 * m1 + 1e-5f);
            float4 T; LERP4(T, tlo, thi, fr);
            float4 ef;
            ef.x = ri1 * (pc.x + pn.x + T.x - m1 * s1q.x) + c1q.x;
            ef.y = ri1 * (pc.y + pn.y + T.y - m1 * s1q.y) + c1q.y;
            ef.z = ri1 * (pc.z + pn.z + T.z - m1 * s1q.z) + c1q.z;
            ef.w = ri1 * (pc.w + pn.w + T.w - m1 * s1q.w) + c1q.w;
            const float S_s = hsum16(ef.x + ef.y + ef.z + ef.w);
            const float S_q = hsum16(fmaf(ef.x, ef.x, fmaf(ef.y, ef.y, fmaf(ef.z, ef.z, ef.w * ef.w))));
            const float S_d = hsum16(fmaf(ef.x, gwq.x, fmaf(ef.y, gwq.y, fmaf(ef.z, gwq.z, ef.w * gwq.w))));
            const float m2 = (S_s + nc.x) * (1.f / 128.f);
            const float ri2 = rsqrtf((S_q + nc.y) * (1.f / 128.f) - m2 * m2 + 1e-5f);
            const float sc = ri2 * (S_d + nc.z - m2 * S2) + C2;
            if (l == 0) { g_score[ge] = sc; g_efsc[ge] = make_float4(S_s, S_q, m1, ri1); }
            runmax = fmaxf(runmax, sc);
        }
    }
#pragma unroll
    for (int o = 16; o; o >>= 1) runmax = fmaxf(runmax, __shfl_xor_sync(0xffffffffu, runmax, o));
    if (lane == 0) smax_s[w] = runmax;
    __syncthreads();
    if (tid == 0) {
        float m = smax_s[0];
        for (int i = 1; i < 8; i++) m = fmaxf(m, smax_s[i]);
        atomicMax(&g_umax, enc_key(m));
    }
}

__global__ void __launch_bounds__(256) k_sumexp() {
    __shared__ float sred[256];
    const float mx = dec_key(g_umax);
    float v = 0.f;
    for (int i = blockIdx.x * 256 + threadIdx.x; i < NE; i += gridDim.x * 256)
        v += expf(g_score[i] - mx);
    sred[threadIdx.x] = v;
    __syncthreads();
    for (int o = 128; o; o >>= 1) {
        if (threadIdx.x < o) sred[threadIdx.x] += sred[threadIdx.x + o];
        __syncthreads();
    }
    if (threadIdx.x == 0) atomicAdd(&g_sumexp, sred[0]);
}

// ---------------- K3: recompute ef (m1,ri1 from efsc), red.v4 scatter ----------------
__global__ void __launch_bounds__(256) k_scatter(const int* __restrict__ eidx,
                                                 const float* __restrict__ elen) {
    const int tid = threadIdx.x, w = tid >> 5, lane = tid & 31;
    const int g = lane >> 4, l = lane & 15;
    const float4 s1q = ((const float4*)g_s1)[l];
    const float4 c1q = ((const float4*)g_c1)[l];
    const float mx = dec_key(g_umax);
    const float inv = 1.f / g_sumexp;
    for (int base = blockIdx.x * 64 + w * 8 + g * 4; base < NE; base += gridDim.x * 64) {
#pragma unroll
        for (int e = 0; e < 4; e++) {
            const int ge = base + e;
            const int ec = eidx[ge], en = eidx[NE + ge];
            const float r = elen[ge];
            const float4 es = g_efsc[ge];   // m1=.z ri1=.w
            const float4 pc = ((const float4*)g_Pc)[ec * 16 + l];
            const float4 pn = ((const float4*)g_Pn)[en * 16 + l];
            float u = (r - 0.5f) * ((float)TBL / 5.5f);
            u = fminf(fmaxf(u, 0.f), (float)TBL - 0.001f);
            const int gi = (int)u;
            const float fr = u - (float)gi;
            const float4 tlo = ((const float4*)g_T)[gi * 16 + l];
            const float4 thi = ((const float4*)g_T)[(gi + 1) * 16 + l];
            float4 T; LERP4(T, tlo, thi, fr);
            const float m1 = es.z, ri1 = es.w;
            const float wgt = expf(g_score[ge] - mx) * inv;
            float4 ef;
            ef.x = (ri1 * (pc.x + pn.x + T.x - m1 * s1q.x) + c1q.x) * wgt;
            ef.y = (ri1 * (pc.y + pn.y + T.y - m1 * s1q.y) + c1q.y) * wgt;
            ef.z = (ri1 * (pc.z + pn.z + T.z - m1 * s1q.z) + c1q.z) * wgt;
            ef.w = (ri1 * (pc.w + pn.w + T.w - m1 * s1q.w) + c1q.w) * wgt;
            float* dst = &g_pooled[(size_t)ec * 64 + 4 * l];
            asm volatile("red.global.add.v4.f32 [%0], {%1,%2,%3,%4};"
                         :: "l"(dst), "f"(ef.x), "f"(ef.y), "f"(ef.z), "f"(ef.w) : "memory");
        }
    }
}

// ---------------- pool projections ----------------
#define POOL_SMEM 18432
__global__ void __launch_bounds__(256) k_poolproj(const float* __restrict__ W3,
                                                  const float* __restrict__ ln3g) {
    extern __shared__ float sm[];
    float* sw1 = sm;            // 4096
    float* sp = sw1 + 4096;     // 512
    const int tid = threadIdx.x;
    for (int idx = tid; idx < 4096; idx += 256)
        sw1[idx] = ln3g[64 + (idx >> 6)] * W3[(64 + (idx >> 6)) * 64 + (idx & 63)];
    __syncthreads();
    const int s = tid >> 6, c = tid & 63;
    for (int nb = blockIdx.x; nb < NN / 8; nb += gridDim.x) {
        for (int idx = tid; idx < 512; idx += 256)
            sp[idx] = g_pooled[(size_t)(nb * 8) * 64 + idx];
        __syncthreads();
        float a0 = 0.f, a1 = 0.f;
#pragma unroll 4
        for (int k = 0; k < 64; k++) {
            const float wv = sw1[k * 64 + c];
            a0 = fmaf(sp[s * 64 + k], wv, a0);
            a1 = fmaf(sp[(s + 4) * 64 + k], wv, a1);
        }
        g_PP[(size_t)(nb * 8 + s) * 64 + c] = a0;
        g_PP[(size_t)(nb * 8 + s + 4) * 64 + c] = a1;
        if (tid < 8) {
            float su = 0.f, q = 0.f;
            for (int k = 0; k < 64; k++) {
                const float a = sp[tid * 64 + k];
                su += a; q = fmaf(a, a, q);
            }
            g_nodeB[nb * 8 + tid] = make_float2(su, q);
        }
        __syncthreads();
    }
}

// ---------------- K4: out (m1,ri1 from efsc; float4 lanes) ----------------
__global__ void __launch_bounds__(256) k_out(const int* __restrict__ eidx,
                                             const float* __restrict__ elen,
                                             const float* __restrict__ resp,
                                             float* __restrict__ out) {
    const int tid = threadIdx.x, w = tid >> 5, lane = tid & 31;
    const int g = lane >> 4, l = lane & 15;
    const float4 u1q = ((const float4*)g_u1)[l];
    const float4 w1q = ((const float4*)g_w1)[l];
    const float4 s3q = ((const float4*)g_s3)[l];
    const float4 c3q = ((const float4*)g_c3)[l];
    const float p = resp[0];
    const float uc = 1.f / (1.f + expf(-p));
    const float cc = rsqrtf(uc * uc + 1.f);
    const float ssc = uc * cc * (1.f + cc + cc * cc);   // 3 recycles collapsed
    for (int base = blockIdx.x * 64 + w * 8 + g * 4; base < NE; base += gridDim.x * 64) {
#pragma unroll
        for (int e = 0; e < 4; e++) {
            const int ge = base + e;
            const int ec = eidx[ge], en = eidx[NE + ge];
            const float r = elen[ge];
            const float4 es = g_efsc[ge];
            const float2 nb = g_nodeB[ec];
            const float4 yc = ((const float4*)g_Yc)[ec * 16 + l];
            const float4 yn = ((const float4*)g_Yn)[en * 16 + l];
            const float4 pp = ((const float4*)g_PP)[ec * 16 + l];
            float u = (r - 0.5f) * ((float)TBL / 5.5f);
            u = fminf(fmaxf(u, 0.f), (float)TBL - 0.001f);
            const int gi = (int)u;
            const float fr = u - (float)gi;
            const float4 t3l = ((const float4*)g_T3)[gi * 16 + l];
            const float4 t3h = ((const float4*)g_T3)[(gi + 1) * 16 + l];
            const float4 glo = ((const float4*)g_gate)[gi * 16 + l];
            const float4 ghi = ((const float4*)g_gate)[(gi + 1) * 16 + l];
            float4 T3, G;
            LERP4(T3, t3l, t3h, fr);
            LERP4(G, glo, ghi, fr);
            const float m1 = es.z, ri1 = es.w;
            const float m3 = (es.x + nb.x) * (1.f / 128.f);
            const float ri3 = rsqrtf((es.y + nb.y) * (1.f / 128.f) - m3 * m3 + 1e-5f);
            float4 o;
            o.x = (ri3 * (ri1 * (yc.x + yn.x + T3.x - m1 * u1q.x) + w1q.x + pp.x - m3 * s3q.x) + c3q.x) * G.x * ssc;
            o.y = (ri3 * (ri1 * (yc.y + yn.y + T3.y - m1 * u1q.y) + w1q.y + pp.y - m3 * s3q.y) + c3q.y) * G.y * ssc;
            o.z = (ri3 * (ri1 * (yc.z + yn.z + T3.z - m1 * u1q.z) + w1q.z + pp.z - m3 * s3q.z) + c3q.z) * G.z * ssc;
            o.w = (ri3 * (ri1 * (yc.w + yn.w + T3.w - m1 * u1q.w) + w1q.w + pp.w - m3 * s3q.w) + c3q.w) * G.w * ssc;
            ((float4*)out)[(size_t)ge * 16 + l] = o;
        }
    }
}

extern "C" void kernel_launch(void* const* d_in, const int* in_sizes, int n_in,
                              void* d_out, int out_size) {
    const int*   eidx  = (const int*)d_in[0];
    const float* elen  = (const float*)d_in[1];
    const float* nattr = (const float*)d_in[2];
    const float* ln1g  = (const float*)d_in[3];
    const float* ln1b  = (const float*)d_in[4];
    const float* W1    = (const float*)d_in[5];
    const float* b1    = (const float*)d_in[6];
    const float* ln2g  = (const float*)d_in[7];
    const float* ln2b  = (const float*)d_in[8];
    const float* W2    = (const float*)d_in[9];
    const float* b2    = (const float*)d_in[10];
    const float* ln3g  = (const float*)d_in[11];
    const float* ln3b  = (const float*)d_in[12];
    const float* W3    = (const float*)d_in[13];
    const float* b3    = (const float*)d_in[14];
    const float* fW1   = (const float*)d_in[15];
    const float* fW2   = (const float*)d_in[16];
    const float* resp  = (const float*)d_in[17];
    float* out = (float*)d_out;

    static int once = 0;
    if (!once) {
        cudaFuncSetAttribute(k_mats, cudaFuncAttributeMaxDynamicSharedMemorySize, MATS_SMEM);
        cudaFuncSetAttribute(k_table, cudaFuncAttributeMaxDynamicSharedMemorySize, TBLK_SMEM);
        cudaFuncSetAttribute(k_nodes, cudaFuncAttributeMaxDynamicSharedMemorySize, NODES_SMEM);
        once = 1;
    }
    k_init<<<512, 256>>>();
    k_mats<<<9, 256, MATS_SMEM>>>(W1, b1, ln1g, ln1b, ln2g, ln2b, W2, b2, ln3g, ln3b, W3, b3);
    k_table<<<(TBL + 8) / 8, 256, TBLK_SMEM>>>(W1, ln1g, W3, ln3g, fW1, fW2);
    k_nodes<<<296, 256, NODES_SMEM>>>(nattr, W1, ln1g, ln2g, W2);
    k_score<<<1184, 256>>>(eidx, elen);
    k_sumexp<<<592, 256>>>();
    k_scatter<<<1184, 256>>>(eidx, elen);
    k_poolproj<<<296, 256, POOL_SMEM>>>(W3, ln3g);
    k_out<<<1184, 256>>>(eidx, elen, resp, out);
}

// round 11
// speedup vs baseline: 3.5215x; 1.0629x over previous
#include <cuda_runtime.h>
#include <cuda_fp16.h>
#include <math.h>
#include <stdint.h>

#define NE 640000
#define NN 20000
#define TBL 8192

__device__ float g_M13[4096], g_M23[4096];
__device__ __align__(16) float g_s1[64], g_c1[64], g_u1[64], g_w1[64], g_s3[64], g_c3[64], g_gw2a[64];
__device__ float g_S2, g_C2;
__device__ __align__(16) float g_Pc[NN * 64], g_Pn[NN * 64];
__device__ __align__(16) __half g_Ych[NN * 64], g_Ynh[NN * 64], g_PPh[NN * 64];
__device__ __align__(16) float4 g_nodeA[NN];   // sumA, sumsqA, w2a, 0
__device__ __align__(16) float2 g_nodeB[NN];   // sumPool, sumsqPool
__device__ __align__(16) float g_T[(TBL + 1) * 64];
__device__ __align__(16) __half g_C3[(TBL + 1) * 128];  // [0:64)=T3, [64:128)=gate
__device__ __align__(16) float2 g_tsc[TBL + 1];
__device__ float g_score[NE];
__device__ __align__(16) float4 g_efsc[NE];    // S_s, S_q, m1, ri1
__device__ __align__(16) __half g_efh[(size_t)NE * 64];
__device__ __align__(16) float g_pooled[NN * 64];
__device__ unsigned g_umax;
__device__ float g_sumexp;

__device__ __forceinline__ float hsum16(float v) {
#pragma unroll
    for (int o = 8; o; o >>= 1) v += __shfl_xor_sync(0xffffffffu, v, o);
    return v;
}
__device__ __forceinline__ unsigned enc_key(float f) {
    int b = __float_as_int(f);
    return (b >= 0) ? ((unsigned)b | 0x80000000u) : ~(unsigned)b;
}
__device__ __forceinline__ float dec_key(unsigned u) {
    int b = (u & 0x80000000u) ? (int)(u ^ 0x80000000u) : ~(int)u;
    return __int_as_float(b);
}
__device__ __forceinline__ void bessel8(float r, float* rb) {
    float t = r * (1.0f / 6.0f), t2 = t * t, t6 = t2 * t2 * t2;
    float ct = tanhf(1.0f - t6);
    const float pre = 0.57735026918962576f / r * (ct * ct * ct);
    const float th = r * 0.5235987755982988f;
    const float tc = 2.f * cosf(th);
    float sm1 = 0.f, sc = sinf(th);
#pragma unroll
    for (int n = 0; n < 8; n++) {
        rb[n] = pre * sc;
        const float nx = tc * sc - sm1;
        sm1 = sc; sc = nx;
    }
}
__device__ __forceinline__ uint2 f4h(float4 v) {
    __half2 a = __floats2half2_rn(v.x, v.y), b = __floats2half2_rn(v.z, v.w);
    uint2 r; r.x = *(unsigned*)&a; r.y = *(unsigned*)&b; return r;
}
__device__ __forceinline__ float4 h4f(uint2 u) {
    float2 a = __half22float2(*(__half2*)&u.x), b = __half22float2(*(__half2*)&u.y);
    return make_float4(a.x, a.y, b.x, b.y);
}
#define LERP(lo, hi, f) fmaf(f, (hi) - (lo), lo)
#define LERP4(d, lo, hi, f) do { d.x = LERP(lo.x, hi.x, f); d.y = LERP(lo.y, hi.y, f); \
    d.z = LERP(lo.z, hi.z, f); d.w = LERP(lo.w, hi.w, f); } while (0)

__global__ void k_init() {
    int i = blockIdx.x * blockDim.x + threadIdx.x;
    for (; i < NN * 64; i += gridDim.x * blockDim.x) g_pooled[i] = 0.f;
    if (blockIdx.x == 0 && threadIdx.x == 0) { g_umax = 0u; g_sumexp = 0.f; }
}

// ---------------- matrix precomputes ----------------
#define MATS_SMEM 86592
__global__ void __launch_bounds__(256) k_mats(
    const float* __restrict__ W1, const float* __restrict__ b1,
    const float* __restrict__ ln1g, const float* __restrict__ ln1b,
    const float* __restrict__ ln2g, const float* __restrict__ ln2b,
    const float* __restrict__ W2, const float* __restrict__ b2,
    const float* __restrict__ ln3g, const float* __restrict__ ln3b,
    const float* __restrict__ W3, const float* __restrict__ b3)
{
    extern __shared__ float sm[];
    float* W1s = sm;
    float* W3s = W1s + 8704;
    float* G3a = W3s + 8192;
    float* ss1 = G3a + 4096;
    float* sc1 = ss1 + 64;
    float* g1s = sc1 + 64;
    float* b1s = g1s + 136;
    float* g3s = b1s + 136;
    float* b3s = g3s + 128;
    const int tid = threadIdx.x;
    for (int i = tid; i < 8704; i += 256) W1s[i] = W1[i];
    for (int i = tid; i < 8192; i += 256) W3s[i] = W3[i];
    for (int i = tid; i < 136; i += 256) { g1s[i] = ln1g[i]; b1s[i] = ln1b[i]; }
    for (int i = tid; i < 128; i += 256) { g3s[i] = ln3g[i]; b3s[i] = ln3b[i]; }
    __syncthreads();
    for (int i = tid; i < 4096; i += 256) G3a[i] = g3s[i >> 6] * W3s[i];
    if (blockIdx.x == 0) {
        if (tid < 64) {
            float s = 0.f, c = 0.f;
            for (int k = 0; k < 136; k++) {
                s = fmaf(g1s[k], W1s[k * 64 + tid], s);
                c = fmaf(b1s[k], W1s[k * 64 + tid], c);
            }
            ss1[tid] = s; sc1[tid] = c + b1[tid];
            g_s1[tid] = s; g_c1[tid] = sc1[tid];
        } else if (tid < 128) {
            const int j = tid - 64;
            float s = 0.f, c = 0.f;
            for (int k = 0; k < 128; k++) {
                s = fmaf(g3s[k], W3s[k * 64 + j], s);
                c = fmaf(b3s[k], W3s[k * 64 + j], c);
            }
            g_s3[j] = s; g_c3[j] = c + b3[j];
        } else if (tid < 192) {
            const int j = tid - 128;
            g_gw2a[j] = ln2g[j] * W2[j];
        } else if (tid == 192) {
            float s = 0.f, c = 0.f;
            for (int k = 0; k < 128; k++) { s = fmaf(ln2g[k], W2[k], s); c = fmaf(ln2b[k], W2[k], c); }
            g_S2 = s; g_C2 = c + b2[0];
        }
        __syncthreads();
        if (tid < 64) {
            float a = 0.f, b_ = 0.f;
            for (int k = 0; k < 64; k++) {
                a = fmaf(ss1[k], G3a[k * 64 + tid], a);
                b_ = fmaf(sc1[k], G3a[k * 64 + tid], b_);
            }
            g_u1[tid] = a; g_w1[tid] = b_;
        }
    } else {
        const int idx = (blockIdx.x - 1) * 512 + tid;
#pragma unroll
        for (int h = 0; h < 2; h++) {
            const int ix = idx + h * 256, i = ix >> 6, j = ix & 63;
            float a = 0.f, b_ = 0.f;
            for (int k = 0; k < 64; k++) {
                a = fmaf(W1s[i * 64 + k], G3a[k * 64 + j], a);
                b_ = fmaf(W1s[(64 + i) * 64 + k], G3a[k * 64 + j], b_);
            }
            g_M13[ix] = g1s[i] * a;
            g_M23[ix] = g1s[64 + i] * b_;
        }
    }
}

// ---------------- r-tables ----------------
#define TBLK_SMEM 65536
__global__ void __launch_bounds__(256) k_table(
    const float* __restrict__ W1, const float* __restrict__ ln1g,
    const float* __restrict__ W3, const float* __restrict__ ln3g,
    const float* __restrict__ fW1, const float* __restrict__ fW2)
{
    extern __shared__ float sm[];
    float* G3a = sm;
    float* G1b = G3a + 4096;
    float* f1s = G1b + 512;
    float* f2s = f1s + 2048;
    float* sT  = f2s + 8192;
    float* st  = sT + 512;
    const int tid = threadIdx.x, w = tid >> 5, lane = tid & 31;
    for (int i = tid; i < 4096; i += 256) G3a[i] = ln3g[i >> 6] * W3[i];
    for (int i = tid; i < 512; i += 256)
        G1b[i] = ln1g[128 + (i >> 6)] * W1[(128 + (i >> 6)) * 64 + (i & 63)];
    for (int i = tid; i < 2048; i += 256) f1s[i] = fW1[i];
    for (int i = tid; i < 8192; i += 256) f2s[i] = fW2[i];
    __syncthreads();
    const int p = blockIdx.x * 8 + w;
    if (p > TBL) return;
    const float r = 0.5f + (5.5f / (float)TBL) * (float)p;
    float rb[8];
    bessel8(r, rb);
    const int j0 = 2 * lane;
    float T0 = 0.f, T1 = 0.f;
#pragma unroll
    for (int i = 0; i < 8; i++) {
        T0 = fmaf(rb[i], G1b[i * 64 + j0], T0);
        T1 = fmaf(rb[i], G1b[i * 64 + j0 + 1], T1);
    }
    sT[w * 64 + j0] = T0; sT[w * 64 + j0 + 1] = T1;
    g_T[p * 64 + j0] = T0; g_T[p * 64 + j0 + 1] = T1;
    __syncwarp();
    float a3 = 0.f, b3_ = 0.f;
#pragma unroll 8
    for (int k = 0; k < 64; k++) {
        const float tv = sT[w * 64 + k];
        a3 = fmaf(tv, G3a[k * 64 + j0], a3);
        b3_ = fmaf(tv, G3a[k * 64 + j0 + 1], b3_);
    }
    g_C3[p * 128 + j0] = __float2half(a3);
    g_C3[p * 128 + j0 + 1] = __float2half(b3_);
#pragma unroll
    for (int j = 0; j < 4; j++) {
        const int k = lane + 32 * j;
        float a = 0.f, g = 0.f;
#pragma unroll
        for (int n = 0; n < 8; n++) {
            a = fmaf(rb[n], f1s[n * 256 + k], a);
            g = fmaf(rb[n], f1s[n * 256 + 128 + k], g);
        }
        st[w * 128 + k] = a / (1.f + expf(-a)) * g;
    }
    __syncwarp();
    float q0 = 0.f, q1 = 0.f;
#pragma unroll 8
    for (int k = 0; k < 128; k++) {
        const float tv = st[w * 128 + k];
        q0 = fmaf(tv, f2s[k * 64 + j0], q0);
        q1 = fmaf(tv, f2s[k * 64 + j0 + 1], q1);
    }
    g_C3[p * 128 + 64 + j0] = __float2half(1.f / (1.f + expf(-q0)));
    g_C3[p * 128 + 64 + j0 + 1] = __float2half(1.f / (1.f + expf(-q1)));
    if (lane == 0) {
        float s = 0.f, q = 0.f;
#pragma unroll
        for (int i = 0; i < 8; i++) { s += rb[i]; q = fmaf(rb[i], rb[i], q); }
        g_tsc[p] = make_float2(s, q);
    }
}

// ---------------- node precomputes: weights in registers, broadcast LDS ----------------
__global__ void __launch_bounds__(256) k_nodes(
    const float* __restrict__ nattr, const float* __restrict__ W1,
    const float* __restrict__ ln1g, const float* __restrict__ ln2g,
    const float* __restrict__ W2)
{
    __shared__ float sa[512];
    __shared__ float gwb[64];
    const int tid = threadIdx.x;
    const int m = tid >> 6, c = tid & 63;
    float wreg[64];
#pragma unroll 16
    for (int k = 0; k < 64; k++) {
        if (m == 0) wreg[k] = ln1g[k] * W1[k * 64 + c];
        else if (m == 1) wreg[k] = ln1g[64 + k] * W1[(64 + k) * 64 + c];
        else if (m == 2) wreg[k] = g_M13[k * 64 + c];
        else wreg[k] = g_M23[k * 64 + c];
    }
    if (tid < 64) gwb[tid] = ln2g[64 + tid] * W2[64 + tid];
    __syncthreads();
    for (int nb = blockIdx.x; nb < NN / 8; nb += gridDim.x) {
        if (tid < 128) ((float4*)sa)[tid] = ((const float4*)(nattr + (size_t)nb * 512))[tid];
        __syncthreads();
        float acc[8];
#pragma unroll
        for (int nd = 0; nd < 8; nd++) acc[nd] = 0.f;
#pragma unroll
        for (int k4 = 0; k4 < 16; k4++) {
            const float w0 = wreg[4 * k4], w1 = wreg[4 * k4 + 1];
            const float w2 = wreg[4 * k4 + 2], w3 = wreg[4 * k4 + 3];
#pragma unroll
            for (int nd = 0; nd < 8; nd++) {
                const float4 av = *(const float4*)(sa + nd * 64 + 4 * k4);
                acc[nd] = fmaf(av.x, w0, fmaf(av.y, w1, fmaf(av.z, w2, fmaf(av.w, w3, acc[nd]))));
            }
        }
#pragma unroll
        for (int nd = 0; nd < 8; nd++) {
            const size_t off = (size_t)(nb * 8 + nd) * 64 + c;
            if (m == 0) g_Pc[off] = acc[nd];
            else if (m == 1) g_Pn[off] = acc[nd];
            else if (m == 2) g_Ych[off] = __float2half(acc[nd]);
            else g_Ynh[off] = __float2half(acc[nd]);
        }
        if (tid < 8) {
            float s = 0.f, q = 0.f, w2s = 0.f;
            for (int k = 0; k < 64; k++) {
                const float a = sa[tid * 64 + k];
                s += a; q = fmaf(a, a, q); w2s = fmaf(a, gwb[k], w2s);
            }
            g_nodeA[nb * 8 + tid] = make_float4(s, q, w2s, 0.f);
        }
        __syncthreads();
    }
}

// ---------------- K1: score + efsc + fp16 ef ----------------
__global__ void __launch_bounds__(256) k_score(const int* __restrict__ eidx,
                                               const float* __restrict__ elen) {
    __shared__ float smax_s[8];
    const int tid = threadIdx.x, w = tid >> 5, lane = tid & 31;
    const int g = lane >> 4, l = lane & 15;
    const float4 s1q = ((const float4*)g_s1)[l];
    const float4 c1q = ((const float4*)g_c1)[l];
    const float4 gwq = ((const float4*)g_gw2a)[l];
    const float S2 = g_S2, C2 = g_C2;
    float runmax = -3.4e38f;
    for (int base = blockIdx.x * 64 + w * 8 + g * 4; base < NE; base += gridDim.x * 64) {
#pragma unroll
        for (int e = 0; e < 4; e++) {
            const int ge = base + e;
            const int ec = eidx[ge], en = eidx[NE + ge];
            const float r = elen[ge];
            const float4 nc = g_nodeA[ec], nn = g_nodeA[en];
            const float4 pc = ((const float4*)g_Pc)[ec * 16 + l];
            const float4 pn = ((const float4*)g_Pn)[en * 16 + l];
            float u = (r - 0.5f) * ((float)TBL / 5.5f);
            u = fminf(fmaxf(u, 0.f), (float)TBL - 0.001f);
            const int gi = (int)u;
            const float fr = u - (float)gi;
            const float4 tlo = ((const float4*)g_T)[gi * 16 + l];
            const float4 thi = ((const float4*)g_T)[(gi + 1) * 16 + l];
            const float2 slo = g_tsc[gi], shi = g_tsc[gi + 1];
            const float m1 = (nc.x + nn.x + LERP(slo.x, shi.x, fr)) * (1.f / 136.f);
            const float ri1 = rsqrtf((nc.y + nn.y + LERP(slo.y, shi.y, fr)) * (1.f / 136.f)
                                     - m1 * m1 + 1e-5f);
            float4 T; LERP4(T, tlo, thi, fr);
            float4 ef;
            ef.x = ri1 * (pc.x + pn.x + T.x - m1 * s1q.x) + c1q.x;
            ef.y = ri1 * (pc.y + pn.y + T.y - m1 * s1q.y) + c1q.y;
            ef.z = ri1 * (pc.z + pn.z + T.z - m1 * s1q.z) + c1q.z;
            ef.w = ri1 * (pc.w + pn.w + T.w - m1 * s1q.w) + c1q.w;
            *(uint2*)&g_efh[(size_t)ge * 64 + 4 * l] = f4h(ef);
            const float S_s = hsum16(ef.x + ef.y + ef.z + ef.w);
            const float S_q = hsum16(fmaf(ef.x, ef.x, fmaf(ef.y, ef.y, fmaf(ef.z, ef.z, ef.w * ef.w))));
            const float S_d = hsum16(fmaf(ef.x, gwq.x, fmaf(ef.y, gwq.y, fmaf(ef.z, gwq.z, ef.w * gwq.w))));
            const float m2 = (S_s + nc.x) * (1.f / 128.f);
            const float ri2 = rsqrtf((S_q + nc.y) * (1.f / 128.f) - m2 * m2 + 1e-5f);
            const float sc = ri2 * (S_d + nc.z - m2 * S2) + C2;
            if (l == 0) { g_score[ge] = sc; g_efsc[ge] = make_float4(S_s, S_q, m1, ri1); }
            runmax = fmaxf(runmax, sc);
        }
    }
#pragma unroll
    for (int o = 16; o; o >>= 1) runmax = fmaxf(runmax, __shfl_xor_sync(0xffffffffu, runmax, o));
    if (lane == 0) smax_s[w] = runmax;
    __syncthreads();
    if (tid == 0) {
        float m = smax_s[0];
        for (int i = 1; i < 8; i++) m = fmaxf(m, smax_s[i]);
        atomicMax(&g_umax, enc_key(m));
    }
}

__global__ void __launch_bounds__(256) k_sumexp() {
    __shared__ float sred[256];
    const float mx = dec_key(g_umax);
    float v = 0.f;
    for (int i = blockIdx.x * 256 + threadIdx.x; i < NE; i += gridDim.x * 256)
        v += expf(g_score[i] - mx);
    sred[threadIdx.x] = v;
    __syncthreads();
    for (int o = 128; o; o >>= 1) {
        if (threadIdx.x < o) sred[threadIdx.x] += sred[threadIdx.x + o];
        __syncthreads();
    }
    if (threadIdx.x == 0) atomicAdd(&g_sumexp, sred[0]);
}

// ---------------- K3: read fp16 ef, red.v4 scatter ----------------
__global__ void __launch_bounds__(256) k_scatter(const int* __restrict__ eidx) {
    const int tid = threadIdx.x, w = tid >> 5, lane = tid & 31;
    const int g = lane >> 4, l = lane & 15;
    const float mx = dec_key(g_umax);
    const float inv = 1.f / g_sumexp;
    for (int base = blockIdx.x * 64 + w * 8 + g * 4; base < NE; base += gridDim.x * 64) {
#pragma unroll
        for (int e = 0; e < 4; e++) {
            const int ge = base + e;
            const int ec = eidx[ge];
            const float wgt = expf(g_score[ge] - mx) * inv;
            const float4 ef = h4f(*(const uint2*)&g_efh[(size_t)ge * 64 + 4 * l]);
            float* dst = &g_pooled[(size_t)ec * 64 + 4 * l];
            asm volatile("red.global.add.v4.f32 [%0], {%1,%2,%3,%4};"
                         :: "l"(dst), "f"(wgt * ef.x), "f"(wgt * ef.y),
                            "f"(wgt * ef.z), "f"(wgt * ef.w) : "memory");
        }
    }
}

// ---------------- pool projections ----------------
#define POOL_SMEM 18432
__global__ void __launch_bounds__(256) k_poolproj(const float* __restrict__ W3,
                                                  const float* __restrict__ ln3g) {
    extern __shared__ float sm[];
    float* sw1 = sm;
    float* sp = sw1 + 4096;
    const int tid = threadIdx.x;
    for (int idx = tid; idx < 4096; idx += 256)
        sw1[idx] = ln3g[64 + (idx >> 6)] * W3[(64 + (idx >> 6)) * 64 + (idx & 63)];
    __syncthreads();
    const int s = tid >> 6, c = tid & 63;
    for (int nb = blockIdx.x; nb < NN / 8; nb += gridDim.x) {
        for (int idx = tid; idx < 512; idx += 256)
            sp[idx] = g_pooled[(size_t)(nb * 8) * 64 + idx];
        __syncthreads();
        float a0 = 0.f, a1 = 0.f;
#pragma unroll 4
        for (int k = 0; k < 64; k++) {
            const float wv = sw1[k * 64 + c];
            a0 = fmaf(sp[s * 64 + k], wv, a0);
            a1 = fmaf(sp[(s + 4) * 64 + k], wv, a1);
        }
        g_PPh[(size_t)(nb * 8 + s) * 64 + c] = __float2half(a0);
        g_PPh[(size_t)(nb * 8 + s + 4) * 64 + c] = __float2half(a1);
        if (tid < 8) {
            float su = 0.f, q = 0.f;
            for (int k = 0; k < 64; k++) {
                const float a = sp[tid * 64 + k];
                su += a; q = fmaf(a, a, q);
            }
            g_nodeB[nb * 8 + tid] = make_float2(su, q);
        }
        __syncthreads();
    }
}

// ---------------- K4: out (fp16 Yc/Yn/PP/T3/gate) ----------------
__global__ void __launch_bounds__(256) k_out(const int* __restrict__ eidx,
                                             const float* __restrict__ elen,
                                             const float* __restrict__ resp,
                                             float* __restrict__ out) {
    const int tid = threadIdx.x, w = tid >> 5, lane = tid & 31;
    const int g = lane >> 4, l = lane & 15;
    const float4 u1q = ((const float4*)g_u1)[l];
    const float4 w1q = ((const float4*)g_w1)[l];
    const float4 s3q = ((const float4*)g_s3)[l];
    const float4 c3q = ((const float4*)g_c3)[l];
    const float p = resp[0];
    const float uc = 1.f / (1.f + expf(-p));
    const float cc = rsqrtf(uc * uc + 1.f);
    const float ssc = uc * cc * (1.f + cc + cc * cc);   // 3 recycles collapsed
    for (int base = blockIdx.x * 64 + w * 8 + g * 4; base < NE; base += gridDim.x * 64) {
#pragma unroll
        for (int e = 0; e < 4; e++) {
            const int ge = base + e;
            const int ec = eidx[ge], en = eidx[NE + ge];
            const float r = elen[ge];
            const float4 es = g_efsc[ge];
            const float2 nb = g_nodeB[ec];
            const float4 yc = h4f(*(const uint2*)&g_Ych[(size_t)ec * 64 + 4 * l]);
            const float4 yn = h4f(*(const uint2*)&g_Ynh[(size_t)en * 64 + 4 * l]);
            const float4 pp = h4f(*(const uint2*)&g_PPh[(size_t)ec * 64 + 4 * l]);
            float u = (r - 0.5f) * ((float)TBL / 5.5f);
            u = fminf(fmaxf(u, 0.f), (float)TBL - 0.001f);
            const int gi = (int)u;
            const float fr = u - (float)gi;
            const float4 t3l = h4f(*(const uint2*)&g_C3[gi * 128 + 4 * l]);
            const float4 t3h = h4f(*(const uint2*)&g_C3[(gi + 1) * 128 + 4 * l]);
            const float4 glo = h4f(*(const uint2*)&g_C3[gi * 128 + 64 + 4 * l]);
            const float4 ghi = h4f(*(const uint2*)&g_C3[(gi + 1) * 128 + 64 + 4 * l]);
            float4 T3, G;
            LERP4(T3, t3l, t3h, fr);
            LERP4(G, glo, ghi, fr);
            const float m1 = es.z, ri1 = es.w;
            const float m3 = (es.x + nb.x) * (1.f / 128.f);
            const float ri3 = rsqrtf((es.y + nb.y) * (1.f / 128.f) - m3 * m3 + 1e-5f);
            float4 o;
            o.x = (ri3 * (ri1 * (yc.x + yn.x + T3.x - m1 * u1q.x) + w1q.x + pp.x - m3 * s3q.x) + c3q.x) * G.x * ssc;
            o.y = (ri3 * (ri1 * (yc.y + yn.y + T3.y - m1 * u1q.y) + w1q.y + pp.y - m3 * s3q.y) + c3q.y) * G.y * ssc;
            o.z = (ri3 * (ri1 * (yc.z + yn.z + T3.z - m1 * u1q.z) + w1q.z + pp.z - m3 * s3q.z) + c3q.z) * G.z * ssc;
            o.w = (ri3 * (ri1 * (yc.w + yn.w + T3.w - m1 * u1q.w) + w1q.w + pp.w - m3 * s3q.w) + c3q.w) * G.w * ssc;
            ((float4*)out)[(size_t)ge * 16 + l] = o;
        }
    }
}

extern "C" void kernel_launch(void* const* d_in, const int* in_sizes, int n_in,
                              void* d_out, int out_size) {
    const int*   eidx  = (const int*)d_in[0];
    const float* elen  = (const float*)d_in[1];
    const float* nattr = (const float*)d_in[2];
    const float* ln1g  = (const float*)d_in[3];
    const float* ln1b  = (const float*)d_in[4];
    const float* W1    = (const float*)d_in[5];
    const float* b1    = (const float*)d_in[6];
    const float* ln2g  = (const float*)d_in[7];
    const float* ln2b  = (const float*)d_in[8];
    const float* W2    = (const float*)d_in[9];
    const float* b2    = (const float*)d_in[10];
    const float* ln3g  = (const float*)d_in[11];
    const float* ln3b  = (const float*)d_in[12];
    const float* W3    = (const float*)d_in[13];
    const float* b3    = (const float*)d_in[14];
    const float* fW1   = (const float*)d_in[15];
    const float* fW2   = (const float*)d_in[16];
    const float* resp  = (const float*)d_in[17];
    float* out = (float*)d_out;

    static int once = 0;
    if (!once) {
        cudaFuncSetAttribute(k_mats, cudaFuncAttributeMaxDynamicSharedMemorySize, MATS_SMEM);
        cudaFuncSetAttribute(k_table, cudaFuncAttributeMaxDynamicSharedMemorySize, TBLK_SMEM);
        once = 1;
    }
    k_init<<<512, 256>>>();
    k_mats<<<9, 256, MATS_SMEM>>>(W1, b1, ln1g, ln1b, ln2g, ln2b, W2, b2, ln3g, ln3b, W3, b3);
    k_table<<<(TBL + 8) / 8, 256, TBLK_SMEM>>>(W1, ln1g, W3, ln3g, fW1, fW2);
    k_nodes<<<296, 256>>>(nattr, W1, ln1g, ln2g, W2);
    k_score<<<1184, 256>>>(eidx, elen);
    k_sumexp<<<592, 256>>>();
    k_scatter<<<1184, 256>>>(eidx);
    k_poolproj<<<296, 256, POOL_SMEM>>>(W3, ln3g);
    k_out<<<1184, 256>>>(eidx, elen, resp, out);
}

// round 13
// speedup vs baseline: 3.7265x; 1.0582x over previous
#include <cuda_runtime.h>
#include <cuda_fp16.h>
#include <math.h>
#include <stdint.h>

#define NE 640000
#define NN 20000
#define TBL 8192

__device__ float g_M13[4096], g_M23[4096];
__device__ __align__(16) float g_s1[64], g_c1[64], g_u1[64], g_w1[64], g_s3[64], g_c3[64], g_gw2a[64];
__device__ float g_S2, g_C2;
__device__ __align__(16) __half g_Pch[NN * 64], g_Pnh[NN * 64];
__device__ __align__(16) __half g_Ych[NN * 64], g_Ynh[NN * 64], g_PPh[NN * 64];
__device__ __align__(16) float4 g_nodeA[NN];   // sumA, sumsqA, w2a, 0
__device__ __align__(16) float2 g_nodeB[NN];   // sumPool, sumsqPool
__device__ __align__(16) __half g_Th[(TBL + 1) * 64];
__device__ __align__(16) __half g_C3[(TBL + 1) * 128];  // [0:64)=T3, [64:128)=gate
__device__ __align__(16) float2 g_tsc[TBL + 1];
__device__ float g_score[NE];
__device__ __align__(16) float4 g_efsc[NE];    // S_s, S_q, m1, ri1
__device__ __align__(16) __half g_efh[(size_t)NE * 64];
__device__ __align__(16) float g_pooled[NN * 64];
__device__ unsigned g_umax;
__device__ float g_sumexp;

__device__ __forceinline__ float hsum16(float v) {
#pragma unroll
    for (int o = 8; o; o >>= 1) v += __shfl_xor_sync(0xffffffffu, v, o);
    return v;
}
__device__ __forceinline__ unsigned enc_key(float f) {
    int b = __float_as_int(f);
    return (b >= 0) ? ((unsigned)b | 0x80000000u) : ~(unsigned)b;
}
__device__ __forceinline__ float dec_key(unsigned u) {
    int b = (u & 0x80000000u) ? (int)(u ^ 0x80000000u) : ~(int)u;
    return __int_as_float(b);
}
__device__ __forceinline__ void bessel8(float r, float* rb) {
    float t = r * (1.0f / 6.0f), t2 = t * t, t6 = t2 * t2 * t2;
    float ct = tanhf(1.0f - t6);
    const float pre = 0.57735026918962576f / r * (ct * ct * ct);
    const float th = r * 0.5235987755982988f;
    const float tc = 2.f * cosf(th);
    float sm1 = 0.f, sc = sinf(th);
#pragma unroll
    for (int n = 0; n < 8; n++) {
        rb[n] = pre * sc;
        const float nx = tc * sc - sm1;
        sm1 = sc; sc = nx;
    }
}
__device__ __forceinline__ uint2 f4h(float4 v) {
    __half2 a = __floats2half2_rn(v.x, v.y), b = __floats2half2_rn(v.z, v.w);
    uint2 r; r.x = *(unsigned*)&a; r.y = *(unsigned*)&b; return r;
}
__device__ __forceinline__ float4 h4f(uint2 u) {
    float2 a = __half22float2(*(__half2*)&u.x), b = __half22float2(*(__half2*)&u.y);
    return make_float4(a.x, a.y, b.x, b.y);
}
#define LERP(lo, hi, f) fmaf(f, (hi) - (lo), lo)
#define LERP4(d, lo, hi, f) do { d.x = LERP(lo.x, hi.x, f); d.y = LERP(lo.y, hi.y, f); \
    d.z = LERP(lo.z, hi.z, f); d.w = LERP(lo.w, hi.w, f); } while (0)

__global__ void k_init() {
    if (threadIdx.x == 0) { g_umax = 0u; g_sumexp = 0.f; }
}

// ---------------- matrix precomputes ----------------
#define MATS_SMEM 86592
__global__ void __launch_bounds__(256) k_mats(
    const float* __restrict__ W1, const float* __restrict__ b1,
    const float* __restrict__ ln1g, const float* __restrict__ ln1b,
    const float* __restrict__ ln2g, const float* __restrict__ ln2b,
    const float* __restrict__ W2, const float* __restrict__ b2,
    const float* __restrict__ ln3g, const float* __restrict__ ln3b,
    const float* __restrict__ W3, const float* __restrict__ b3)
{
    extern __shared__ float sm[];
    float* W1s = sm;
    float* W3s = W1s + 8704;
    float* G3a = W3s + 8192;
    float* ss1 = G3a + 4096;
    float* sc1 = ss1 + 64;
    float* g1s = sc1 + 64;
    float* b1s = g1s + 136;
    float* g3s = b1s + 136;
    float* b3s = g3s + 128;
    const int tid = threadIdx.x;
    for (int i = tid; i < 8704; i += 256) W1s[i] = W1[i];
    for (int i = tid; i < 8192; i += 256) W3s[i] = W3[i];
    for (int i = tid; i < 136; i += 256) { g1s[i] = ln1g[i]; b1s[i] = ln1b[i]; }
    for (int i = tid; i < 128; i += 256) { g3s[i] = ln3g[i]; b3s[i] = ln3b[i]; }
    __syncthreads();
    for (int i = tid; i < 4096; i += 256) G3a[i] = g3s[i >> 6] * W3s[i];
    if (blockIdx.x == 0) {
        if (tid < 64) {
            float s = 0.f, c = 0.f;
            for (int k = 0; k < 136; k++) {
                s = fmaf(g1s[k], W1s[k * 64 + tid], s);
                c = fmaf(b1s[k], W1s[k * 64 + tid], c);
            }
            ss1[tid] = s; sc1[tid] = c + b1[tid];
            g_s1[tid] = s; g_c1[tid] = sc1[tid];
        } else if (tid < 128) {
            const int j = tid - 64;
            float s = 0.f, c = 0.f;
            for (int k = 0; k < 128; k++) {
                s = fmaf(g3s[k], W3s[k * 64 + j], s);
                c = fmaf(b3s[k], W3s[k * 64 + j], c);
            }
            g_s3[j] = s; g_c3[j] = c + b3[j];
        } else if (tid < 192) {
            const int j = tid - 128;
            g_gw2a[j] = ln2g[j] * W2[j];
        } else if (tid == 192) {
            float s = 0.f, c = 0.f;
            for (int k = 0; k < 128; k++) { s = fmaf(ln2g[k], W2[k], s); c = fmaf(ln2b[k], W2[k], c); }
            g_S2 = s; g_C2 = c + b2[0];
        }
        __syncthreads();
        if (tid < 64) {
            float a = 0.f, b_ = 0.f;
            for (int k = 0; k < 64; k++) {
                a = fmaf(ss1[k], G3a[k * 64 + tid], a);
                b_ = fmaf(sc1[k], G3a[k * 64 + tid], b_);
            }
            g_u1[tid] = a; g_w1[tid] = b_;
        }
    } else {
        const int idx = (blockIdx.x - 1) * 512 + tid;
#pragma unroll
        for (int h = 0; h < 2; h++) {
            const int ix = idx + h * 256, i = ix >> 6, j = ix & 63;
            float a = 0.f, b_ = 0.f;
            for (int k = 0; k < 64; k++) {
                a = fmaf(W1s[i * 64 + k], G3a[k * 64 + j], a);
                b_ = fmaf(W1s[(64 + i) * 64 + k], G3a[k * 64 + j], b_);
            }
            g_M13[ix] = g1s[i] * a;
            g_M23[ix] = g1s[64 + i] * b_;
        }
    }
}

// ---------------- r-tables ----------------
#define TBLK_SMEM 65536
__global__ void __launch_bounds__(256) k_table(
    const float* __restrict__ W1, const float* __restrict__ ln1g,
    const float* __restrict__ W3, const float* __restrict__ ln3g,
    const float* __restrict__ fW1, const float* __restrict__ fW2)
{
    extern __shared__ float sm[];
    float* G3a = sm;
    float* G1b = G3a + 4096;
    float* f1s = G1b + 512;
    float* f2s = f1s + 2048;
    float* sT  = f2s + 8192;
    float* st  = sT + 512;
    const int tid = threadIdx.x, w = tid >> 5, lane = tid & 31;
    for (int i = tid; i < 4096; i += 256) G3a[i] = ln3g[i >> 6] * W3[i];
    for (int i = tid; i < 512; i += 256)
        G1b[i] = ln1g[128 + (i >> 6)] * W1[(128 + (i >> 6)) * 64 + (i & 63)];
    for (int i = tid; i < 2048; i += 256) f1s[i] = fW1[i];
    for (int i = tid; i < 8192; i += 256) f2s[i] = fW2[i];
    __syncthreads();
    const int p = blockIdx.x * 8 + w;
    if (p > TBL) return;
    const float r = 0.5f + (5.5f / (float)TBL) * (float)p;
    float rb[8];
    bessel8(r, rb);
    const int j0 = 2 * lane;
    float T0 = 0.f, T1 = 0.f;
#pragma unroll
    for (int i = 0; i < 8; i++) {
        T0 = fmaf(rb[i], G1b[i * 64 + j0], T0);
        T1 = fmaf(rb[i], G1b[i * 64 + j0 + 1], T1);
    }
    sT[w * 64 + j0] = T0; sT[w * 64 + j0 + 1] = T1;
    g_Th[p * 64 + j0] = __float2half(T0);
    g_Th[p * 64 + j0 + 1] = __float2half(T1);
    __syncwarp();
    float a3 = 0.f, b3_ = 0.f;
#pragma unroll 8
    for (int k = 0; k < 64; k++) {
        const float tv = sT[w * 64 + k];
        a3 = fmaf(tv, G3a[k * 64 + j0], a3);
        b3_ = fmaf(tv, G3a[k * 64 + j0 + 1], b3_);
    }
    g_C3[p * 128 + j0] = __float2half(a3);
    g_C3[p * 128 + j0 + 1] = __float2half(b3_);
#pragma unroll
    for (int j = 0; j < 4; j++) {
        const int k = lane + 32 * j;
        float a = 0.f, g = 0.f;
#pragma unroll
        for (int n = 0; n < 8; n++) {
            a = fmaf(rb[n], f1s[n * 256 + k], a);
            g = fmaf(rb[n], f1s[n * 256 + 128 + k], g);
        }
        st[w * 128 + k] = a / (1.f + expf(-a)) * g;
    }
    __syncwarp();
    float q0 = 0.f, q1 = 0.f;
#pragma unroll 8
    for (int k = 0; k < 128; k++) {
        const float tv = st[w * 128 + k];
        q0 = fmaf(tv, f2s[k * 64 + j0], q0);
        q1 = fmaf(tv, f2s[k * 64 + j0 + 1], q1);
    }
    g_C3[p * 128 + 64 + j0] = __float2half(1.f / (1.f + expf(-q0)));
    g_C3[p * 128 + 64 + j0 + 1] = __float2half(1.f / (1.f + expf(-q1)));
    if (lane == 0) {
        float s = 0.f, q = 0.f;
#pragma unroll
        for (int i = 0; i < 8; i++) { s += rb[i]; q = fmaf(rb[i], rb[i], q); }
        g_tsc[p] = make_float2(s, q);
    }
}

// ---------------- node precomputes (+ pooled zeroing) ----------------
__global__ void __launch_bounds__(256) k_nodes(
    const float* __restrict__ nattr, const float* __restrict__ W1,
    const float* __restrict__ ln1g, const float* __restrict__ ln2g,
    const float* __restrict__ W2)
{
    __shared__ float sa[512];
    __shared__ float gwb[64];
    const int tid = threadIdx.x;
    const int m = tid >> 6, c = tid & 63;
    float wreg[64];
#pragma unroll 16
    for (int k = 0; k < 64; k++) {
        if (m == 0) wreg[k] = ln1g[k] * W1[k * 64 + c];
        else if (m == 1) wreg[k] = ln1g[64 + k] * W1[(64 + k) * 64 + c];
        else if (m == 2) wreg[k] = g_M13[k * 64 + c];
        else wreg[k] = g_M23[k * 64 + c];
    }
    if (tid < 64) gwb[tid] = ln2g[64 + tid] * W2[64 + tid];
    __syncthreads();
    const float4 z4 = make_float4(0.f, 0.f, 0.f, 0.f);
    for (int nb = blockIdx.x; nb < NN / 8; nb += gridDim.x) {
        if (tid < 128) {
            ((float4*)sa)[tid] = ((const float4*)(nattr + (size_t)nb * 512))[tid];
            ((float4*)g_pooled)[(size_t)nb * 128 + tid] = z4;   // zero pooled (pre-scatter)
        }
        __syncthreads();
        float acc[8];
#pragma unroll
        for (int nd = 0; nd < 8; nd++) acc[nd] = 0.f;
#pragma unroll
        for (int k4 = 0; k4 < 16; k4++) {
            const float w0 = wreg[4 * k4], w1 = wreg[4 * k4 + 1];
            const float w2 = wreg[4 * k4 + 2], w3 = wreg[4 * k4 + 3];
#pragma unroll
            for (int nd = 0; nd < 8; nd++) {
                const float4 av = *(const float4*)(sa + nd * 64 + 4 * k4);
                acc[nd] = fmaf(av.x, w0, fmaf(av.y, w1, fmaf(av.z, w2, fmaf(av.w, w3, acc[nd]))));
            }
        }
#pragma unroll
        for (int nd = 0; nd < 8; nd++) {
            const size_t off = (size_t)(nb * 8 + nd) * 64 + c;
            if (m == 0) g_Pch[off] = __float2half(acc[nd]);
            else if (m == 1) g_Pnh[off] = __float2half(acc[nd]);
            else if (m == 2) g_Ych[off] = __float2half(acc[nd]);
            else g_Ynh[off] = __float2half(acc[nd]);
        }
        if (tid < 8) {
            float s = 0.f, q = 0.f, w2s = 0.f;
            for (int k = 0; k < 64; k++) {
                const float a = sa[tid * 64 + k];
                s += a; q = fmaf(a, a, q); w2s = fmaf(a, gwb[k], w2s);
            }
            g_nodeA[nb * 8 + tid] = make_float4(s, q, w2s, 0.f);
        }
        __syncthreads();
    }
}

// ---------------- K1: score + efsc + fp16 ef ----------------
__global__ void __launch_bounds__(256) k_score(const int* __restrict__ eidx,
                                               const float* __restrict__ elen) {
    __shared__ float smax_s[8];
    const int tid = threadIdx.x, w = tid >> 5, lane = tid & 31;
    const int g = lane >> 4, l = lane & 15;
    const float4 s1q = ((const float4*)g_s1)[l];
    const float4 c1q = ((const float4*)g_c1)[l];
    const float4 gwq = ((const float4*)g_gw2a)[l];
    const float S2 = g_S2, C2 = g_C2;
    float runmax = -3.4e38f;
    for (int base = blockIdx.x * 64 + w * 8 + g * 4; base < NE; base += gridDim.x * 64) {
#pragma unroll
        for (int e = 0; e < 4; e++) {
            const int ge = base + e;
            const int ec = eidx[ge], en = eidx[NE + ge];
            const float r = elen[ge];
            const float4 nc = g_nodeA[ec], nn = g_nodeA[en];
            const float4 pc = h4f(*(const uint2*)&g_Pch[(size_t)ec * 64 + 4 * l]);
            const float4 pn = h4f(*(const uint2*)&g_Pnh[(size_t)en * 64 + 4 * l]);
            float u = (r - 0.5f) * ((float)TBL / 5.5f);
            u = fminf(fmaxf(u, 0.f), (float)TBL - 0.001f);
            const int gi = (int)u;
            const float fr = u - (float)gi;
            const float4 tlo = h4f(*(const uint2*)&g_Th[(size_t)gi * 64 + 4 * l]);
            const float4 thi = h4f(*(const uint2*)&g_Th[(size_t)(gi + 1) * 64 + 4 * l]);
            const float2 slo = g_tsc[gi], shi = g_tsc[gi + 1];
            const float m1 = (nc.x + nn.x + LERP(slo.x, shi.x, fr)) * (1.f / 136.f);
            const float ri1 = rsqrtf((nc.y + nn.y + LERP(slo.y, shi.y, fr)) * (1.f / 136.f)
                                     - m1 * m1 + 1e-5f);
            float4 T; LERP4(T, tlo, thi, fr);
            float4 ef;
            ef.x = ri1 * (pc.x + pn.x + T.x - m1 * s1q.x) + c1q.x;
            ef.y = ri1 * (pc.y + pn.y + T.y - m1 * s1q.y) + c1q.y;
            ef.z = ri1 * (pc.z + pn.z + T.z - m1 * s1q.z) + c1q.z;
            ef.w = ri1 * (pc.w + pn.w + T.w - m1 * s1q.w) + c1q.w;
            *(uint2*)&g_efh[(size_t)ge * 64 + 4 * l] = f4h(ef);
            const float S_s = hsum16(ef.x + ef.y + ef.z + ef.w);
            const float S_q = hsum16(fmaf(ef.x, ef.x, fmaf(ef.y, ef.y, fmaf(ef.z, ef.z, ef.w * ef.w))));
            const float S_d = hsum16(fmaf(ef.x, gwq.x, fmaf(ef.y, gwq.y, fmaf(ef.z, gwq.z, ef.w * gwq.w))));
            const float m2 = (S_s + nc.x) * (1.f / 128.f);
            const float ri2 = rsqrtf((S_q + nc.y) * (1.f / 128.f) - m2 * m2 + 1e-5f);
            const float sc = ri2 * (S_d + nc.z - m2 * S2) + C2;
            if (l == 0) { g_score[ge] = sc; g_efsc[ge] = make_float4(S_s, S_q, m1, ri1); }
            runmax = fmaxf(runmax, sc);
        }
    }
#pragma unroll
    for (int o = 16; o; o >>= 1) runmax = fmaxf(runmax, __shfl_xor_sync(0xffffffffu, runmax, o));
    if (lane == 0) smax_s[w] = runmax;
    __syncthreads();
    if (tid == 0) {
        float m = smax_s[0];
        for (int i = 1; i < 8; i++) m = fmaxf(m, smax_s[i]);
        atomicMax(&g_umax, enc_key(m));
    }
}

__global__ void __launch_bounds__(256) k_sumexp() {
    __shared__ float sred[256];
    const float mx = dec_key(g_umax);
    float v = 0.f;
    for (int i = blockIdx.x * 256 + threadIdx.x; i < NE; i += gridDim.x * 256)
        v += expf(g_score[i] - mx);
    sred[threadIdx.x] = v;
    __syncthreads();
    for (int o = 128; o; o >>= 1) {
        if (threadIdx.x < o) sred[threadIdx.x] += sred[threadIdx.x + o];
        __syncthreads();
    }
    if (threadIdx.x == 0) atomicAdd(&g_sumexp, sred[0]);
}

// ---------------- K3: read fp16 ef, red.v4 scatter ----------------
__global__ void __launch_bounds__(256) k_scatter(const int* __restrict__ eidx) {
    const int tid = threadIdx.x, w = tid >> 5, lane = tid & 31;
    const int g = lane >> 4, l = lane & 15;
    const float mx = dec_key(g_umax);
    const float inv = 1.f / g_sumexp;
    for (int base = blockIdx.x * 64 + w * 8 + g * 4; base < NE; base += gridDim.x * 64) {
#pragma unroll
        for (int e = 0; e < 4; e++) {
            const int ge = base + e;
            const int ec = eidx[ge];
            const float wgt = expf(g_score[ge] - mx) * inv;
            const float4 ef = h4f(*(const uint2*)&g_efh[(size_t)ge * 64 + 4 * l]);
            float* dst = &g_pooled[(size_t)ec * 64 + 4 * l];
            asm volatile("red.global.add.v4.f32 [%0], {%1,%2,%3,%4};"
                         :: "l"(dst), "f"(wgt * ef.x), "f"(wgt * ef.y),
                            "f"(wgt * ef.z), "f"(wgt * ef.w) : "memory");
        }
    }
}

// ---------------- pool projections ----------------
#define POOL_SMEM 18432
__global__ void __launch_bounds__(256) k_poolproj(const float* __restrict__ W3,
                                                  const float* __restrict__ ln3g) {
    extern __shared__ float sm[];
    float* sw1 = sm;
    float* sp = sw1 + 4096;
    const int tid = threadIdx.x;
    for (int idx = tid; idx < 4096; idx += 256)
        sw1[idx] = ln3g[64 + (idx >> 6)] * W3[(64 + (idx >> 6)) * 64 + (idx & 63)];
    __syncthreads();
    const int s = tid >> 6, c = tid & 63;
    for (int nb = blockIdx.x; nb < NN / 8; nb += gridDim.x) {
        for (int idx = tid; idx < 512; idx += 256)
            sp[idx] = g_pooled[(size_t)(nb * 8) * 64 + idx];
        __syncthreads();
        float a0 = 0.f, a1 = 0.f;
#pragma unroll 4
        for (int k = 0; k < 64; k++) {
            const float wv = sw1[k * 64 + c];
            a0 = fmaf(sp[s * 64 + k], wv, a0);
            a1 = fmaf(sp[(s + 4) * 64 + k], wv, a1);
        }
        g_PPh[(size_t)(nb * 8 + s) * 64 + c] = __float2half(a0);
        g_PPh[(size_t)(nb * 8 + s + 4) * 64 + c] = __float2half(a1);
        if (tid < 8) {
            float su = 0.f, q = 0.f;
            for (int k = 0; k < 64; k++) {
                const float a = sp[tid * 64 + k];
                su += a; q = fmaf(a, a, q);
            }
            g_nodeB[nb * 8 + tid] = make_float2(su, q);
        }
        __syncthreads();
    }
}

// ---------------- K4: out (fp16 Yc/Yn/PP/T3/gate) ----------------
__global__ void __launch_bounds__(256) k_out(const int* __restrict__ eidx,
                                             const float* __restrict__ elen,
                                             const float* __restrict__ resp,
                                             float* __restrict__ out) {
    const int tid = threadIdx.x, w = tid >> 5, lane = tid & 31;
    const int g = lane >> 4, l = lane & 15;
    const float4 u1q = ((const float4*)g_u1)[l];
    const float4 w1q = ((const float4*)g_w1)[l];
    const float4 s3q = ((const float4*)g_s3)[l];
    const float4 c3q = ((const float4*)g_c3)[l];
    const float p = resp[0];
    const float uc = 1.f / (1.f + expf(-p));
    const float cc = rsqrtf(uc * uc + 1.f);
    const float ssc = uc * cc * (1.f + cc + cc * cc);   // 3 recycles collapsed
    for (int base = blockIdx.x * 64 + w * 8 + g * 4; base < NE; base += gridDim.x * 64) {
#pragma unroll
        for (int e = 0; e < 4; e++) {
            const int ge = base + e;
            const int ec = eidx[ge], en = eidx[NE + ge];
            const float r = elen[ge];
            const float4 es = g_efsc[ge];
            const float2 nb = g_nodeB[ec];
            const float4 yc = h4f(*(const uint2*)&g_Ych[(size_t)ec * 64 + 4 * l]);
            const float4 yn = h4f(*(const uint2*)&g_Ynh[(size_t)en * 64 + 4 * l]);
            const float4 pp = h4f(*(const uint2*)&g_PPh[(size_t)ec * 64 + 4 * l]);
            float u = (r - 0.5f) * ((float)TBL / 5.5f);
            u = fminf(fmaxf(u, 0.f), (float)TBL - 0.001f);
            const int gi = (int)u;
            const float fr = u - (float)gi;
            const float4 t3l = h4f(*(const uint2*)&g_C3[gi * 128 + 4 * l]);
            const float4 t3h = h4f(*(const uint2*)&g_C3[(gi + 1) * 128 + 4 * l]);
            const float4 glo = h4f(*(const uint2*)&g_C3[gi * 128 + 64 + 4 * l]);
            const float4 ghi = h4f(*(const uint2*)&g_C3[(gi + 1) * 128 + 64 + 4 * l]);
            float4 T3, G;
            LERP4(T3, t3l, t3h, fr);
            LERP4(G, glo, ghi, fr);
            const float m1 = es.z, ri1 = es.w;
            const float m3 = (es.x + nb.x) * (1.f / 128.f);
            const float ri3 = rsqrtf((es.y + nb.y) * (1.f / 128.f) - m3 * m3 + 1e-5f);
            float4 o;
            o.x = (ri3 * (ri1 * (yc.x + yn.x + T3.x - m1 * u1q.x) + w1q.x + pp.x - m3 * s3q.x) + c3q.x) * G.x * ssc;
            o.y = (ri3 * (ri1 * (yc.y + yn.y + T3.y - m1 * u1q.y) + w1q.y + pp.y - m3 * s3q.y) + c3q.y) * G.y * ssc;
            o.z = (ri3 * (ri1 * (yc.z + yn.z + T3.z - m1 * u1q.z) + w1q.z + pp.z - m3 * s3q.z) + c3q.z) * G.z * ssc;
            o.w = (ri3 * (ri1 * (yc.w + yn.w + T3.w - m1 * u1q.w) + w1q.w + pp.w - m3 * s3q.w) + c3q.w) * G.w * ssc;
            ((float4*)out)[(size_t)ge * 16 + l] = o;
        }
    }
}

extern "C" void kernel_launch(void* const* d_in, const int* in_sizes, int n_in,
                              void* d_out, int out_size) {
    const int*   eidx  = (const int*)d_in[0];
    const float* elen  = (const float*)d_in[1];
    const float* nattr = (const float*)d_in[2];
    const float* ln1g  = (const float*)d_in[3];
    const float* ln1b  = (const float*)d_in[4];
    const float* W1    = (const float*)d_in[5];
    const float* b1    = (const float*)d_in[6];
    const float* ln2g  = (const float*)d_in[7];
    const float* ln2b  = (const float*)d_in[8];
    const float* W2    = (const float*)d_in[9];
    const float* b2    = (const float*)d_in[10];
    const float* ln3g  = (const float*)d_in[11];
    const float* ln3b  = (const float*)d_in[12];
    const float* W3    = (const float*)d_in[13];
    const float* b3    = (const float*)d_in[14];
    const float* fW1   = (const float*)d_in[15];
    const float* fW2   = (const float*)d_in[16];
    const float* resp  = (const float*)d_in[17];
    float* out = (float*)d_out;

    static int once = 0;
    if (!once) {
        cudaFuncSetAttribute(k_mats, cudaFuncAttributeMaxDynamicSharedMemorySize, MATS_SMEM);
        cudaFuncSetAttribute(k_table, cudaFuncAttributeMaxDynamicSharedMemorySize, TBLK_SMEM);
        once = 1;
    }
    k_init<<<1, 32>>>();
    k_mats<<<9, 256, MATS_SMEM>>>(W1, b1, ln1g, ln1b, ln2g, ln2b, W2, b2, ln3g, ln3b, W3, b3);
    k_table<<<(TBL + 8) / 8, 256, TBLK_SMEM>>>(W1, ln1g, W3, ln3g, fW1, fW2);
    k_nodes<<<592, 256>>>(nattr, W1, ln1g, ln2g, W2);
    k_score<<<1184, 256>>>(eidx, elen);
    k_sumexp<<<592, 256>>>();
    k_scatter<<<1184, 256>>>(eidx);
    k_poolproj<<<1184, 256, POOL_SMEM>>>(W3, ln3g);
    k_out<<<1184, 256>>>(eidx, elen, resp, out);
}

// round 14
// speedup vs baseline: 4.5003x; 1.2076x over previous
#include <cuda_runtime.h>
#include <cuda_fp16.h>
#include <math.h>
#include <stdint.h>

#define NE 640000
#define NN 20000
#define TBL 8192

__device__ float g_M13[4096], g_M23[4096], g_WN0[4096], g_WN1[4096];
__device__ __align__(16) float g_s1[64], g_c1[64], g_u1[64], g_w1[64], g_s3[64], g_c3[64], g_gw2a[64];
__device__ float g_S2, g_C2;
__device__ __align__(16) __half g_Pch[NN * 64], g_Pnh[NN * 64];
__device__ __align__(16) __half g_Ych[NN * 64], g_Ynh[NN * 64], g_PPh[NN * 64];
__device__ __align__(16) float4 g_nodeA[NN];   // sumA, sumsqA, w2a, 0
__device__ __align__(16) float2 g_nodeB[NN];   // sumPool, sumsqPool (normalized)
__device__ __align__(16) __half g_Th[(TBL + 1) * 64];
__device__ __align__(16) __half g_C3[(TBL + 1) * 128];  // [0:64)=T3, [64:128)=gate
__device__ __align__(16) float2 g_tsc[TBL + 1];
__device__ __align__(16) float4 g_efsc[NE];    // S_s, S_q, m1, ri1
__device__ __align__(16) float g_pooled[NN * 64];
__device__ float g_sumexp;

__device__ __forceinline__ float hsum16(float v) {
#pragma unroll
    for (int o = 8; o; o >>= 1) v += __shfl_xor_sync(0xffffffffu, v, o);
    return v;
}
__device__ __forceinline__ void bessel8(float r, float* rb) {
    float t = r * (1.0f / 6.0f), t2 = t * t, t6 = t2 * t2 * t2;
    float ct = tanhf(1.0f - t6);
    const float pre = 0.57735026918962576f / r * (ct * ct * ct);
    const float th = r * 0.5235987755982988f;
    const float tc = 2.f * cosf(th);
    float sm1 = 0.f, sc = sinf(th);
#pragma unroll
    for (int n = 0; n < 8; n++) {
        rb[n] = pre * sc;
        const float nx = tc * sc - sm1;
        sm1 = sc; sc = nx;
    }
}
__device__ __forceinline__ float4 h4f(uint2 u) {
    float2 a = __half22float2(*(__half2*)&u.x), b = __half22float2(*(__half2*)&u.y);
    return make_float4(a.x, a.y, b.x, b.y);
}
#define LDGNC(d, p) asm volatile("ld.global.nc.f32 %0, [%1];" : "=f"(d) : "l"(p))
#define LERP(lo, hi, f) fmaf(f, (hi) - (lo), lo)
#define LERP4(d, lo, hi, f) do { d.x = LERP(lo.x, hi.x, f); d.y = LERP(lo.y, hi.y, f); \
    d.z = LERP(lo.z, hi.z, f); d.w = LERP(lo.w, hi.w, f); } while (0)

// ---------------- matrix precomputes (+ sumexp reset) ----------------
#define MATS_SMEM 86592
__global__ void __launch_bounds__(256) k_mats(
    const float* __restrict__ W1, const float* __restrict__ b1,
    const float* __restrict__ ln1g, const float* __restrict__ ln1b,
    const float* __restrict__ ln2g, const float* __restrict__ ln2b,
    const float* __restrict__ W2, const float* __restrict__ b2,
    const float* __restrict__ ln3g, const float* __restrict__ ln3b,
    const float* __restrict__ W3, const float* __restrict__ b3)
{
    extern __shared__ float sm[];
    float* W1s = sm;
    float* W3s = W1s + 8704;
    float* G3a = W3s + 8192;
    float* ss1 = G3a + 4096;
    float* sc1 = ss1 + 64;
    float* g1s = sc1 + 64;
    float* b1s = g1s + 136;
    float* g3s = b1s + 136;
    float* b3s = g3s + 128;
    const int tid = threadIdx.x;
    for (int i = tid; i < 8704; i += 256) W1s[i] = W1[i];
    for (int i = tid; i < 8192; i += 256) W3s[i] = W3[i];
    for (int i = tid; i < 136; i += 256) { g1s[i] = ln1g[i]; b1s[i] = ln1b[i]; }
    for (int i = tid; i < 128; i += 256) { g3s[i] = ln3g[i]; b3s[i] = ln3b[i]; }
    __syncthreads();
    for (int i = tid; i < 4096; i += 256) G3a[i] = g3s[i >> 6] * W3s[i];
    // scaled W1 halves for k_nodes (all blocks contribute)
    for (int i = blockIdx.x * 256 + tid; i < 4096; i += 9 * 256) {
        g_WN0[i] = g1s[i >> 6] * W1s[i];
        g_WN1[i] = g1s[64 + (i >> 6)] * W1s[4096 + i];
    }
    if (blockIdx.x == 0) {
        if (tid < 64) {
            float s = 0.f, c = 0.f;
            for (int k = 0; k < 136; k++) {
                s = fmaf(g1s[k], W1s[k * 64 + tid], s);
                c = fmaf(b1s[k], W1s[k * 64 + tid], c);
            }
            ss1[tid] = s; sc1[tid] = c + b1[tid];
            g_s1[tid] = s; g_c1[tid] = sc1[tid];
        } else if (tid < 128) {
            const int j = tid - 64;
            float s = 0.f, c = 0.f;
            for (int k = 0; k < 128; k++) {
                s = fmaf(g3s[k], W3s[k * 64 + j], s);
                c = fmaf(b3s[k], W3s[k * 64 + j], c);
            }
            g_s3[j] = s; g_c3[j] = c + b3[j];
        } else if (tid < 192) {
            const int j = tid - 128;
            g_gw2a[j] = ln2g[j] * W2[j];
        } else if (tid == 192) {
            float s = 0.f, c = 0.f;
            for (int k = 0; k < 128; k++) { s = fmaf(ln2g[k], W2[k], s); c = fmaf(ln2b[k], W2[k], c); }
            g_S2 = s; g_C2 = c + b2[0];
        } else if (tid == 193) {
            g_sumexp = 0.f;
        }
        __syncthreads();
        if (tid < 64) {
            float a = 0.f, b_ = 0.f;
            for (int k = 0; k < 64; k++) {
                a = fmaf(ss1[k], G3a[k * 64 + tid], a);
                b_ = fmaf(sc1[k], G3a[k * 64 + tid], b_);
            }
            g_u1[tid] = a; g_w1[tid] = b_;
        }
    } else {
        const int idx = (blockIdx.x - 1) * 512 + tid;
#pragma unroll
        for (int h = 0; h < 2; h++) {
            const int ix = idx + h * 256, i = ix >> 6, j = ix & 63;
            float a = 0.f, b_ = 0.f;
            for (int k = 0; k < 64; k++) {
                a = fmaf(W1s[i * 64 + k], G3a[k * 64 + j], a);
                b_ = fmaf(W1s[(64 + i) * 64 + k], G3a[k * 64 + j], b_);
            }
            g_M13[ix] = g1s[i] * a;
            g_M23[ix] = g1s[64 + i] * b_;
        }
    }
}

// ---------------- r-tables ----------------
#define TBLK_SMEM 65536
__global__ void __launch_bounds__(256) k_table(
    const float* __restrict__ W1, const float* __restrict__ ln1g,
    const float* __restrict__ W3, const float* __restrict__ ln3g,
    const float* __restrict__ fW1, const float* __restrict__ fW2)
{
    extern __shared__ float sm[];
    float* G3a = sm;
    float* G1b = G3a + 4096;
    float* f1s = G1b + 512;
    float* f2s = f1s + 2048;
    float* sT  = f2s + 8192;
    float* st  = sT + 512;
    const int tid = threadIdx.x, w = tid >> 5, lane = tid & 31;
    for (int i = tid; i < 4096; i += 256) G3a[i] = ln3g[i >> 6] * W3[i];
    for (int i = tid; i < 512; i += 256)
        G1b[i] = ln1g[128 + (i >> 6)] * W1[(128 + (i >> 6)) * 64 + (i & 63)];
    for (int i = tid; i < 2048; i += 256) f1s[i] = fW1[i];
    for (int i = tid; i < 8192; i += 256) f2s[i] = fW2[i];
    __syncthreads();
    const int p = blockIdx.x * 8 + w;
    if (p > TBL) return;
    const float r = 0.5f + (5.5f / (float)TBL) * (float)p;
    float rb[8];
    bessel8(r, rb);
    const int j0 = 2 * lane;
    float T0 = 0.f, T1 = 0.f;
#pragma unroll
    for (int i = 0; i < 8; i++) {
        T0 = fmaf(rb[i], G1b[i * 64 + j0], T0);
        T1 = fmaf(rb[i], G1b[i * 64 + j0 + 1], T1);
    }
    sT[w * 64 + j0] = T0; sT[w * 64 + j0 + 1] = T1;
    g_Th[p * 64 + j0] = __float2half(T0);
    g_Th[p * 64 + j0 + 1] = __float2half(T1);
    __syncwarp();
    float a3 = 0.f, b3_ = 0.f;
#pragma unroll 8
    for (int k = 0; k < 64; k++) {
        const float tv = sT[w * 64 + k];
        a3 = fmaf(tv, G3a[k * 64 + j0], a3);
        b3_ = fmaf(tv, G3a[k * 64 + j0 + 1], b3_);
    }
    g_C3[p * 128 + j0] = __float2half(a3);
    g_C3[p * 128 + j0 + 1] = __float2half(b3_);
#pragma unroll
    for (int j = 0; j < 4; j++) {
        const int k = lane + 32 * j;
        float a = 0.f, g = 0.f;
#pragma unroll
        for (int n = 0; n < 8; n++) {
            a = fmaf(rb[n], f1s[n * 256 + k], a);
            g = fmaf(rb[n], f1s[n * 256 + 128 + k], g);
        }
        st[w * 128 + k] = a / (1.f + expf(-a)) * g;
    }
    __syncwarp();
    float q0 = 0.f, q1 = 0.f;
#pragma unroll 8
    for (int k = 0; k < 128; k++) {
        const float tv = st[w * 128 + k];
        q0 = fmaf(tv, f2s[k * 64 + j0], q0);
        q1 = fmaf(tv, f2s[k * 64 + j0 + 1], q1);
    }
    g_C3[p * 128 + 64 + j0] = __float2half(1.f / (1.f + expf(-q0)));
    g_C3[p * 128 + 64 + j0 + 1] = __float2half(1.f / (1.f + expf(-q1)));
    if (lane == 0) {
        float s = 0.f, q = 0.f;
#pragma unroll
        for (int i = 0; i < 8; i++) { s += rb[i]; q = fmaf(rb[i], rb[i], q); }
        g_tsc[p] = make_float2(s, q);
    }
}

// ---------------- node precomputes (+ pooled zeroing); weights via L1-resident LDG ----------------
__global__ void __launch_bounds__(256) k_nodes(
    const float* __restrict__ nattr, const float* __restrict__ ln2g,
    const float* __restrict__ W2)
{
    __shared__ float sa[512];
    __shared__ float gwb[64];
    const int tid = threadIdx.x;
    const int m = tid >> 6, c = tid & 63;
    const float* wp = (m == 0) ? g_WN0 : (m == 1) ? g_WN1 : (m == 2) ? g_M13 : g_M23;
    wp += c;
    if (tid < 64) gwb[tid] = ln2g[64 + tid] * W2[64 + tid];
    __syncthreads();
    const float4 z4 = make_float4(0.f, 0.f, 0.f, 0.f);
    for (int nb = blockIdx.x; nb < NN / 8; nb += gridDim.x) {
        if (tid < 128) {
            ((float4*)sa)[tid] = ((const float4*)(nattr + (size_t)nb * 512))[tid];
            ((float4*)g_pooled)[(size_t)nb * 128 + tid] = z4;
        }
        __syncthreads();
        float acc[8];
#pragma unroll
        for (int nd = 0; nd < 8; nd++) acc[nd] = 0.f;
#pragma unroll
        for (int k4 = 0; k4 < 16; k4++) {
            float w0, w1, w2v, w3;
            LDGNC(w0, wp + (4 * k4) * 64);
            LDGNC(w1, wp + (4 * k4 + 1) * 64);
            LDGNC(w2v, wp + (4 * k4 + 2) * 64);
            LDGNC(w3, wp + (4 * k4 + 3) * 64);
#pragma unroll
            for (int nd = 0; nd < 8; nd++) {
                const float4 av = *(const float4*)(sa + nd * 64 + 4 * k4);
                acc[nd] = fmaf(av.x, w0, fmaf(av.y, w1, fmaf(av.z, w2v, fmaf(av.w, w3, acc[nd]))));
            }
        }
#pragma unroll
        for (int nd = 0; nd < 8; nd++) {
            const size_t off = (size_t)(nb * 8 + nd) * 64 + c;
            if (m == 0) g_Pch[off] = __float2half(acc[nd]);
            else if (m == 1) g_Pnh[off] = __float2half(acc[nd]);
            else if (m == 2) g_Ych[off] = __float2half(acc[nd]);
            else g_Ynh[off] = __float2half(acc[nd]);
        }
        if (tid < 8) {
            float s = 0.f, q = 0.f, w2s = 0.f;
            for (int k = 0; k < 64; k++) {
                const float a = sa[tid * 64 + k];
                s += a; q = fmaf(a, a, q); w2s = fmaf(a, gwb[k], w2s);
            }
            g_nodeA[nb * 8 + tid] = make_float4(s, q, w2s, 0.f);
        }
        __syncthreads();
    }
}

// ---------------- K1: ef + score + FUSED unnormalized scatter + sumexp ----------------
__global__ void __launch_bounds__(256) k_score(const int* __restrict__ eidx,
                                               const float* __restrict__ elen) {
    __shared__ float ssum[8];
    const int tid = threadIdx.x, w = tid >> 5, lane = tid & 31;
    const int g = lane >> 4, l = lane & 15;
    const float4 s1q = ((const float4*)g_s1)[l];
    const float4 c1q = ((const float4*)g_c1)[l];
    const float4 gwq = ((const float4*)g_gw2a)[l];
    const float S2 = g_S2, C2 = g_C2;
    float lsum = 0.f;
    for (int base = blockIdx.x * 64 + w * 8 + g * 4; base < NE; base += gridDim.x * 64) {
#pragma unroll
        for (int e = 0; e < 4; e++) {
            const int ge = base + e;
            const int ec = eidx[ge], en = eidx[NE + ge];
            const float r = elen[ge];
            const float4 nc = g_nodeA[ec], nn = g_nodeA[en];
            const float4 pc = h4f(*(const uint2*)&g_Pch[(size_t)ec * 64 + 4 * l]);
            const float4 pn = h4f(*(const uint2*)&g_Pnh[(size_t)en * 64 + 4 * l]);
            float u = (r - 0.5f) * ((float)TBL / 5.5f);
            u = fminf(fmaxf(u, 0.f), (float)TBL - 0.001f);
            const int gi = (int)u;
            const float fr = u - (float)gi;
            const float4 tlo = h4f(*(const uint2*)&g_Th[(size_t)gi * 64 + 4 * l]);
            const float4 thi = h4f(*(const uint2*)&g_Th[(size_t)(gi + 1) * 64 + 4 * l]);
            const float2 slo = g_tsc[gi], shi = g_tsc[gi + 1];
            const float m1 = (nc.x + nn.x + LERP(slo.x, shi.x, fr)) * (1.f / 136.f);
            const float ri1 = rsqrtf((nc.y + nn.y + LERP(slo.y, shi.y, fr)) * (1.f / 136.f)
                                     - m1 * m1 + 1e-5f);
            float4 T; LERP4(T, tlo, thi, fr);
            float4 ef;
            ef.x = ri1 * (pc.x + pn.x + T.x - m1 * s1q.x) + c1q.x;
            ef.y = ri1 * (pc.y + pn.y + T.y - m1 * s1q.y) + c1q.y;
            ef.z = ri1 * (pc.z + pn.z + T.z - m1 * s1q.z) + c1q.z;
            ef.w = ri1 * (pc.w + pn.w + T.w - m1 * s1q.w) + c1q.w;
            const float S_s = hsum16(ef.x + ef.y + ef.z + ef.w);
            const float S_q = hsum16(fmaf(ef.x, ef.x, fmaf(ef.y, ef.y, fmaf(ef.z, ef.z, ef.w * ef.w))));
            const float S_d = hsum16(fmaf(ef.x, gwq.x, fmaf(ef.y, gwq.y, fmaf(ef.z, gwq.z, ef.w * gwq.w))));
            const float m2 = (S_s + nc.x) * (1.f / 128.f);
            const float ri2 = rsqrtf((S_q + nc.y) * (1.f / 128.f) - m2 * m2 + 1e-5f);
            const float sc = ri2 * (S_d + nc.z - m2 * S2) + C2;
            const float wexp = expf(sc);          // unnormalized softmax weight
            if (l == 0) {
                g_efsc[ge] = make_float4(S_s, S_q, m1, ri1);
                lsum += wexp;
            }
            float* dst = &g_pooled[(size_t)ec * 64 + 4 * l];
            asm volatile("red.global.add.v4.f32 [%0], {%1,%2,%3,%4};"
                         :: "l"(dst), "f"(wexp * ef.x), "f"(wexp * ef.y),
                            "f"(wexp * ef.z), "f"(wexp * ef.w) : "memory");
        }
    }
#pragma unroll
    for (int o = 16; o; o >>= 1) lsum += __shfl_xor_sync(0xffffffffu, lsum, o);
    if (lane == 0) ssum[w] = lsum;
    __syncthreads();
    if (tid == 0) {
        float s = ssum[0];
        for (int i = 1; i < 8; i++) s += ssum[i];
        atomicAdd(&g_sumexp, s);
    }
}

// ---------------- pool projections (normalize by sumexp here) ----------------
#define POOL_SMEM 18432
__global__ void __launch_bounds__(256) k_poolproj(const float* __restrict__ W3,
                                                  const float* __restrict__ ln3g) {
    extern __shared__ float sm[];
    float* sw1 = sm;
    float* sp = sw1 + 4096;
    const int tid = threadIdx.x;
    const float inv = 1.f / g_sumexp;
    for (int idx = tid; idx < 4096; idx += 256)
        sw1[idx] = ln3g[64 + (idx >> 6)] * W3[(64 + (idx >> 6)) * 64 + (idx & 63)];
    __syncthreads();
    const int s = tid >> 6, c = tid & 63;
    for (int nb = blockIdx.x; nb < NN / 8; nb += gridDim.x) {
        for (int idx = tid; idx < 512; idx += 256)
            sp[idx] = g_pooled[(size_t)(nb * 8) * 64 + idx] * inv;
        __syncthreads();
        float a0 = 0.f, a1 = 0.f;
#pragma unroll 4
        for (int k = 0; k < 64; k++) {
            const float wv = sw1[k * 64 + c];
            a0 = fmaf(sp[s * 64 + k], wv, a0);
            a1 = fmaf(sp[(s + 4) * 64 + k], wv, a1);
        }
        g_PPh[(size_t)(nb * 8 + s) * 64 + c] = __float2half(a0);
        g_PPh[(size_t)(nb * 8 + s + 4) * 64 + c] = __float2half(a1);
        if (tid < 8) {
            float su = 0.f, q = 0.f;
            for (int k = 0; k < 64; k++) {
                const float a = sp[tid * 64 + k];
                su += a; q = fmaf(a, a, q);
            }
            g_nodeB[nb * 8 + tid] = make_float2(su, q);
        }
        __syncthreads();
    }
}

// ---------------- K4: out (fp16 Yc/Yn/PP/T3/gate) ----------------
__global__ void __launch_bounds__(256) k_out(const int* __restrict__ eidx,
                                             const float* __restrict__ elen,
                                             const float* __restrict__ resp,
                                             float* __restrict__ out) {
    const int tid = threadIdx.x, w = tid >> 5, lane = tid & 31;
    const int g = lane >> 4, l = lane & 15;
    const float4 u1q = ((const float4*)g_u1)[l];
    const float4 w1q = ((const float4*)g_w1)[l];
    const float4 s3q = ((const float4*)g_s3)[l];
    const float4 c3q = ((const float4*)g_c3)[l];
    const float p = resp[0];
    const float uc = 1.f / (1.f + expf(-p));
    const float cc = rsqrtf(uc * uc + 1.f);
    const float ssc = uc * cc * (1.f + cc + cc * cc);   // 3 recycles collapsed
    for (int base = blockIdx.x * 64 + w * 8 + g * 4; base < NE; base += gridDim.x * 64) {
#pragma unroll
        for (int e = 0; e < 4; e++) {
            const int ge = base + e;
            const int ec = eidx[ge], en = eidx[NE + ge];
            const float r = elen[ge];
            const float4 es = g_efsc[ge];
            const float2 nb = g_nodeB[ec];
            const float4 yc = h4f(*(const uint2*)&g_Ych[(size_t)ec * 64 + 4 * l]);
            const float4 yn = h4f(*(const uint2*)&g_Ynh[(size_t)en * 64 + 4 * l]);
            const float4 pp = h4f(*(const uint2*)&g_PPh[(size_t)ec * 64 + 4 * l]);
            float u = (r - 0.5f) * ((float)TBL / 5.5f);
            u = fminf(fmaxf(u, 0.f), (float)TBL - 0.001f);
            const int gi = (int)u;
            const float fr = u - (float)gi;
            const float4 t3l = h4f(*(const uint2*)&g_C3[gi * 128 + 4 * l]);
            const float4 t3h = h4f(*(const uint2*)&g_C3[(gi + 1) * 128 + 4 * l]);
            const float4 glo = h4f(*(const uint2*)&g_C3[gi * 128 + 64 + 4 * l]);
            const float4 ghi = h4f(*(const uint2*)&g_C3[(gi + 1) * 128 + 64 + 4 * l]);
            float4 T3, G;
            LERP4(T3, t3l, t3h, fr);
            LERP4(G, glo, ghi, fr);
            const float m1 = es.z, ri1 = es.w;
            const float m3 = (es.x + nb.x) * (1.f / 128.f);
            const float ri3 = rsqrtf((es.y + nb.y) * (1.f / 128.f) - m3 * m3 + 1e-5f);
            float4 o;
            o.x = (ri3 * (ri1 * (yc.x + yn.x + T3.x - m1 * u1q.x) + w1q.x + pp.x - m3 * s3q.x) + c3q.x) * G.x * ssc;
            o.y = (ri3 * (ri1 * (yc.y + yn.y + T3.y - m1 * u1q.y) + w1q.y + pp.y - m3 * s3q.y) + c3q.y) * G.y * ssc;
            o.z = (ri3 * (ri1 * (yc.z + yn.z + T3.z - m1 * u1q.z) + w1q.z + pp.z - m3 * s3q.z) + c3q.z) * G.z * ssc;
            o.w = (ri3 * (ri1 * (yc.w + yn.w + T3.w - m1 * u1q.w) + w1q.w + pp.w - m3 * s3q.w) + c3q.w) * G.w * ssc;
            ((float4*)out)[(size_t)ge * 16 + l] = o;
        }
    }
}

extern "C" void kernel_launch(void* const* d_in, const int* in_sizes, int n_in,
                              void* d_out, int out_size) {
    const int*   eidx  = (const int*)d_in[0];
    const float* elen  = (const float*)d_in[1];
    const float* nattr = (const float*)d_in[2];
    const float* ln1g  = (const float*)d_in[3];
    const float* ln1b  = (const float*)d_in[4];
    const float* W1    = (const float*)d_in[5];
    const float* b1    = (const float*)d_in[6];
    const float* ln2g  = (const float*)d_in[7];
    const float* ln2b  = (const float*)d_in[8];
    const float* W2    = (const float*)d_in[9];
    const float* b2    = (const float*)d_in[10];
    const float* ln3g  = (const float*)d_in[11];
    const float* ln3b  = (const float*)d_in[12];
    const float* W3    = (const float*)d_in[13];
    const float* b3    = (const float*)d_in[14];
    const float* fW1   = (const float*)d_in[15];
    const float* fW2   = (const float*)d_in[16];
    const float* resp  = (const float*)d_in[17];
    float* out = (float*)d_out;

    static int once = 0;
    if (!once) {
        cudaFuncSetAttribute(k_mats, cudaFuncAttributeMaxDynamicSharedMemorySize, MATS_SMEM);
        cudaFuncSetAttribute(k_table, cudaFuncAttributeMaxDynamicSharedMemorySize, TBLK_SMEM);
        once = 1;
    }
    k_mats<<<9, 256, MATS_SMEM>>>(W1, b1, ln1g, ln1b, ln2g, ln2b, W2, b2, ln3g, ln3b, W3, b3);
    k_table<<<(TBL + 8) / 8, 256, TBLK_SMEM>>>(W1, ln1g, W3, ln3g, fW1, fW2);
    k_nodes<<<1184, 256>>>(nattr, ln2g, W2);
    k_score<<<1184, 256>>>(eidx, elen);
    k_poolproj<<<1184, 256, POOL_SMEM>>>(W3, ln3g);
    k_out<<<1184, 256>>>(eidx, elen, resp, out);
}

// round 15
// speedup vs baseline: 4.6865x; 1.0414x over previous
#include <cuda_runtime.h>
#include <cuda_fp16.h>
#include <math.h>
#include <stdint.h>

#define NE 640000
#define NN 20000
#define TBL 8192

__device__ float g_M13[4096], g_M23[4096], g_WN0[4096], g_WN1[4096];
__device__ __align__(16) float g_s1[64], g_c1[64], g_u1[64], g_w1[64], g_s3[64], g_c3[64], g_gw2a[64];
__device__ __align__(16) float g_wsv[256];       // ws0|wg0|ws1|wg1
__device__ __align__(16) float4 g_sc4;           // A1,B1,A2,B2
__device__ float g_S2, g_C2;
__device__ __align__(16) __half g_Pch[NN * 64], g_Pnh[NN * 64];
__device__ __align__(16) __half g_Ych[NN * 64], g_Ynh[NN * 64], g_PPh[NN * 64];
__device__ __align__(16) float4 g_nodeAB[NN * 2]; // [2n]=(sumA,sumsqA,w2a,pcs) [2n+1]=(pcgw,pns,pngw,0)
__device__ __align__(16) float2 g_nodeB[NN];      // sumPool, sumsqPool (normalized)
__device__ __align__(16) __half g_Th[(TBL + 1) * 64];
__device__ __align__(16) __half g_C3[(TBL + 1) * 128];  // [0:64)=T3, [64:128)=gate
__device__ __align__(16) float4 g_tsc4[TBL + 1];  // rbsum, rbsq, Tsum, Tgw
__device__ __align__(16) float4 g_efsc[NE];       // S_s, S_q, m1, ri1
__device__ __align__(16) float g_pooled[NN * 64];
__device__ float g_sumexp;

__device__ __forceinline__ float hsum16(float v) {
#pragma unroll
    for (int o = 8; o; o >>= 1) v += __shfl_xor_sync(0xffffffffu, v, o);
    return v;
}
__device__ __forceinline__ void bessel8(float r, float* rb) {
    float t = r * (1.0f / 6.0f), t2 = t * t, t6 = t2 * t2 * t2;
    float ct = tanhf(1.0f - t6);
    const float pre = 0.57735026918962576f / r * (ct * ct * ct);
    const float th = r * 0.5235987755982988f;
    const float tc = 2.f * cosf(th);
    float sm1 = 0.f, sc = sinf(th);
#pragma unroll
    for (int n = 0; n < 8; n++) {
        rb[n] = pre * sc;
        const float nx = tc * sc - sm1;
        sm1 = sc; sc = nx;
    }
}
__device__ __forceinline__ float4 h4f(uint2 u) {
    float2 a = __half22float2(*(__half2*)&u.x), b = __half22float2(*(__half2*)&u.y);
    return make_float4(a.x, a.y, b.x, b.y);
}
#define LDGNC(d, p) asm volatile("ld.global.nc.f32 %0, [%1];" : "=f"(d) : "l"(p))
#define LERP(lo, hi, f) fmaf(f, (hi) - (lo), lo)
#define LERP4(d, lo, hi, f) do { d.x = LERP(lo.x, hi.x, f); d.y = LERP(lo.y, hi.y, f); \
    d.z = LERP(lo.z, hi.z, f); d.w = LERP(lo.w, hi.w, f); } while (0)

// ---------------- matrix precomputes ----------------
#define MATS_SMEM 86592
__global__ void __launch_bounds__(256) k_mats(
    const float* __restrict__ W1, const float* __restrict__ b1,
    const float* __restrict__ ln1g, const float* __restrict__ ln1b,
    const float* __restrict__ ln2g, const float* __restrict__ ln2b,
    const float* __restrict__ W2, const float* __restrict__ b2,
    const float* __restrict__ ln3g, const float* __restrict__ ln3b,
    const float* __restrict__ W3, const float* __restrict__ b3)
{
    extern __shared__ float sm[];
    float* W1s = sm;
    float* W3s = W1s + 8704;
    float* G3a = W3s + 8192;
    float* ss1 = G3a + 4096;
    float* sc1 = ss1 + 64;
    float* g1s = sc1 + 64;
    float* b1s = g1s + 136;
    float* g3s = b1s + 136;
    float* b3s = g3s + 128;
    const int tid = threadIdx.x;
    for (int i = tid; i < 8704; i += 256) W1s[i] = W1[i];
    for (int i = tid; i < 8192; i += 256) W3s[i] = W3[i];
    for (int i = tid; i < 136; i += 256) { g1s[i] = ln1g[i]; b1s[i] = ln1b[i]; }
    for (int i = tid; i < 128; i += 256) { g3s[i] = ln3g[i]; b3s[i] = ln3b[i]; }
    __syncthreads();
    for (int i = tid; i < 4096; i += 256) G3a[i] = g3s[i >> 6] * W3s[i];
    for (int i = blockIdx.x * 256 + tid; i < 4096; i += 9 * 256) {
        g_WN0[i] = g1s[i >> 6] * W1s[i];
        g_WN1[i] = g1s[64 + (i >> 6)] * W1s[4096 + i];
    }
    if (blockIdx.x == 0) {
        if (tid < 64) {
            float s = 0.f, c = 0.f;
            for (int k = 0; k < 136; k++) {
                s = fmaf(g1s[k], W1s[k * 64 + tid], s);
                c = fmaf(b1s[k], W1s[k * 64 + tid], c);
            }
            ss1[tid] = s; sc1[tid] = c + b1[tid];
            g_s1[tid] = s; g_c1[tid] = sc1[tid];
        } else if (tid < 128) {
            const int j = tid - 64;
            float s = 0.f, c = 0.f;
            for (int k = 0; k < 128; k++) {
                s = fmaf(g3s[k], W3s[k * 64 + j], s);
                c = fmaf(b3s[k], W3s[k * 64 + j], c);
            }
            g_s3[j] = s; g_c3[j] = c + b3[j];
        } else if (tid < 192) {
            const int j = tid - 128;
            g_gw2a[j] = ln2g[j] * W2[j];
        } else if (tid == 192) {
            float s = 0.f, c = 0.f;
            for (int k = 0; k < 128; k++) { s = fmaf(ln2g[k], W2[k], s); c = fmaf(ln2b[k], W2[k], c); }
            g_S2 = s; g_C2 = c + b2[0];
        } else if (tid == 193) {
            g_sumexp = 0.f;
        }
        __syncthreads();
        if (tid < 64) {
            float a = 0.f, b_ = 0.f;
            for (int k = 0; k < 64; k++) {
                a = fmaf(ss1[k], G3a[k * 64 + tid], a);
                b_ = fmaf(sc1[k], G3a[k * 64 + tid], b_);
            }
            g_u1[tid] = a; g_w1[tid] = b_;
        } else if (tid == 64) {
            float A1 = 0.f, B1 = 0.f, A2 = 0.f, B2 = 0.f;
            for (int c = 0; c < 64; c++) {
                const float gw = ln2g[c] * W2[c];
                A1 += ss1[c]; B1 += sc1[c];
                A2 = fmaf(ss1[c], gw, A2); B2 = fmaf(sc1[c], gw, B2);
            }
            g_sc4 = make_float4(A1, B1, A2, B2);
        } else if (tid >= 128) {
            const int idx = tid - 128, k = idx & 63, pair = idx >> 6;
            const int row = pair ? (64 + k) : k;
            const float gk = g1s[row];
            float s = 0.f, gacc = 0.f;
            for (int c = 0; c < 64; c++) {
                const float wv = gk * W1s[row * 64 + c];
                s += wv;
                gacc = fmaf(wv, ln2g[c] * W2[c], gacc);
            }
            g_wsv[pair * 128 + k] = s;
            g_wsv[pair * 128 + 64 + k] = gacc;
        }
    } else {
        const int idx = (blockIdx.x - 1) * 512 + tid;
#pragma unroll
        for (int h = 0; h < 2; h++) {
            const int ix = idx + h * 256, i = ix >> 6, j = ix & 63;
            float a = 0.f, b_ = 0.f;
            for (int k = 0; k < 64; k++) {
                a = fmaf(W1s[i * 64 + k], G3a[k * 64 + j], a);
                b_ = fmaf(W1s[(64 + i) * 64 + k], G3a[k * 64 + j], b_);
            }
            g_M13[ix] = g1s[i] * a;
            g_M23[ix] = g1s[64 + i] * b_;
        }
    }
}

// ---------------- r-tables ----------------
#define TBLK_SMEM 65536
__global__ void __launch_bounds__(256) k_table(
    const float* __restrict__ W1, const float* __restrict__ ln1g,
    const float* __restrict__ W3, const float* __restrict__ ln3g,
    const float* __restrict__ fW1, const float* __restrict__ fW2)
{
    extern __shared__ float sm[];
    float* G3a = sm;
    float* G1b = G3a + 4096;
    float* f1s = G1b + 512;
    float* f2s = f1s + 2048;
    float* sT  = f2s + 8192;
    float* st  = sT + 512;
    const int tid = threadIdx.x, w = tid >> 5, lane = tid & 31;
    for (int i = tid; i < 4096; i += 256) G3a[i] = ln3g[i >> 6] * W3[i];
    for (int i = tid; i < 512; i += 256)
        G1b[i] = ln1g[128 + (i >> 6)] * W1[(128 + (i >> 6)) * 64 + (i & 63)];
    for (int i = tid; i < 2048; i += 256) f1s[i] = fW1[i];
    for (int i = tid; i < 8192; i += 256) f2s[i] = fW2[i];
    __syncthreads();
    const int p = blockIdx.x * 8 + w;
    if (p > TBL) return;
    const float r = 0.5f + (5.5f / (float)TBL) * (float)p;
    float rb[8];
    bessel8(r, rb);
    const int j0 = 2 * lane;
    float T0 = 0.f, T1 = 0.f;
#pragma unroll
    for (int i = 0; i < 8; i++) {
        T0 = fmaf(rb[i], G1b[i * 64 + j0], T0);
        T1 = fmaf(rb[i], G1b[i * 64 + j0 + 1], T1);
    }
    sT[w * 64 + j0] = T0; sT[w * 64 + j0 + 1] = T1;
    g_Th[p * 64 + j0] = __float2half(T0);
    g_Th[p * 64 + j0 + 1] = __float2half(T1);
    // table scalars: Tsum, Tgw
    float ps = T0 + T1;
    float pg = fmaf(T0, g_gw2a[j0], T1 * g_gw2a[j0 + 1]);
#pragma unroll
    for (int o = 16; o; o >>= 1) {
        ps += __shfl_xor_sync(0xffffffffu, ps, o);
        pg += __shfl_xor_sync(0xffffffffu, pg, o);
    }
    __syncwarp();
    float a3 = 0.f, b3_ = 0.f;
#pragma unroll 8
    for (int k = 0; k < 64; k++) {
        const float tv = sT[w * 64 + k];
        a3 = fmaf(tv, G3a[k * 64 + j0], a3);
        b3_ = fmaf(tv, G3a[k * 64 + j0 + 1], b3_);
    }
    g_C3[p * 128 + j0] = __float2half(a3);
    g_C3[p * 128 + j0 + 1] = __float2half(b3_);
#pragma unroll
    for (int j = 0; j < 4; j++) {
        const int k = lane + 32 * j;
        float a = 0.f, g = 0.f;
#pragma unroll
        for (int n = 0; n < 8; n++) {
            a = fmaf(rb[n], f1s[n * 256 + k], a);
            g = fmaf(rb[n], f1s[n * 256 + 128 + k], g);
        }
        st[w * 128 + k] = a / (1.f + expf(-a)) * g;
    }
    __syncwarp();
    float q0 = 0.f, q1 = 0.f;
#pragma unroll 8
    for (int k = 0; k < 128; k++) {
        const float tv = st[w * 128 + k];
        q0 = fmaf(tv, f2s[k * 64 + j0], q0);
        q1 = fmaf(tv, f2s[k * 64 + j0 + 1], q1);
    }
    g_C3[p * 128 + 64 + j0] = __float2half(1.f / (1.f + expf(-q0)));
    g_C3[p * 128 + 64 + j0 + 1] = __float2half(1.f / (1.f + expf(-q1)));
    if (lane == 0) {
        float s = 0.f, q = 0.f;
#pragma unroll
        for (int i = 0; i < 8; i++) { s += rb[i]; q = fmaf(rb[i], rb[i], q); }
        g_tsc4[p] = make_float4(s, q, ps, pg);
    }
}

// ---------------- node precomputes (+ pooled zeroing) ----------------
__global__ void __launch_bounds__(256) k_nodes(
    const float* __restrict__ nattr, const float* __restrict__ ln2g,
    const float* __restrict__ W2)
{
    __shared__ float sa[512];
    __shared__ float gwb[64];
    __shared__ float sws[256];
    const int tid = threadIdx.x;
    const int m = tid >> 6, c = tid & 63;
    const float* wp = (m == 0) ? g_WN0 : (m == 1) ? g_WN1 : (m == 2) ? g_M13 : g_M23;
    wp += c;
    if (tid < 64) gwb[tid] = ln2g[64 + tid] * W2[64 + tid];
    if (tid < 256) sws[tid] = g_wsv[tid];
    __syncthreads();
    const float4 z4 = make_float4(0.f, 0.f, 0.f, 0.f);
    for (int nb = blockIdx.x; nb < NN / 8; nb += gridDim.x) {
        if (tid < 128) {
            ((float4*)sa)[tid] = ((const float4*)(nattr + (size_t)nb * 512))[tid];
            ((float4*)g_pooled)[(size_t)nb * 128 + tid] = z4;
        }
        __syncthreads();
        float acc[8];
#pragma unroll
        for (int nd = 0; nd < 8; nd++) acc[nd] = 0.f;
#pragma unroll
        for (int k4 = 0; k4 < 16; k4++) {
            float w0, w1, w2v, w3;
            LDGNC(w0, wp + (4 * k4) * 64);
            LDGNC(w1, wp + (4 * k4 + 1) * 64);
            LDGNC(w2v, wp + (4 * k4 + 2) * 64);
            LDGNC(w3, wp + (4 * k4 + 3) * 64);
#pragma unroll
            for (int nd = 0; nd < 8; nd++) {
                const float4 av = *(const float4*)(sa + nd * 64 + 4 * k4);
                acc[nd] = fmaf(av.x, w0, fmaf(av.y, w1, fmaf(av.z, w2v, fmaf(av.w, w3, acc[nd]))));
            }
        }
#pragma unroll
        for (int nd = 0; nd < 8; nd++) {
            const size_t off = (size_t)(nb * 8 + nd) * 64 + c;
            if (m == 0) g_Pch[off] = __float2half(acc[nd]);
            else if (m == 1) g_Pnh[off] = __float2half(acc[nd]);
            else if (m == 2) g_Ych[off] = __float2half(acc[nd]);
            else g_Ynh[off] = __float2half(acc[nd]);
        }
        if (tid < 8) {
            float s = 0.f, q = 0.f, w2s = 0.f, ps = 0.f, pg = 0.f, ns = 0.f, ng = 0.f;
            for (int k = 0; k < 64; k++) {
                const float a = sa[tid * 64 + k];
                s += a; q = fmaf(a, a, q); w2s = fmaf(a, gwb[k], w2s);
                ps = fmaf(a, sws[k], ps);       pg = fmaf(a, sws[64 + k], pg);
                ns = fmaf(a, sws[128 + k], ns); ng = fmaf(a, sws[192 + k], ng);
            }
            g_nodeAB[(nb * 8 + tid) * 2]     = make_float4(s, q, w2s, ps);
            g_nodeAB[(nb * 8 + tid) * 2 + 1] = make_float4(pg, ns, ng, 0.f);
        }
        __syncthreads();
    }
}

// ---------------- K1: ef + score + fused scatter; S_s/S_d via scalars ----------------
__global__ void __launch_bounds__(256) k_score(const int* __restrict__ eidx,
                                               const float* __restrict__ elen) {
    __shared__ float ssum[8];
    const int tid = threadIdx.x, w = tid >> 5, lane = tid & 31;
    const int g = lane >> 4, l = lane & 15;
    const float4 s1q = ((const float4*)g_s1)[l];
    const float4 c1q = ((const float4*)g_c1)[l];
    const float4 scal = g_sc4;   // A1,B1,A2,B2
    const float S2 = g_S2, C2 = g_C2;
    float lsum = 0.f;
    for (int base = blockIdx.x * 64 + w * 8 + g * 4; base < NE; base += gridDim.x * 64) {
#pragma unroll
        for (int e = 0; e < 4; e++) {
            const int ge = base + e;
            const int ec = eidx[ge], en = eidx[NE + ge];
            const float r = elen[ge];
            const float4 ncA = g_nodeAB[2 * ec], ncB = g_nodeAB[2 * ec + 1];
            const float4 nnA = g_nodeAB[2 * en], nnB = g_nodeAB[2 * en + 1];
            const float4 pc = h4f(*(const uint2*)&g_Pch[(size_t)ec * 64 + 4 * l]);
            const float4 pn = h4f(*(const uint2*)&g_Pnh[(size_t)en * 64 + 4 * l]);
            float u = (r - 0.5f) * ((float)TBL / 5.5f);
            u = fminf(fmaxf(u, 0.f), (float)TBL - 0.001f);
            const int gi = (int)u;
            const float fr = u - (float)gi;
            const float4 tlo = h4f(*(const uint2*)&g_Th[(size_t)gi * 64 + 4 * l]);
            const float4 thi = h4f(*(const uint2*)&g_Th[(size_t)(gi + 1) * 64 + 4 * l]);
            const float4 slo = g_tsc4[gi], shi = g_tsc4[gi + 1];
            const float m1 = (ncA.x + nnA.x + LERP(slo.x, shi.x, fr)) * (1.f / 136.f);
            const float ri1 = rsqrtf((ncA.y + nnA.y + LERP(slo.y, shi.y, fr)) * (1.f / 136.f)
                                     - m1 * m1 + 1e-5f);
            const float Ts = LERP(slo.z, shi.z, fr), Tg = LERP(slo.w, shi.w, fr);
            float4 T; LERP4(T, tlo, thi, fr);
            float4 ef;
            ef.x = ri1 * (pc.x + pn.x + T.x - m1 * s1q.x) + c1q.x;
            ef.y = ri1 * (pc.y + pn.y + T.y - m1 * s1q.y) + c1q.y;
            ef.z = ri1 * (pc.z + pn.z + T.z - m1 * s1q.z) + c1q.z;
            ef.w = ri1 * (pc.w + pn.w + T.w - m1 * s1q.w) + c1q.w;
            const float S_s = ri1 * (ncA.w + nnB.y + Ts - m1 * scal.x) + scal.y;
            const float S_d = ri1 * (ncB.x + nnB.z + Tg - m1 * scal.z) + scal.w;
            const float S_q = hsum16(fmaf(ef.x, ef.x, fmaf(ef.y, ef.y, fmaf(ef.z, ef.z, ef.w * ef.w))));
            const float m2 = (S_s + ncA.x) * (1.f / 128.f);
            const float ri2 = rsqrtf((S_q + ncA.y) * (1.f / 128.f) - m2 * m2 + 1e-5f);
            const float sc = ri2 * (S_d + ncA.z - m2 * S2) + C2;
            const float wexp = expf(sc);
            if (l == 0) {
                g_efsc[ge] = make_float4(S_s, S_q, m1, ri1);
                lsum += wexp;
            }
            float* dst = &g_pooled[(size_t)ec * 64 + 4 * l];
            asm volatile("red.global.add.v4.f32 [%0], {%1,%2,%3,%4};"
                         :: "l"(dst), "f"(wexp * ef.x), "f"(wexp * ef.y),
                            "f"(wexp * ef.z), "f"(wexp * ef.w) : "memory");
        }
    }
#pragma unroll
    for (int o = 16; o; o >>= 1) lsum += __shfl_xor_sync(0xffffffffu, lsum, o);
    if (lane == 0) ssum[w] = lsum;
    __syncthreads();
    if (tid == 0) {
        float s = ssum[0];
        for (int i = 1; i < 8; i++) s += ssum[i];
        atomicAdd(&g_sumexp, s);
    }
}

// ---------------- pool projections (normalize by sumexp) ----------------
#define POOL_SMEM 18432
__global__ void __launch_bounds__(256) k_poolproj(const float* __restrict__ W3,
                                                  const float* __restrict__ ln3g) {
    extern __shared__ float sm[];
    float* sw1 = sm;
    float* sp = sw1 + 4096;
    const int tid = threadIdx.x;
    const float inv = 1.f / g_sumexp;
    for (int idx = tid; idx < 4096; idx += 256)
        sw1[idx] = ln3g[64 + (idx >> 6)] * W3[(64 + (idx >> 6)) * 64 + (idx & 63)];
    __syncthreads();
    const int s = tid >> 6, c = tid & 63;
    for (int nb = blockIdx.x; nb < NN / 8; nb += gridDim.x) {
        for (int idx = tid; idx < 512; idx += 256)
            sp[idx] = g_pooled[(size_t)(nb * 8) * 64 + idx] * inv;
        __syncthreads();
        float a0 = 0.f, a1 = 0.f;
#pragma unroll 4
        for (int k = 0; k < 64; k++) {
            const float wv = sw1[k * 64 + c];
            a0 = fmaf(sp[s * 64 + k], wv, a0);
            a1 = fmaf(sp[(s + 4) * 64 + k], wv, a1);
        }
        g_PPh[(size_t)(nb * 8 + s) * 64 + c] = __float2half(a0);
        g_PPh[(size_t)(nb * 8 + s + 4) * 64 + c] = __float2half(a1);
        if (tid < 8) {
            float su = 0.f, q = 0.f;
            for (int k = 0; k < 64; k++) {
                const float a = sp[tid * 64 + k];
                su += a; q = fmaf(a, a, q);
            }
            g_nodeB[nb * 8 + tid] = make_float2(su, q);
        }
        __syncthreads();
    }
}

// ---------------- K4: out (nearest-neighbor C3) ----------------
__global__ void __launch_bounds__(256) k_out(const int* __restrict__ eidx,
                                             const float* __restrict__ elen,
                                             const float* __restrict__ resp,
                                             float* __restrict__ out) {
    const int tid = threadIdx.x, w = tid >> 5, lane = tid & 31;
    const int g = lane >> 4, l = lane & 15;
    const float4 u1q = ((const float4*)g_u1)[l];
    const float4 w1q = ((const float4*)g_w1)[l];
    const float4 s3q = ((const float4*)g_s3)[l];
    const float4 c3q = ((const float4*)g_c3)[l];
    const float p = resp[0];
    const float uc = 1.f / (1.f + expf(-p));
    const float cc = rsqrtf(uc * uc + 1.f);
    const float ssc = uc * cc * (1.f + cc + cc * cc);   // 3 recycles collapsed
    for (int base = blockIdx.x * 64 + w * 8 + g * 4; base < NE; base += gridDim.x * 64) {
#pragma unroll
        for (int e = 0; e < 4; e++) {
            const int ge = base + e;
            const int ec = eidx[ge], en = eidx[NE + ge];
            const float r = elen[ge];
            const float4 es = g_efsc[ge];
            const float2 nb = g_nodeB[ec];
            const float4 yc = h4f(*(const uint2*)&g_Ych[(size_t)ec * 64 + 4 * l]);
            const float4 yn = h4f(*(const uint2*)&g_Ynh[(size_t)en * 64 + 4 * l]);
            const float4 pp = h4f(*(const uint2*)&g_PPh[(size_t)ec * 64 + 4 * l]);
            float u = (r - 0.5f) * ((float)TBL / 5.5f);
            u = fminf(fmaxf(u, 0.f), (float)TBL - 0.001f);
            const int gi = (int)(u + 0.5f);        // nearest
            const float4 T3 = h4f(*(const uint2*)&g_C3[gi * 128 + 4 * l]);
            const float4 G  = h4f(*(const uint2*)&g_C3[gi * 128 + 64 + 4 * l]);
            const float m1 = es.z, ri1 = es.w;
            const float m3 = (es.x + nb.x) * (1.f / 128.f);
            const float ri3 = rsqrtf((es.y + nb.y) * (1.f / 128.f) - m3 * m3 + 1e-5f);
            float4 o;
            o.x = (ri3 * (ri1 * (yc.x + yn.x + T3.x - m1 * u1q.x) + w1q.x + pp.x - m3 * s3q.x) + c3q.x) * G.x * ssc;
            o.y = (ri3 * (ri1 * (yc.y + yn.y + T3.y - m1 * u1q.y) + w1q.y + pp.y - m3 * s3q.y) + c3q.y) * G.y * ssc;
            o.z = (ri3 * (ri1 * (yc.z + yn.z + T3.z - m1 * u1q.z) + w1q.z + pp.z - m3 * s3q.z) + c3q.z) * G.z * ssc;
            o.w = (ri3 * (ri1 * (yc.w + yn.w + T3.w - m1 * u1q.w) + w1q.w + pp.w - m3 * s3q.w) + c3q.w) * G.w * ssc;
            ((float4*)out)[(size_t)ge * 16 + l] = o;
        }
    }
}

extern "C" void kernel_launch(void* const* d_in, const int* in_sizes, int n_in,
                              void* d_out, int out_size) {
    const int*   eidx  = (const int*)d_in[0];
    const float* elen  = (const float*)d_in[1];
    const float* nattr = (const float*)d_in[2];
    const float* ln1g  = (const float*)d_in[3];
    const float* ln1b  = (const float*)d_in[4];
    const float* W1    = (const float*)d_in[5];
    const float* b1    = (const float*)d_in[6];
    const float* ln2g  = (const float*)d_in[7];
    const float* ln2b  = (const float*)d_in[8];
    const float* W2    = (const float*)d_in[9];
    const float* b2    = (const float*)d_in[10];
    const float* ln3g  = (const float*)d_in[11];
    const float* ln3b  = (const float*)d_in[12];
    const float* W3    = (const float*)d_in[13];
    const float* b3    = (const float*)d_in[14];
    const float* fW1   = (const float*)d_in[15];
    const float* fW2   = (const float*)d_in[16];
    const float* resp  = (const float*)d_in[17];
    float* out = (float*)d_out;

    static int once = 0;
    if (!once) {
        cudaFuncSetAttribute(k_mats, cudaFuncAttributeMaxDynamicSharedMemorySize, MATS_SMEM);
        cudaFuncSetAttribute(k_table, cudaFuncAttributeMaxDynamicSharedMemorySize, TBLK_SMEM);
        once = 1;
    }
    k_mats<<<9, 256, MATS_SMEM>>>(W1, b1, ln1g, ln1b, ln2g, ln2b, W2, b2, ln3g, ln3b, W3, b3);
    k_table<<<(TBL + 8) / 8, 256, TBLK_SMEM>>>(W1, ln1g, W3, ln3g, fW1, fW2);
    k_nodes<<<1184, 256>>>(nattr, ln2g, W2);
    k_score<<<1184, 256>>>(eidx, elen);
    k_poolproj<<<1184, 256, POOL_SMEM>>>(W3, ln3g);
    k_out<<<1184, 256>>>(eidx, elen, resp, out);
}

// round 17
// speedup vs baseline: 4.7716x; 1.0181x over previous
#include <cuda_runtime.h>
#include <cuda_fp16.h>
#include <math.h>
#include <stdint.h>

#define NE 640000
#define NN 20000
#define TBL 8192

__device__ float g_M13[4096], g_M23[4096], g_WN0[4096], g_WN1[4096];
__device__ __align__(16) float g_s1[64], g_c1[64], g_u1[64], g_w1[64], g_s3[64], g_c3[64], g_gw2a[64];
__device__ __align__(16) float g_wsv[256];       // ws0|wg0|ws1|wg1
__device__ __align__(16) float4 g_sc4;           // A1,B1,A2,B2
__device__ float g_S2, g_C2;
__device__ __align__(16) __half g_Pch[NN * 64], g_Pnh[NN * 64];
__device__ __align__(16) __half g_YP[NN * 128];  // [0:64)=Yc, [64:128)=PP
__device__ __align__(16) __half g_Ynh[NN * 64];
__device__ __align__(16) float4 g_nodeAB[NN * 2]; // [2n]=(sumA,sumsqA,w2a,pcs) [2n+1]=(pcgw,pns,pngw,0)
__device__ __align__(16) float2 g_nodeB[NN];      // sumPool, sumsqPool (normalized)
__device__ __align__(16) __half g_Th[(TBL + 1) * 64];
__device__ __align__(16) __half g_C3[(TBL + 1) * 128];  // [0:64)=T3, [64:128)=gate
__device__ __align__(16) float4 g_tsc4[TBL + 1];  // rbsum, rbsq, Tsum, Tgw
__device__ __align__(16) float4 g_efsc[NE];       // S_s, S_q, m1, ri1
__device__ __align__(16) float g_pooled[NN * 64];
__device__ float g_sumexp;

__device__ __forceinline__ float hsum16(float v) {
#pragma unroll
    for (int o = 8; o; o >>= 1) v += __shfl_xor_sync(0xffffffffu, v, o);
    return v;
}
__device__ __forceinline__ void bessel8(float r, float* rb) {
    float t = r * (1.0f / 6.0f), t2 = t * t, t6 = t2 * t2 * t2;
    float ct = tanhf(1.0f - t6);
    const float pre = 0.57735026918962576f / r * (ct * ct * ct);
    const float th = r * 0.5235987755982988f;
    const float tc = 2.f * cosf(th);
    float sm1 = 0.f, sc = sinf(th);
#pragma unroll
    for (int n = 0; n < 8; n++) {
        rb[n] = pre * sc;
        const float nx = tc * sc - sm1;
        sm1 = sc; sc = nx;
    }
}
__device__ __forceinline__ float4 h4f(uint2 u) {
    float2 a = __half22float2(*(__half2*)&u.x), b = __half22float2(*(__half2*)&u.y);
    return make_float4(a.x, a.y, b.x, b.y);
}
#define LDGNC(d, p) asm volatile("ld.global.nc.f32 %0, [%1];" : "=f"(d) : "l"(p))
#define LERP(lo, hi, f) fmaf(f, (hi) - (lo), lo)

// ---------------- matrix precomputes ----------------
#define MATS_SMEM 86592
__global__ void __launch_bounds__(256) k_mats(
    const float* __restrict__ W1, const float* __restrict__ b1,
    const float* __restrict__ ln1g, const float* __restrict__ ln1b,
    const float* __restrict__ ln2g, const float* __restrict__ ln2b,
    const float* __restrict__ W2, const float* __restrict__ b2,
    const float* __restrict__ ln3g, const float* __restrict__ ln3b,
    const float* __restrict__ W3, const float* __restrict__ b3)
{
    extern __shared__ float sm[];
    float* W1s = sm;
    float* W3s = W1s + 8704;
    float* G3a = W3s + 8192;
    float* ss1 = G3a + 4096;
    float* sc1 = ss1 + 64;
    float* g1s = sc1 + 64;
    float* b1s = g1s + 136;
    float* g3s = b1s + 136;
    float* b3s = g3s + 128;
    const int tid = threadIdx.x;
    for (int i = tid; i < 8704; i += 256) W1s[i] = W1[i];
    for (int i = tid; i < 8192; i += 256) W3s[i] = W3[i];
    for (int i = tid; i < 136; i += 256) { g1s[i] = ln1g[i]; b1s[i] = ln1b[i]; }
    for (int i = tid; i < 128; i += 256) { g3s[i] = ln3g[i]; b3s[i] = ln3b[i]; }
    __syncthreads();
    for (int i = tid; i < 4096; i += 256) G3a[i] = g3s[i >> 6] * W3s[i];
    for (int i = blockIdx.x * 256 + tid; i < 4096; i += 9 * 256) {
        g_WN0[i] = g1s[i >> 6] * W1s[i];
        g_WN1[i] = g1s[64 + (i >> 6)] * W1s[4096 + i];
    }
    if (blockIdx.x == 0) {
        if (tid < 64) {
            float s = 0.f, c = 0.f;
            for (int k = 0; k < 136; k++) {
                s = fmaf(g1s[k], W1s[k * 64 + tid], s);
                c = fmaf(b1s[k], W1s[k * 64 + tid], c);
            }
            ss1[tid] = s; sc1[tid] = c + b1[tid];
            g_s1[tid] = s; g_c1[tid] = sc1[tid];
        } else if (tid < 128) {
            const int j = tid - 64;
            float s = 0.f, c = 0.f;
            for (int k = 0; k < 128; k++) {
                s = fmaf(g3s[k], W3s[k * 64 + j], s);
                c = fmaf(b3s[k], W3s[k * 64 + j], c);
            }
            g_s3[j] = s; g_c3[j] = c + b3[j];
        } else if (tid < 192) {
            const int j = tid - 128;
            g_gw2a[j] = ln2g[j] * W2[j];
        } else if (tid == 192) {
            float s = 0.f, c = 0.f;
            for (int k = 0; k < 128; k++) { s = fmaf(ln2g[k], W2[k], s); c = fmaf(ln2b[k], W2[k], c); }
            g_S2 = s; g_C2 = c + b2[0];
        } else if (tid == 193) {
            g_sumexp = 0.f;
        }
        __syncthreads();
        if (tid < 64) {
            float a = 0.f, b_ = 0.f;
            for (int k = 0; k < 64; k++) {
                a = fmaf(ss1[k], G3a[k * 64 + tid], a);
                b_ = fmaf(sc1[k], G3a[k * 64 + tid], b_);
            }
            g_u1[tid] = a; g_w1[tid] = b_;
        } else if (tid == 64) {
            float A1 = 0.f, B1 = 0.f, A2 = 0.f, B2 = 0.f;
            for (int c = 0; c < 64; c++) {
                const float gw = ln2g[c] * W2[c];
                A1 += ss1[c]; B1 += sc1[c];
                A2 = fmaf(ss1[c], gw, A2); B2 = fmaf(sc1[c], gw, B2);
            }
            g_sc4 = make_float4(A1, B1, A2, B2);
        } else if (tid >= 128) {
            const int idx = tid - 128, k = idx & 63, pair = idx >> 6;
            const int row = pair ? (64 + k) : k;
            const float gk = g1s[row];
            float s = 0.f, gacc = 0.f;
            for (int c = 0; c < 64; c++) {
                const float wv = gk * W1s[row * 64 + c];
                s += wv;
                gacc = fmaf(wv, ln2g[c] * W2[c], gacc);
            }
            g_wsv[pair * 128 + k] = s;
            g_wsv[pair * 128 + 64 + k] = gacc;
        }
    } else {
        const int idx = (blockIdx.x - 1) * 512 + tid;
#pragma unroll
        for (int h = 0; h < 2; h++) {
            const int ix = idx + h * 256, i = ix >> 6, j = ix & 63;
            float a = 0.f, b_ = 0.f;
            for (int k = 0; k < 64; k++) {
                a = fmaf(W1s[i * 64 + k], G3a[k * 64 + j], a);
                b_ = fmaf(W1s[(64 + i) * 64 + k], G3a[k * 64 + j], b_);
            }
            g_M13[ix] = g1s[i] * a;
            g_M23[ix] = g1s[64 + i] * b_;
        }
    }
}

// ---------------- r-tables ----------------
#define TBLK_SMEM 65536
__global__ void __launch_bounds__(256) k_table(
    const float* __restrict__ W1, const float* __restrict__ ln1g,
    const float* __restrict__ W3, const float* __restrict__ ln3g,
    const float* __restrict__ fW1, const float* __restrict__ fW2)
{
    extern __shared__ float sm[];
    float* G3a = sm;
    float* G1b = G3a + 4096;
    float* f1s = G1b + 512;
    float* f2s = f1s + 2048;
    float* sT  = f2s + 8192;
    float* st  = sT + 512;
    const int tid = threadIdx.x, w = tid >> 5, lane = tid & 31;
    for (int i = tid; i < 4096; i += 256) G3a[i] = ln3g[i >> 6] * W3[i];
    for (int i = tid; i < 512; i += 256)
        G1b[i] = ln1g[128 + (i >> 6)] * W1[(128 + (i >> 6)) * 64 + (i & 63)];
    for (int i = tid; i < 2048; i += 256) f1s[i] = fW1[i];
    for (int i = tid; i < 8192; i += 256) f2s[i] = fW2[i];
    __syncthreads();
    const int p = blockIdx.x * 8 + w;
    if (p > TBL) return;
    const float r = 0.5f + (5.5f / (float)TBL) * (float)p;
    float rb[8];
    bessel8(r, rb);
    const int j0 = 2 * lane;
    float T0 = 0.f, T1 = 0.f;
#pragma unroll
    for (int i = 0; i < 8; i++) {
        T0 = fmaf(rb[i], G1b[i * 64 + j0], T0);
        T1 = fmaf(rb[i], G1b[i * 64 + j0 + 1], T1);
    }
    sT[w * 64 + j0] = T0; sT[w * 64 + j0 + 1] = T1;
    g_Th[p * 64 + j0] = __float2half(T0);
    g_Th[p * 64 + j0 + 1] = __float2half(T1);
    float ps = T0 + T1;
    float pg = fmaf(T0, g_gw2a[j0], T1 * g_gw2a[j0 + 1]);
#pragma unroll
    for (int o = 16; o; o >>= 1) {
        ps += __shfl_xor_sync(0xffffffffu, ps, o);
        pg += __shfl_xor_sync(0xffffffffu, pg, o);
    }
    __syncwarp();
    float a3 = 0.f, b3_ = 0.f;
#pragma unroll 8
    for (int k = 0; k < 64; k++) {
        const float tv = sT[w * 64 + k];
        a3 = fmaf(tv, G3a[k * 64 + j0], a3);
        b3_ = fmaf(tv, G3a[k * 64 + j0 + 1], b3_);
    }
    g_C3[p * 128 + j0] = __float2half(a3);
    g_C3[p * 128 + j0 + 1] = __float2half(b3_);
#pragma unroll
    for (int j = 0; j < 4; j++) {
        const int k = lane + 32 * j;
        float a = 0.f, g = 0.f;
#pragma unroll
        for (int n = 0; n < 8; n++) {
            a = fmaf(rb[n], f1s[n * 256 + k], a);
            g = fmaf(rb[n], f1s[n * 256 + 128 + k], g);
        }
        st[w * 128 + k] = a / (1.f + expf(-a)) * g;
    }
    __syncwarp();
    float q0 = 0.f, q1 = 0.f;
#pragma unroll 8
    for (int k = 0; k < 128; k++) {
        const float tv = st[w * 128 + k];
        q0 = fmaf(tv, f2s[k * 64 + j0], q0);
        q1 = fmaf(tv, f2s[k * 64 + j0 + 1], q1);
    }
    g_C3[p * 128 + 64 + j0] = __float2half(1.f / (1.f + expf(-q0)));
    g_C3[p * 128 + 64 + j0 + 1] = __float2half(1.f / (1.f + expf(-q1)));
    if (lane == 0) {
        float s = 0.f, q = 0.f;
#pragma unroll
        for (int i = 0; i < 8; i++) { s += rb[i]; q = fmaf(rb[i], rb[i], q); }
        g_tsc4[p] = make_float4(s, q, ps, pg);
    }
}

// ---------------- node precomputes (+ pooled zeroing) ----------------
__global__ void __launch_bounds__(256) k_nodes(
    const float* __restrict__ nattr, const float* __restrict__ ln2g,
    const float* __restrict__ W2)
{
    __shared__ float sa[512];
    __shared__ float gwb[64];
    __shared__ float sws[256];
    const int tid = threadIdx.x;
    const int m = tid >> 6, c = tid & 63;
    const float* wp = (m == 0) ? g_WN0 : (m == 1) ? g_WN1 : (m == 2) ? g_M13 : g_M23;
    wp += c;
    if (tid < 64) gwb[tid] = ln2g[64 + tid] * W2[64 + tid];
    if (tid < 256) sws[tid] = g_wsv[tid];
    __syncthreads();
    const float4 z4 = make_float4(0.f, 0.f, 0.f, 0.f);
    for (int nb = blockIdx.x; nb < NN / 8; nb += gridDim.x) {
        if (tid < 128) {
            ((float4*)sa)[tid] = ((const float4*)(nattr + (size_t)nb * 512))[tid];
            ((float4*)g_pooled)[(size_t)nb * 128 + tid] = z4;
        }
        __syncthreads();
        float acc[8];
#pragma unroll
        for (int nd = 0; nd < 8; nd++) acc[nd] = 0.f;
#pragma unroll
        for (int k4 = 0; k4 < 16; k4++) {
            float w0, w1, w2v, w3;
            LDGNC(w0, wp + (4 * k4) * 64);
            LDGNC(w1, wp + (4 * k4 + 1) * 64);
            LDGNC(w2v, wp + (4 * k4 + 2) * 64);
            LDGNC(w3, wp + (4 * k4 + 3) * 64);
#pragma unroll
            for (int nd = 0; nd < 8; nd++) {
                const float4 av = *(const float4*)(sa + nd * 64 + 4 * k4);
                acc[nd] = fmaf(av.x, w0, fmaf(av.y, w1, fmaf(av.z, w2v, fmaf(av.w, w3, acc[nd]))));
            }
        }
#pragma unroll
        for (int nd = 0; nd < 8; nd++) {
            const int node = nb * 8 + nd;
            if (m == 0) g_Pch[(size_t)node * 64 + c] = __float2half(acc[nd]);
            else if (m == 1) g_Pnh[(size_t)node * 64 + c] = __float2half(acc[nd]);
            else if (m == 2) g_YP[(size_t)node * 128 + c] = __float2half(acc[nd]);
            else g_Ynh[(size_t)node * 64 + c] = __float2half(acc[nd]);
        }
        if (tid < 8) {
            float s = 0.f, q = 0.f, w2s = 0.f, ps = 0.f, pg = 0.f, ns = 0.f, ng = 0.f;
            for (int k = 0; k < 64; k++) {
                const float a = sa[tid * 64 + k];
                s += a; q = fmaf(a, a, q); w2s = fmaf(a, gwb[k], w2s);
                ps = fmaf(a, sws[k], ps);       pg = fmaf(a, sws[64 + k], pg);
                ns = fmaf(a, sws[128 + k], ns); ng = fmaf(a, sws[192 + k], ng);
            }
            g_nodeAB[(nb * 8 + tid) * 2]     = make_float4(s, q, w2s, ps);
            g_nodeAB[(nb * 8 + tid) * 2 + 1] = make_float4(pg, ns, ng, 0.f);
        }
        __syncthreads();
    }
}

// ---------------- K1: ef + score + fused scatter; NN tables ----------------
__global__ void __launch_bounds__(256) k_score(const int* __restrict__ eidx,
                                               const float* __restrict__ elen) {
    __shared__ float ssum[8];
    const int tid = threadIdx.x, w = tid >> 5, lane = tid & 31;
    const int g = lane >> 4, l = lane & 15;
    const float4 s1q = ((const float4*)g_s1)[l];
    const float4 c1q = ((const float4*)g_c1)[l];
    const float4 scal = g_sc4;   // A1,B1,A2,B2
    const float S2 = g_S2, C2 = g_C2;
    float lsum = 0.f;
    for (int base = blockIdx.x * 64 + w * 8 + g * 4; base < NE; base += gridDim.x * 64) {
#pragma unroll
        for (int e = 0; e < 4; e++) {
            const int ge = base + e;
            const int ec = eidx[ge], en = eidx[NE + ge];
            const float r = elen[ge];
            const float4 ncA = g_nodeAB[2 * ec], ncB = g_nodeAB[2 * ec + 1];
            const float4 nnA = g_nodeAB[2 * en], nnB = g_nodeAB[2 * en + 1];
            const float4 pc = h4f(*(const uint2*)&g_Pch[(size_t)ec * 64 + 4 * l]);
            const float4 pn = h4f(*(const uint2*)&g_Pnh[(size_t)en * 64 + 4 * l]);
            float u = (r - 0.5f) * ((float)TBL / 5.5f);
            u = fminf(fmaxf(u, 0.f), (float)TBL - 0.001f);
            const int gi = (int)(u + 0.5f);           // nearest-neighbor
            const float4 T = h4f(*(const uint2*)&g_Th[(size_t)gi * 64 + 4 * l]);
            const float4 ts = g_tsc4[gi];             // rbsum, rbsq, Tsum, Tgw
            const float m1 = (ncA.x + nnA.x + ts.x) * (1.f / 136.f);
            const float ri1 = rsqrtf((ncA.y + nnA.y + ts.y) * (1.f / 136.f) - m1 * m1 + 1e-5f);
            float4 ef;
            ef.x = ri1 * (pc.x + pn.x + T.x - m1 * s1q.x) + c1q.x;
            ef.y = ri1 * (pc.y + pn.y + T.y - m1 * s1q.y) + c1q.y;
            ef.z = ri1 * (pc.z + pn.z + T.z - m1 * s1q.z) + c1q.z;
            ef.w = ri1 * (pc.w + pn.w + T.w - m1 * s1q.w) + c1q.w;
            const float S_s = ri1 * (ncA.w + nnB.y + ts.z - m1 * scal.x) + scal.y;
            const float S_d = ri1 * (ncB.x + nnB.z + ts.w - m1 * scal.z) + scal.w;
            const float S_q = hsum16(fmaf(ef.x, ef.x, fmaf(ef.y, ef.y, fmaf(ef.z, ef.z, ef.w * ef.w))));
            const float m2 = (S_s + ncA.x) * (1.f / 128.f);
            const float ri2 = rsqrtf((S_q + ncA.y) * (1.f / 128.f) - m2 * m2 + 1e-5f);
            const float sc = ri2 * (S_d + ncA.z - m2 * S2) + C2;
            const float wexp = expf(sc);
            if (l == 0) {
                g_efsc[ge] = make_float4(S_s, S_q, m1, ri1);
                lsum += wexp;
            }
            float* dst = &g_pooled[(size_t)ec * 64 + 4 * l];
            asm volatile("red.global.add.v4.f32 [%0], {%1,%2,%3,%4};"
                         :: "l"(dst), "f"(wexp * ef.x), "f"(wexp * ef.y),
                            "f"(wexp * ef.z), "f"(wexp * ef.w) : "memory");
        }
    }
#pragma unroll
    for (int o = 16; o; o >>= 1) lsum += __shfl_xor_sync(0xffffffffu, lsum, o);
    if (lane == 0) ssum[w] = lsum;
    __syncthreads();
    if (tid == 0) {
        float s = ssum[0];
        for (int i = 1; i < 8; i++) s += ssum[i];
        atomicAdd(&g_sumexp, s);
    }
}

// ---------------- pool projections (normalize by sumexp) ----------------
#define POOL_SMEM 18432
__global__ void __launch_bounds__(256) k_poolproj(const float* __restrict__ W3,
                                                  const float* __restrict__ ln3g) {
    extern __shared__ float sm[];
    float* sw1 = sm;
    float* sp = sw1 + 4096;
    const int tid = threadIdx.x;
    const float inv = 1.f / g_sumexp;
    for (int idx = tid; idx < 4096; idx += 256)
        sw1[idx] = ln3g[64 + (idx >> 6)] * W3[(64 + (idx >> 6)) * 64 + (idx & 63)];
    __syncthreads();
    const int s = tid >> 6, c = tid & 63;
    for (int nb = blockIdx.x; nb < NN / 8; nb += gridDim.x) {
        for (int idx = tid; idx < 512; idx += 256)
            sp[idx] = g_pooled[(size_t)(nb * 8) * 64 + idx] * inv;
        __syncthreads();
        float a0 = 0.f, a1 = 0.f;
#pragma unroll 4
        for (int k = 0; k < 64; k++) {
            const float wv = sw1[k * 64 + c];
            a0 = fmaf(sp[s * 64 + k], wv, a0);
            a1 = fmaf(sp[(s + 4) * 64 + k], wv, a1);
        }
        g_YP[(size_t)(nb * 8 + s) * 128 + 64 + c] = __float2half(a0);
        g_YP[(size_t)(nb * 8 + s + 4) * 128 + 64 + c] = __float2half(a1);
        if (tid < 8) {
            float su = 0.f, q = 0.f;
            for (int k = 0; k < 64; k++) {
                const float a = sp[tid * 64 + k];
                su += a; q = fmaf(a, a, q);
            }
            g_nodeB[nb * 8 + tid] = make_float2(su, q);
        }
        __syncthreads();
    }
}

// ---------------- K4: out (NN C3; merged YP row) ----------------
__global__ void __launch_bounds__(256) k_out(const int* __restrict__ eidx,
                                             const float* __restrict__ elen,
                                             const float* __restrict__ resp,
                                             float* __restrict__ out) {
    const int tid = threadIdx.x, w = tid >> 5, lane = tid & 31;
    const int g = lane >> 4, l = lane & 15;
    const float4 u1q = ((const float4*)g_u1)[l];
    const float4 w1q = ((const float4*)g_w1)[l];
    const float4 s3q = ((const float4*)g_s3)[l];
    const float4 c3q = ((const float4*)g_c3)[l];
    const float p = resp[0];
    const float uc = 1.f / (1.f + expf(-p));
    const float cc = rsqrtf(uc * uc + 1.f);
    const float ssc = uc * cc * (1.f + cc + cc * cc);   // 3 recycles collapsed
    for (int base = blockIdx.x * 64 + w * 8 + g * 4; base < NE; base += gridDim.x * 64) {
#pragma unroll
        for (int e = 0; e < 4; e++) {
            const int ge = base + e;
            const int ec = eidx[ge], en = eidx[NE + ge];
            const float r = elen[ge];
            const float4 es = g_efsc[ge];
            const float2 nb = g_nodeB[ec];
            const float4 yc = h4f(*(const uint2*)&g_YP[(size_t)ec * 128 + 4 * l]);
            const float4 pp = h4f(*(const uint2*)&g_YP[(size_t)ec * 128 + 64 + 4 * l]);
            const float4 yn = h4f(*(const uint2*)&g_Ynh[(size_t)en * 64 + 4 * l]);
            float u = (r - 0.5f) * ((float)TBL / 5.5f);
            u = fminf(fmaxf(u, 0.f), (float)TBL - 0.001f);
            const int gi = (int)(u + 0.5f);        // nearest
            const float4 T3 = h4f(*(const uint2*)&g_C3[gi * 128 + 4 * l]);
            const float4 G  = h4f(*(const uint2*)&g_C3[gi * 128 + 64 + 4 * l]);
            const float m1 = es.z, ri1 = es.w;
            const float m3 = (es.x + nb.x) * (1.f / 128.f);
            const float ri3 = rsqrtf((es.y + nb.y) * (1.f / 128.f) - m3 * m3 + 1e-5f);
            float4 o;
            o.x = (ri3 * (ri1 * (yc.x + yn.x + T3.x - m1 * u1q.x) + w1q.x + pp.x - m3 * s3q.x) + c3q.x) * G.x * ssc;
            o.y = (ri3 * (ri1 * (yc.y + yn.y + T3.y - m1 * u1q.y) + w1q.y + pp.y - m3 * s3q.y) + c3q.y) * G.y * ssc;
            o.z = (ri3 * (ri1 * (yc.z + yn.z + T3.z - m1 * u1q.z) + w1q.z + pp.z - m3 * s3q.z) + c3q.z) * G.z * ssc;
            o.w = (ri3 * (ri1 * (yc.w + yn.w + T3.w - m1 * u1q.w) + w1q.w + pp.w - m3 * s3q.w) + c3q.w) * G.w * ssc;
            ((float4*)out)[(size_t)ge * 16 + l] = o;
        }
    }
}

extern "C" void kernel_launch(void* const* d_in, const int* in_sizes, int n_in,
                              void* d_out, int out_size) {
    const int*   eidx  = (const int*)d_in[0];
    const float* elen  = (const float*)d_in[1];
    const float* nattr = (const float*)d_in[2];
    const float* ln1g  = (const float*)d_in[3];
    const float* ln1b  = (const float*)d_in[4];
    const float* W1    = (const float*)d_in[5];
    const float* b1    = (const float*)d_in[6];
    const float* ln2g  = (const float*)d_in[7];
    const float* ln2b  = (const float*)d_in[8];
    const float* W2    = (const float*)d_in[9];
    const float* b2    = (const float*)d_in[10];
    const float* ln3g  = (const float*)d_in[11];
    const float* ln3b  = (const float*)d_in[12];
    const float* W3    = (const float*)d_in[13];
    const float* b3    = (const float*)d_in[14];
    const float* fW1   = (const float*)d_in[15];
    const float* fW2   = (const float*)d_in[16];
    const float* resp  = (const float*)d_in[17];
    float* out = (float*)d_out;

    static int once = 0;
    if (!once) {
        cudaFuncSetAttribute(k_mats, cudaFuncAttributeMaxDynamicSharedMemorySize, MATS_SMEM);
        cudaFuncSetAttribute(k_table, cudaFuncAttributeMaxDynamicSharedMemorySize, TBLK_SMEM);
        once = 1;
    }
    k_mats<<<9, 256, MATS_SMEM>>>(W1, b1, ln1g, ln1b, ln2g, ln2b, W2, b2, ln3g, ln3b, W3, b3);
    k_table<<<(TBL + 8) / 8, 256, TBLK_SMEM>>>(W1, ln1g, W3, ln3g, fW1, fW2);
    k_nodes<<<1184, 256>>>(nattr, ln2g, W2);
    k_score<<<1184, 256>>>(eidx, elen);
    k_poolproj<<<1184, 256, POOL_SMEM>>>(W3, ln3g);
    k_out<<<1184, 256>>>(eidx, elen, resp, out);
}